// round 4
// baseline (speedup 1.0000x reference)
#include <cuda_runtime.h>
#include <cuda_fp16.h>
#include <math.h>
#include <stdint.h>

#define BATCH 32768
#define FEAT  784
#define FV    196
#define NITER 8
#define BROWS (BATCH * 4)        // 131072 capsule rows

#define KPAD_CAP 208             // capsule K padded (13*16)
#define NPAD_CAP 224             // capsule N padded (2*112)

// ----------------------------- scratch ------------------------------------
__device__ __align__(256) __half g_hhi [(size_t)BROWS * KPAD_CAP];
__device__ __align__(256) __half g_hlo [(size_t)BROWS * KPAD_CAP];
__device__ __align__(256) __half g_hhi2[(size_t)BROWS * KPAD_CAP];
__device__ __align__(256) __half g_hlo2[(size_t)BROWS * KPAD_CAP];
__device__ __align__(256) float  g_q[(size_t)BROWS * FV];
__device__ __align__(256) float  g_k[(size_t)BROWS * FV];
__device__ __align__(256) float  g_p[(size_t)BATCH * 16];
__device__ __align__(256) __half g_w1hi[NPAD_CAP * KPAD_CAP], g_w1lo[NPAD_CAP * KPAD_CAP];
__device__ __align__(256) __half g_w2hi[NPAD_CAP * KPAD_CAP], g_w2lo[NPAD_CAP * KPAD_CAP];
__device__ __align__(256) __half g_w3hi[NPAD_CAP * KPAD_CAP], g_w3lo[NPAD_CAP * KPAD_CAP];
__device__ __align__(256) __half g_wd1hi[FEAT * FEAT], g_wd1lo[FEAT * FEAT];
__device__ __align__(256) __half g_wd2hi[FEAT * FEAT], g_wd2lo[FEAT * FEAT];
__device__ __align__(256) __half g_dhi[(size_t)BATCH * FEAT], g_dlo[(size_t)BATCH * FEAT];
__device__ __align__(256) __half g_thi[(size_t)BATCH * FEAT], g_tlo[(size_t)BATCH * FEAT];
__device__ __align__(256) float  g_dec[(size_t)BATCH * FEAT];

// ----------------------------- PTX helpers --------------------------------
__device__ __forceinline__ uint32_t smem_u32(const void* p) {
    uint32_t a;
    asm("{ .reg .u64 t; cvta.to.shared.u64 t, %1; cvt.u32.u64 %0, t; }" : "=r"(a) : "l"(p));
    return a;
}
__device__ __forceinline__ void cp_async16(uint32_t dst, const void* src) {
    asm volatile("cp.async.cg.shared.global [%0], [%1], 16;" :: "r"(dst), "l"(src));
}
__device__ __forceinline__ void ldsm_x4(uint32_t* r, uint32_t addr) {
    asm volatile("ldmatrix.sync.aligned.m8n8.x4.shared.b16 {%0,%1,%2,%3}, [%4];"
                 : "=r"(r[0]), "=r"(r[1]), "=r"(r[2]), "=r"(r[3]) : "r"(addr));
}
__device__ __forceinline__ void ldsm_x2(uint32_t* r, uint32_t addr) {
    asm volatile("ldmatrix.sync.aligned.m8n8.x2.shared.b16 {%0,%1}, [%2];"
                 : "=r"(r[0]), "=r"(r[1]) : "r"(addr));
}
__device__ __forceinline__ void mma16816(float* c, const uint32_t* a, const uint32_t* b) {
    asm volatile("mma.sync.aligned.m16n8k16.row.col.f32.f16.f16.f32 "
                 "{%0,%1,%2,%3}, {%4,%5,%6,%7}, {%8,%9}, {%0,%1,%2,%3};"
                 : "+f"(c[0]), "+f"(c[1]), "+f"(c[2]), "+f"(c[3])
                 : "r"(a[0]), "r"(a[1]), "r"(a[2]), "r"(a[3]), "r"(b[0]), "r"(b[1]));
}
// conflict-free swizzle for 64B rows, 16B granules
__device__ __forceinline__ uint32_t swz(int r, int g) {
    return (uint32_t)r * 64u + ((uint32_t)(g ^ (r & 3) ^ ((r >> 2) & 1)) << 4);
}

// ----------------------------- GEMM (fp16x3 mma.sync, 2-stage pipe) -------
// C[M, n_real] = (Ahi+Alo) @ (Whi+Wlo)^T + bias, fp32 accumulation.
// block 128 x 112, BK=32 chunks double-buffered. 8 warps 4x2, warp 32x56.
// If probs != null: capsule-u mode; epilogue computes h = probs @ u in-register
// and writes Hhi/Hlo (stride KPAD_CAP) and optionally Dhi/Dlo (decoder layout).
#define STAGE_BYTES 30720u
#define OFF_ALO 8192u
#define OFF_W   16384u
#define OFF_WLO 7168u
#define SMEM_BYTES 61440

__global__ __launch_bounds__(256, 2)
void gemm_mma(const __half* __restrict__ Ahi, const __half* __restrict__ Alo, int lda,
              const __half* __restrict__ Whi, const __half* __restrict__ Wlo, int ldw,
              const float* __restrict__ bias,
              float* __restrict__ Cf, __half* __restrict__ Chi, __half* __restrict__ Clo,
              int ldc, int K, int n_real, int relu,
              const float* __restrict__ probs,
              __half* __restrict__ Hhi, __half* __restrict__ Hlo,
              __half* __restrict__ Dhi, __half* __restrict__ Dlo)
{
    extern __shared__ char smem[];
    const uint32_t sb = smem_u32(smem);
    const int tid = threadIdx.x;
    const int lane = tid & 31;
    const int wid = tid >> 5;
    const int wm = wid & 3;
    const int wn = wid >> 2;
    const int m0 = blockIdx.y * 128;
    const int n0 = blockIdx.x * 112;
    const int nch = (K + 31) >> 5;

    float acc[2][7][4];
#pragma unroll
    for (int i = 0; i < 2; i++)
#pragma unroll
        for (int j = 0; j < 7; j++)
#pragma unroll
            for (int v = 0; v < 4; v++) acc[i][j][v] = 0.f;

    auto load_chunk = [&](int ch) {
        const int kc = ch << 5;
        const int cur = min(32, K - kc);
        const int gc = cur >> 3;               // granules/row: 4 or 2
        const int gsh = (gc == 4) ? 2 : 1;
        const int gm = gc - 1;
        const uint32_t sa = sb + (uint32_t)(ch & 1) * STAGE_BYTES;
        for (int idx = tid; idx < 128 * gc; idx += 256) {
            int r = idx >> gsh, g = idx & gm;
            size_t src = (size_t)(m0 + r) * lda + kc + g * 8;
            uint32_t d = sa + swz(r, g);
            cp_async16(d, Ahi + src);
            cp_async16(d + OFF_ALO, Alo + src);
        }
        for (int idx = tid; idx < 112 * gc; idx += 256) {
            int r = idx >> gsh, g = idx & gm;
            size_t src = (size_t)(n0 + r) * ldw + kc + g * 8;
            uint32_t d = sa + OFF_W + swz(r, g);
            cp_async16(d, Whi + src);
            cp_async16(d + OFF_WLO, Wlo + src);
        }
        asm volatile("cp.async.commit_group;");
    };

    load_chunk(0);
    for (int ch = 0; ch < nch; ch++) {
        if (ch + 1 < nch) {
            load_chunk(ch + 1);
            asm volatile("cp.async.wait_group 1;");
        } else {
            asm volatile("cp.async.wait_group 0;");
        }
        __syncthreads();

        const int cur = min(32, K - (ch << 5));
        const int nks = cur >> 4;
        const uint32_t sa = sb + (uint32_t)(ch & 1) * STAGE_BYTES;
        const uint32_t sw = sa + OFF_W;

        for (int ks = 0; ks < nks; ks++) {
            uint32_t ah[2][4], al[2][4], bh[7][2], bl[7][2];
#pragma unroll
            for (int mf = 0; mf < 2; mf++) {
                int r = wm * 32 + mf * 16 + (lane & 15);
                int g = ks * 2 + (lane >> 4);
                uint32_t off = swz(r, g);
                ldsm_x4(ah[mf], sa + off);
                ldsm_x4(al[mf], sa + OFF_ALO + off);
            }
#pragma unroll
            for (int p = 0; p < 3; p++) {
                int r = wn * 56 + p * 16 + (lane & 7) + ((lane >> 4) & 1) * 8;
                int g = ks * 2 + ((lane >> 3) & 1);
                uint32_t off = swz(r, g);
                uint32_t t4[4];
                ldsm_x4(t4, sw + off);
                bh[2*p][0] = t4[0]; bh[2*p][1] = t4[1];
                bh[2*p+1][0] = t4[2]; bh[2*p+1][1] = t4[3];
                ldsm_x4(t4, sw + OFF_WLO + off);
                bl[2*p][0] = t4[0]; bl[2*p][1] = t4[1];
                bl[2*p+1][0] = t4[2]; bl[2*p+1][1] = t4[3];
            }
            {
                int l15 = lane & 15;
                int r = wn * 56 + 48 + (l15 & 7);
                int g = ks * 2 + ((l15 >> 3) & 1);
                uint32_t off = swz(r, g);
                ldsm_x2(bh[6], sw + off);
                ldsm_x2(bl[6], sw + OFF_WLO + off);
            }
#pragma unroll
            for (int mf = 0; mf < 2; mf++)
#pragma unroll
                for (int nf = 0; nf < 7; nf++) {
                    mma16816(acc[mf][nf], ah[mf], bh[nf]);   // hi*hi
                    mma16816(acc[mf][nf], al[mf], bh[nf]);   // lo*hi
                    mma16816(acc[mf][nf], ah[mf], bl[nf]);   // hi*lo
                }
        }
        __syncthreads();
    }

    if (probs) {
        // fused attention epilogue: u in acc; h[t] = sum_s p[t][s] * u[s]
#pragma unroll
        for (int mf = 0; mf < 2; mf++)
#pragma unroll
        for (int hf = 0; hf < 2; hf++) {
            int row = m0 + wm * 32 + mf * 16 + hf * 8 + (lane >> 2);
            int batch = row >> 2, t = row & 3;
            float4 pv = *(const float4*)(probs + (size_t)batch * 16 + t * 4);
            int base = (lane >> 2) & 4;     // start of 4-row group within 8-row half
#pragma unroll
            for (int nf = 0; nf < 7; nf++)
#pragma unroll
            for (int e = 0; e < 2; e++) {
                int c = n0 + wn * 56 + nf * 8 + ((lane & 3) << 1) + e;
                float uv = acc[mf][nf][hf * 2 + e] + ((c < n_real) ? bias[c] : 0.f);
                float h = 0.f;
#pragma unroll
                for (int s = 0; s < 4; s++) {
                    float us = __shfl_sync(0xffffffffu, uv, ((base + s) << 2) | (lane & 3));
                    float ps = (s == 0) ? pv.x : (s == 1) ? pv.y : (s == 2) ? pv.z : pv.w;
                    h = fmaf(ps, us, h);
                }
                if (c < n_real) {
                    __half hi = __float2half_rn(h);
                    __half lo = __float2half_rn(h - __half2float(hi));
                    size_t ho = (size_t)row * KPAD_CAP + c;
                    Hhi[ho] = hi; Hlo[ho] = lo;
                    if (Dhi) {
                        size_t dof = (size_t)batch * FEAT + t * FV + c;
                        Dhi[dof] = hi; Dlo[dof] = lo;
                    }
                }
            }
        }
    } else {
        // plain epilogue
#pragma unroll
        for (int mf = 0; mf < 2; mf++)
#pragma unroll
        for (int nf = 0; nf < 7; nf++) {
            int r = m0 + wm * 32 + mf * 16 + (lane >> 2);
            int c = n0 + wn * 56 + nf * 8 + ((lane & 3) << 1);
#pragma unroll
            for (int hf = 0; hf < 2; hf++) {
                int rr = r + hf * 8;
#pragma unroll
                for (int e = 0; e < 2; e++) {
                    int cc = c + e;
                    if (cc >= n_real) continue;
                    float v = acc[mf][nf][hf * 2 + e] + bias[cc];
                    if (relu) v = fmaxf(v, 0.f);
                    size_t o = (size_t)rr * ldc + cc;
                    if (Cf) Cf[o] = v;
                    if (Chi) {
                        __half hi = __float2half_rn(v);
                        Chi[o] = hi;
                        Clo[o] = __float2half_rn(v - __half2float(hi));
                    }
                }
            }
        }
    }
}

// ----------------------------- conversions --------------------------------
__global__ void convert_x_kernel(const float* __restrict__ x,
                                 __half* __restrict__ hhi, __half* __restrict__ hlo,
                                 __half* __restrict__ hhi2, __half* __restrict__ hlo2)
{
    size_t idx = (size_t)blockIdx.x * blockDim.x + threadIdx.x;
    if (idx >= (size_t)BROWS * KPAD_CAP) return;
    size_t R = idx / KPAD_CAP;
    int f = (int)(idx % KPAD_CAP);
    float v = (f < FV) ? x[R * FV + f] : 0.f;
    __half hi = __float2half_rn(v);
    __half lo = __float2half_rn(v - __half2float(hi));
    hhi[idx] = hi;  hlo[idx] = lo;
    hhi2[idx] = hi; hlo2[idx] = lo;   // pad columns must be zero in both buffers
}

__global__ void convert_w_kernel(const float* __restrict__ W, int rin, int cin,
                                 __half* __restrict__ hi, __half* __restrict__ lo,
                                 int rout, int cout)
{
    int idx = blockIdx.x * blockDim.x + threadIdx.x;
    if (idx >= rout * cout) return;
    int r = idx / cout, c = idx % cout;
    float v = (r < rin && c < cin) ? W[(size_t)r * cin + c] : 0.f;
    __half h = __float2half_rn(v);
    hi[idx] = h;
    lo[idx] = __float2half_rn(v - __half2float(h));
}

// ----------------------------- scores (fp32) -------------------------------
__global__ __launch_bounds__(256)
void score_kernel(const float* __restrict__ q, const float* __restrict__ k,
                  float* __restrict__ probs)
{
    const int b    = blockIdx.x * 8 + threadIdx.y;
    const int lane = threadIdx.x;
    const float* qb = q + (size_t)b * FEAT;
    const float* kb = k + (size_t)b * FEAT;

    float s[4][4];
#pragma unroll
    for (int t = 0; t < 4; t++)
#pragma unroll
        for (int r = 0; r < 4; r++) s[t][r] = 0.f;

    for (int f = lane; f < FV; f += 32) {
        float qa[4], ka[4];
#pragma unroll
        for (int t = 0; t < 4; t++) { qa[t] = qb[t * FV + f]; ka[t] = kb[t * FV + f]; }
#pragma unroll
        for (int t = 0; t < 4; t++)
#pragma unroll
            for (int r = 0; r < 4; r++)
                s[t][r] = fmaf(qa[t], ka[r], s[t][r]);
    }
#pragma unroll
    for (int t = 0; t < 4; t++)
#pragma unroll
        for (int r = 0; r < 4; r++)
#pragma unroll
            for (int off = 16; off > 0; off >>= 1)
                s[t][r] += __shfl_xor_sync(0xffffffffu, s[t][r], off);

    float p[4][4];
#pragma unroll
    for (int t = 0; t < 4; t++) {
        float m = fmaxf(fmaxf(s[t][0], s[t][1]), fmaxf(s[t][2], s[t][3]));
        float e0 = expf(s[t][0] - m), e1 = expf(s[t][1] - m);
        float e2 = expf(s[t][2] - m), e3 = expf(s[t][3] - m);
        float inv = 1.f / (e0 + e1 + e2 + e3);
        p[t][0] = e0 * inv; p[t][1] = e1 * inv; p[t][2] = e2 * inv; p[t][3] = e3 * inv;
    }
    if (lane < 16)
        probs[(size_t)b * 16 + lane] = p[lane >> 2][lane & 3];
}

// ----------------------------- head ----------------------------------------
__global__ __launch_bounds__(256)
void head_kernel(const float* __restrict__ A, const float* __restrict__ Wo,
                 const float* __restrict__ bo, float* __restrict__ out)
{
    const int b    = blockIdx.x * 8 + threadIdx.y;
    const int lane = threadIdx.x;
    const float* a = A + (size_t)b * FEAT;

    float acc[10];
#pragma unroll
    for (int j = 0; j < 10; j++) acc[j] = 0.f;
    for (int kk = lane; kk < FEAT; kk += 32) {
        float av = a[kk];
#pragma unroll
        for (int j = 0; j < 10; j++)
            acc[j] = fmaf(av, Wo[j * FEAT + kk], acc[j]);
    }
#pragma unroll
    for (int j = 0; j < 10; j++)
#pragma unroll
        for (int off = 16; off > 0; off >>= 1)
            acc[j] += __shfl_xor_sync(0xffffffffu, acc[j], off);

    if (lane == 0) {
        float v[10], m = -1e30f;
#pragma unroll
        for (int j = 0; j < 10; j++) { v[j] = acc[j] + bo[j]; m = fmaxf(m, v[j]); }
        float ssum = 0.f;
#pragma unroll
        for (int j = 0; j < 10; j++) { v[j] = expf(v[j] - m); ssum += v[j]; }
        float inv = 1.f / ssum;
#pragma unroll
        for (int j = 0; j < 10; j++) out[(size_t)b * 10 + j] = v[j] * inv;
    }
}

// ---------------------------------------------------------------------------
extern "C" void kernel_launch(void* const* d_in, const int* in_sizes, int n_in,
                              void* d_out, int out_size)
{
    const float* x   = (const float*)d_in[0];
    const float* W1  = (const float*)d_in[1];
    const float* b1  = (const float*)d_in[2];
    const float* W2  = (const float*)d_in[3];
    const float* b2  = (const float*)d_in[4];
    const float* W3  = (const float*)d_in[5];
    const float* b3  = (const float*)d_in[6];
    const float* Wd1 = (const float*)d_in[7];
    const float* bd1 = (const float*)d_in[8];
    const float* Wd2 = (const float*)d_in[9];
    const float* bd2 = (const float*)d_in[10];
    const float* Wo  = (const float*)d_in[11];
    const float* bo  = (const float*)d_in[12];
    float* out = (float*)d_out;

    cudaFuncSetAttribute(gemm_mma, cudaFuncAttributeMaxDynamicSharedMemorySize, SMEM_BYTES);

    __half *hhi, *hlo, *hhi2, *hlo2, *w1hi, *w1lo, *w2hi, *w2lo, *w3hi, *w3lo;
    __half *wd1hi, *wd1lo, *wd2hi, *wd2lo, *dhi, *dlo, *thi, *tlo;
    float *q, *k, *p, *dec;
    cudaGetSymbolAddress((void**)&hhi, g_hhi);     cudaGetSymbolAddress((void**)&hlo, g_hlo);
    cudaGetSymbolAddress((void**)&hhi2, g_hhi2);   cudaGetSymbolAddress((void**)&hlo2, g_hlo2);
    cudaGetSymbolAddress((void**)&q, g_q);         cudaGetSymbolAddress((void**)&k, g_k);
    cudaGetSymbolAddress((void**)&p, g_p);         cudaGetSymbolAddress((void**)&dec, g_dec);
    cudaGetSymbolAddress((void**)&w1hi, g_w1hi);   cudaGetSymbolAddress((void**)&w1lo, g_w1lo);
    cudaGetSymbolAddress((void**)&w2hi, g_w2hi);   cudaGetSymbolAddress((void**)&w2lo, g_w2lo);
    cudaGetSymbolAddress((void**)&w3hi, g_w3hi);   cudaGetSymbolAddress((void**)&w3lo, g_w3lo);
    cudaGetSymbolAddress((void**)&wd1hi, g_wd1hi); cudaGetSymbolAddress((void**)&wd1lo, g_wd1lo);
    cudaGetSymbolAddress((void**)&wd2hi, g_wd2hi); cudaGetSymbolAddress((void**)&wd2lo, g_wd2lo);
    cudaGetSymbolAddress((void**)&dhi, g_dhi);     cudaGetSymbolAddress((void**)&dlo, g_dlo);
    cudaGetSymbolAddress((void**)&thi, g_thi);     cudaGetSymbolAddress((void**)&tlo, g_tlo);

    // conversions
    convert_x_kernel<<<(int)(((size_t)BROWS * KPAD_CAP + 255) / 256), 256>>>(x, hhi, hlo, hhi2, hlo2);
    int wcap = NPAD_CAP * KPAD_CAP;
    convert_w_kernel<<<(wcap + 255) / 256, 256>>>(W1, FV, FV, w1hi, w1lo, NPAD_CAP, KPAD_CAP);
    convert_w_kernel<<<(wcap + 255) / 256, 256>>>(W2, FV, FV, w2hi, w2lo, NPAD_CAP, KPAD_CAP);
    convert_w_kernel<<<(wcap + 255) / 256, 256>>>(W3, FV, FV, w3hi, w3lo, NPAD_CAP, KPAD_CAP);
    int wdec = FEAT * FEAT;
    convert_w_kernel<<<(wdec + 255) / 256, 256>>>(Wd1, FEAT, FEAT, wd1hi, wd1lo, FEAT, FEAT);
    convert_w_kernel<<<(wdec + 255) / 256, 256>>>(Wd2, FEAT, FEAT, wd2hi, wd2lo, FEAT, FEAT);

    // capsule iterations (h double-buffered: read cur, write nxt)
    const dim3 gcap(2, BROWS / 128);
    for (int it = 0; it < NITER; it++) {
        __half* chi = (it & 1) ? hhi2 : hhi;
        __half* clo = (it & 1) ? hlo2 : hlo;
        __half* nhi = (it & 1) ? hhi : hhi2;
        __half* nlo = (it & 1) ? hlo : hlo2;
        int last = (it == NITER - 1);
        gemm_mma<<<gcap, 256, SMEM_BYTES>>>(chi, clo, KPAD_CAP, w1hi, w1lo, KPAD_CAP, b1,
                                            q, nullptr, nullptr, FV, KPAD_CAP, FV, 0,
                                            nullptr, nullptr, nullptr, nullptr, nullptr);
        gemm_mma<<<gcap, 256, SMEM_BYTES>>>(chi, clo, KPAD_CAP, w2hi, w2lo, KPAD_CAP, b2,
                                            k, nullptr, nullptr, FV, KPAD_CAP, FV, 0,
                                            nullptr, nullptr, nullptr, nullptr, nullptr);
        score_kernel<<<BATCH / 8, dim3(32, 8)>>>(q, k, p);
        gemm_mma<<<gcap, 256, SMEM_BYTES>>>(chi, clo, KPAD_CAP, w3hi, w3lo, KPAD_CAP, b3,
                                            nullptr, nullptr, nullptr, 0, KPAD_CAP, FV, 0,
                                            p, nhi, nlo,
                                            last ? dhi : nullptr, last ? dlo : nullptr);
    }

    // decoder
    const dim3 gdec(7, BATCH / 128);
    gemm_mma<<<gdec, 256, SMEM_BYTES>>>(dhi, dlo, FEAT, wd1hi, wd1lo, FEAT, bd1,
                                        nullptr, thi, tlo, FEAT, FEAT, FEAT, 1,
                                        nullptr, nullptr, nullptr, nullptr, nullptr);
    gemm_mma<<<gdec, 256, SMEM_BYTES>>>(thi, tlo, FEAT, wd2hi, wd2lo, FEAT, bd2,
                                        dec, nullptr, nullptr, FEAT, FEAT, FEAT, 0,
                                        nullptr, nullptr, nullptr, nullptr, nullptr);
    head_kernel<<<BATCH / 8, dim3(32, 8)>>>(dec, Wo, bo, out);
}

// round 5
// speedup vs baseline: 1.2607x; 1.2607x over previous
#include <cuda_runtime.h>
#include <cuda_fp16.h>
#include <math.h>
#include <stdint.h>

#define BATCH 32768
#define FEAT  784
#define FV    196
#define NITER 8
#define BROWS (BATCH * 4)        // 131072 capsule rows

#define KPAD_CAP 208             // capsule K padded (13*16)
#define NPAD_CAP 224             // capsule N padded (2*112)

// ----------------------------- scratch ------------------------------------
__device__ __align__(256) __half g_hhi [(size_t)BROWS * KPAD_CAP];
__device__ __align__(256) __half g_hlo [(size_t)BROWS * KPAD_CAP];
__device__ __align__(256) __half g_hhi2[(size_t)BROWS * KPAD_CAP];
__device__ __align__(256) __half g_hlo2[(size_t)BROWS * KPAD_CAP];
__device__ __align__(256) float  g_z[(size_t)BROWS * FV];
__device__ __align__(256) float  g_p[(size_t)BATCH * 16];
__device__ __align__(256) __half g_gthi[NPAD_CAP * KPAD_CAP], g_gtlo[NPAD_CAP * KPAD_CAP];
__device__ __align__(256) float  g_g2[FV];
__device__ __align__(256) __half g_w3hi[NPAD_CAP * KPAD_CAP], g_w3lo[NPAD_CAP * KPAD_CAP];
__device__ __align__(256) __half g_wd1hi[FEAT * FEAT], g_wd1lo[FEAT * FEAT];
__device__ __align__(256) __half g_wd2hi[FEAT * FEAT], g_wd2lo[FEAT * FEAT];
__device__ __align__(256) __half g_dhi[(size_t)BATCH * FEAT], g_dlo[(size_t)BATCH * FEAT];
__device__ __align__(256) __half g_thi[(size_t)BATCH * FEAT], g_tlo[(size_t)BATCH * FEAT];
__device__ __align__(256) float  g_dec[(size_t)BATCH * FEAT];
__device__ __align__(256) float  g_zero_bias[NPAD_CAP];

// ----------------------------- PTX helpers --------------------------------
__device__ __forceinline__ uint32_t smem_u32(const void* p) {
    uint32_t a;
    asm("{ .reg .u64 t; cvta.to.shared.u64 t, %1; cvt.u32.u64 %0, t; }" : "=r"(a) : "l"(p));
    return a;
}
__device__ __forceinline__ void cp_async16(uint32_t dst, const void* src) {
    asm volatile("cp.async.cg.shared.global [%0], [%1], 16;" :: "r"(dst), "l"(src));
}
__device__ __forceinline__ void ldsm_x4(uint32_t* r, uint32_t addr) {
    asm volatile("ldmatrix.sync.aligned.m8n8.x4.shared.b16 {%0,%1,%2,%3}, [%4];"
                 : "=r"(r[0]), "=r"(r[1]), "=r"(r[2]), "=r"(r[3]) : "r"(addr));
}
__device__ __forceinline__ void ldsm_x2(uint32_t* r, uint32_t addr) {
    asm volatile("ldmatrix.sync.aligned.m8n8.x2.shared.b16 {%0,%1}, [%2];"
                 : "=r"(r[0]), "=r"(r[1]) : "r"(addr));
}
__device__ __forceinline__ void mma16816(float* c, const uint32_t* a, const uint32_t* b) {
    asm volatile("mma.sync.aligned.m16n8k16.row.col.f32.f16.f16.f32 "
                 "{%0,%1,%2,%3}, {%4,%5,%6,%7}, {%8,%9}, {%0,%1,%2,%3};"
                 : "+f"(c[0]), "+f"(c[1]), "+f"(c[2]), "+f"(c[3])
                 : "r"(a[0]), "r"(a[1]), "r"(a[2]), "r"(a[3]), "r"(b[0]), "r"(b[1]));
}
// swizzle for 128B rows, 16B granules
__device__ __forceinline__ uint32_t swz(int r, int g) {
    return (uint32_t)r * 128u + ((uint32_t)(g ^ (r & 7)) << 4);
}

// ----------------------------- GEMM (fp16x3 mma.sync) ---------------------
// C[M, n_real] = (Ahi+Alo) @ (Whi+Wlo)^T + bias, fp32 accumulation.
// block 128 x 112, BK=64, single-buffered (2 CTAs/SM overlap). 8 warps 4x2.
// If probs != null: capsule-u mode; epilogue computes h = probs @ (u + bias)
// and writes Hhi/Hlo (stride KPAD_CAP) and optionally Dhi/Dlo (decoder layout).
#define OFF_ALO 16384u
#define OFF_WHI 32768u
#define OFF_WLO 47104u
#define SMEM_BYTES 61440

__global__ __launch_bounds__(256, 2)
void gemm_mma(const __half* __restrict__ Ahi, const __half* __restrict__ Alo, int lda,
              const __half* __restrict__ Whi, const __half* __restrict__ Wlo, int ldw,
              const float* __restrict__ bias,
              float* __restrict__ Cf, __half* __restrict__ Chi, __half* __restrict__ Clo,
              int ldc, int K, int n_real, int relu,
              const float* __restrict__ probs,
              __half* __restrict__ Hhi, __half* __restrict__ Hlo,
              __half* __restrict__ Dhi, __half* __restrict__ Dlo)
{
    extern __shared__ char smem[];
    const uint32_t sb = smem_u32(smem);
    const int tid = threadIdx.x;
    const int lane = tid & 31;
    const int wid = tid >> 5;
    const int wm = wid & 3;
    const int wn = wid >> 2;
    const int m0 = blockIdx.y * 128;
    const int n0 = blockIdx.x * 112;

    float acc[2][7][4];
#pragma unroll
    for (int i = 0; i < 2; i++)
#pragma unroll
        for (int j = 0; j < 7; j++)
#pragma unroll
            for (int v = 0; v < 4; v++) acc[i][j][v] = 0.f;

    for (int kc = 0; kc < K; kc += 64) {
        const int cur = min(64, K - kc);
        const int gc = cur >> 3;               // granules/row: 8 or 2
        const int gsh = (gc == 8) ? 3 : 1;
        const int gm = gc - 1;

        if (kc > 0) __syncthreads();

        for (int idx = tid; idx < 128 * gc; idx += 256) {
            int r = idx >> gsh, g = idx & gm;
            size_t src = (size_t)(m0 + r) * lda + kc + g * 8;
            uint32_t d = sb + swz(r, g);
            cp_async16(d, Ahi + src);
            cp_async16(d + OFF_ALO, Alo + src);
        }
        for (int idx = tid; idx < 112 * gc; idx += 256) {
            int r = idx >> gsh, g = idx & gm;
            size_t src = (size_t)(n0 + r) * ldw + kc + g * 8;
            uint32_t d = sb + OFF_WHI + swz(r, g);
            cp_async16(d, Whi + src);
            cp_async16(d + (OFF_WLO - OFF_WHI), Wlo + src);
        }
        asm volatile("cp.async.commit_group;");
        asm volatile("cp.async.wait_group 0;");
        __syncthreads();

        const int nks = cur >> 4;
        const uint32_t sw = sb + OFF_WHI;

        for (int ks = 0; ks < nks; ks++) {
            uint32_t ah[2][4], al[2][4], bh[7][2], bl[7][2];
#pragma unroll
            for (int mf = 0; mf < 2; mf++) {
                int r = wm * 32 + mf * 16 + (lane & 15);
                int g = ks * 2 + (lane >> 4);
                uint32_t off = swz(r, g);
                ldsm_x4(ah[mf], sb + off);
                ldsm_x4(al[mf], sb + OFF_ALO + off);
            }
#pragma unroll
            for (int p = 0; p < 3; p++) {
                int r = wn * 56 + p * 16 + (lane & 7) + ((lane >> 4) & 1) * 8;
                int g = ks * 2 + ((lane >> 3) & 1);
                uint32_t off = swz(r, g);
                uint32_t t4[4];
                ldsm_x4(t4, sw + off);
                bh[2*p][0] = t4[0]; bh[2*p][1] = t4[1];
                bh[2*p+1][0] = t4[2]; bh[2*p+1][1] = t4[3];
                ldsm_x4(t4, sw + (OFF_WLO - OFF_WHI) + off);
                bl[2*p][0] = t4[0]; bl[2*p][1] = t4[1];
                bl[2*p+1][0] = t4[2]; bl[2*p+1][1] = t4[3];
            }
            {
                int l15 = lane & 15;
                int r = wn * 56 + 48 + (l15 & 7);
                int g = ks * 2 + ((l15 >> 3) & 1);
                uint32_t off = swz(r, g);
                ldsm_x2(bh[6], sw + off);
                ldsm_x2(bl[6], sw + (OFF_WLO - OFF_WHI) + off);
            }
#pragma unroll
            for (int mf = 0; mf < 2; mf++)
#pragma unroll
                for (int nf = 0; nf < 7; nf++) {
                    mma16816(acc[mf][nf], ah[mf], bh[nf]);   // hi*hi
                    mma16816(acc[mf][nf], al[mf], bh[nf]);   // lo*hi
                    mma16816(acc[mf][nf], ah[mf], bl[nf]);   // hi*lo
                }
        }
    }

    if (probs) {
        // fused attention epilogue: u in acc; h[t] = sum_s p[t][s] * (u[s]+bias)
#pragma unroll
        for (int mf = 0; mf < 2; mf++)
#pragma unroll
        for (int hf = 0; hf < 2; hf++) {
            int row = m0 + wm * 32 + mf * 16 + hf * 8 + (lane >> 2);
            int batch = row >> 2, t = row & 3;
            float4 pv = *(const float4*)(probs + (size_t)batch * 16 + t * 4);
            int base = (lane >> 2) & 4;
#pragma unroll
            for (int nf = 0; nf < 7; nf++)
#pragma unroll
            for (int e = 0; e < 2; e++) {
                int c = n0 + wn * 56 + nf * 8 + ((lane & 3) << 1) + e;
                float uv = acc[mf][nf][hf * 2 + e] + ((c < n_real) ? bias[c] : 0.f);
                float h = 0.f;
#pragma unroll
                for (int s = 0; s < 4; s++) {
                    float us = __shfl_sync(0xffffffffu, uv, ((base + s) << 2) | (lane & 3));
                    float ps = (s == 0) ? pv.x : (s == 1) ? pv.y : (s == 2) ? pv.z : pv.w;
                    h = fmaf(ps, us, h);
                }
                if (c < n_real) {
                    __half hi = __float2half_rn(h);
                    __half lo = __float2half_rn(h - __half2float(hi));
                    size_t ho = (size_t)row * KPAD_CAP + c;
                    Hhi[ho] = hi; Hlo[ho] = lo;
                    if (Dhi) {
                        size_t dof = (size_t)batch * FEAT + t * FV + c;
                        Dhi[dof] = hi; Dlo[dof] = lo;
                    }
                }
            }
        }
    } else {
#pragma unroll
        for (int mf = 0; mf < 2; mf++)
#pragma unroll
        for (int nf = 0; nf < 7; nf++) {
            int r = m0 + wm * 32 + mf * 16 + (lane >> 2);
            int c = n0 + wn * 56 + nf * 8 + ((lane & 3) << 1);
#pragma unroll
            for (int hf = 0; hf < 2; hf++) {
                int rr = r + hf * 8;
#pragma unroll
                for (int e = 0; e < 2; e++) {
                    int cc = c + e;
                    if (cc >= n_real) continue;
                    float v = acc[mf][nf][hf * 2 + e] + bias[cc];
                    if (relu) v = fmaxf(v, 0.f);
                    size_t o = (size_t)rr * ldc + cc;
                    if (Cf) Cf[o] = v;
                    if (Chi) {
                        __half hi = __float2half_rn(v);
                        Chi[o] = hi;
                        Clo[o] = __float2half_rn(v - __half2float(hi));
                    }
                }
            }
        }
    }
}

// ----------------------------- precompute ----------------------------------
// Gt[n,k] = sum_j W1[j,k] * W2[j,n]   (so z = v @ Gt^T = v @ (W1^T W2))
// g2[k]   = sum_j b1[j] * W2[j,k]
__global__ void compute_gt(const float* __restrict__ W1, const float* __restrict__ W2,
                           const float* __restrict__ b1,
                           __half* __restrict__ gthi, __half* __restrict__ gtlo,
                           float* __restrict__ g2, float* __restrict__ zbias)
{
    int idx = blockIdx.x * blockDim.x + threadIdx.x;
    if (idx < FV) {
        float s = 0.f;
        for (int j = 0; j < FV; j++) s = fmaf(b1[j], W2[(size_t)j * FV + idx], s);
        g2[idx] = s;
    }
    if (idx < NPAD_CAP) zbias[idx] = 0.f;
    if (idx >= NPAD_CAP * KPAD_CAP) return;
    int n = idx / KPAD_CAP, k = idx % KPAD_CAP;
    float s = 0.f;
    if (n < FV && k < FV) {
        for (int j = 0; j < FV; j++)
            s = fmaf(W1[(size_t)j * FV + k], W2[(size_t)j * FV + n], s);
    }
    __half hi = __float2half_rn(s);
    gthi[idx] = hi;
    gtlo[idx] = __float2half_rn(s - __half2float(hi));
}

// ----------------------------- conversions --------------------------------
__global__ void convert_x_kernel(const float* __restrict__ x,
                                 __half* __restrict__ hhi, __half* __restrict__ hlo,
                                 __half* __restrict__ hhi2, __half* __restrict__ hlo2)
{
    size_t idx = (size_t)blockIdx.x * blockDim.x + threadIdx.x;
    if (idx >= (size_t)BROWS * KPAD_CAP) return;
    size_t R = idx / KPAD_CAP;
    int f = (int)(idx % KPAD_CAP);
    float v = (f < FV) ? x[R * FV + f] : 0.f;
    __half hi = __float2half_rn(v);
    __half lo = __float2half_rn(v - __half2float(hi));
    hhi[idx] = hi;  hlo[idx] = lo;
    hhi2[idx] = hi; hlo2[idx] = lo;   // pad columns zero in both buffers
}

__global__ void convert_w_kernel(const float* __restrict__ W, int rin, int cin,
                                 __half* __restrict__ hi, __half* __restrict__ lo,
                                 int rout, int cout)
{
    int idx = blockIdx.x * blockDim.x + threadIdx.x;
    if (idx >= rout * cout) return;
    int r = idx / cout, c = idx % cout;
    float v = (r < rin && c < cin) ? W[(size_t)r * cin + c] : 0.f;
    __half h = __float2half_rn(v);
    hi[idx] = h;
    lo[idx] = __float2half_rn(v - __half2float(h));
}

// ----------------------------- scores (fp32) -------------------------------
// probs[b,t,s] = softmax_s( z_t . v_s + beta_s ),  beta_s = v_s . g2
__global__ __launch_bounds__(256)
void score_kernel(const float* __restrict__ z,
                  const __half* __restrict__ hhi, const __half* __restrict__ hlo,
                  const float* __restrict__ g2, float* __restrict__ probs)
{
    const int b    = blockIdx.x * 8 + threadIdx.y;
    const int lane = threadIdx.x;
    const float* zb = z + (size_t)b * 4 * FV;
    const __half* vhi = hhi + (size_t)b * 4 * KPAD_CAP;
    const __half* vlo = hlo + (size_t)b * 4 * KPAD_CAP;

    float s[4][4], beta[4];
#pragma unroll
    for (int t = 0; t < 4; t++) {
        beta[t] = 0.f;
#pragma unroll
        for (int r = 0; r < 4; r++) s[t][r] = 0.f;
    }

    for (int f = lane; f < FV; f += 32) {
        float zt[4], vs[4];
        float g2f = g2[f];
#pragma unroll
        for (int t = 0; t < 4; t++) {
            zt[t] = zb[t * FV + f];
            vs[t] = __half2float(vhi[t * KPAD_CAP + f]) + __half2float(vlo[t * KPAD_CAP + f]);
        }
#pragma unroll
        for (int t = 0; t < 4; t++) {
            beta[t] = fmaf(vs[t], g2f, beta[t]);
#pragma unroll
            for (int r = 0; r < 4; r++)
                s[t][r] = fmaf(zt[t], vs[r], s[t][r]);
        }
    }
#pragma unroll
    for (int t = 0; t < 4; t++) {
#pragma unroll
        for (int off = 16; off > 0; off >>= 1)
            beta[t] += __shfl_xor_sync(0xffffffffu, beta[t], off);
#pragma unroll
        for (int r = 0; r < 4; r++)
#pragma unroll
            for (int off = 16; off > 0; off >>= 1)
                s[t][r] += __shfl_xor_sync(0xffffffffu, s[t][r], off);
    }

    float p[4][4];
#pragma unroll
    for (int t = 0; t < 4; t++) {
        float sc[4];
#pragma unroll
        for (int r = 0; r < 4; r++) sc[r] = s[t][r] + beta[r];
        float m = fmaxf(fmaxf(sc[0], sc[1]), fmaxf(sc[2], sc[3]));
        float e0 = expf(sc[0] - m), e1 = expf(sc[1] - m);
        float e2 = expf(sc[2] - m), e3 = expf(sc[3] - m);
        float inv = 1.f / (e0 + e1 + e2 + e3);
        p[t][0] = e0 * inv; p[t][1] = e1 * inv; p[t][2] = e2 * inv; p[t][3] = e3 * inv;
    }
    if (lane < 16)
        probs[(size_t)b * 16 + lane] = p[lane >> 2][lane & 3];
}

// ----------------------------- head ----------------------------------------
__global__ __launch_bounds__(256)
void head_kernel(const float* __restrict__ A, const float* __restrict__ Wo,
                 const float* __restrict__ bo, float* __restrict__ out)
{
    const int b    = blockIdx.x * 8 + threadIdx.y;
    const int lane = threadIdx.x;
    const float* a = A + (size_t)b * FEAT;

    float acc[10];
#pragma unroll
    for (int j = 0; j < 10; j++) acc[j] = 0.f;
    for (int kk = lane; kk < FEAT; kk += 32) {
        float av = a[kk];
#pragma unroll
        for (int j = 0; j < 10; j++)
            acc[j] = fmaf(av, Wo[j * FEAT + kk], acc[j]);
    }
#pragma unroll
    for (int j = 0; j < 10; j++)
#pragma unroll
        for (int off = 16; off > 0; off >>= 1)
            acc[j] += __shfl_xor_sync(0xffffffffu, acc[j], off);

    if (lane == 0) {
        float v[10], m = -1e30f;
#pragma unroll
        for (int j = 0; j < 10; j++) { v[j] = acc[j] + bo[j]; m = fmaxf(m, v[j]); }
        float ssum = 0.f;
#pragma unroll
        for (int j = 0; j < 10; j++) { v[j] = expf(v[j] - m); ssum += v[j]; }
        float inv = 1.f / ssum;
#pragma unroll
        for (int j = 0; j < 10; j++) out[(size_t)b * 10 + j] = v[j] * inv;
    }
}

// ---------------------------------------------------------------------------
extern "C" void kernel_launch(void* const* d_in, const int* in_sizes, int n_in,
                              void* d_out, int out_size)
{
    const float* x   = (const float*)d_in[0];
    const float* W1  = (const float*)d_in[1];
    const float* b1  = (const float*)d_in[2];
    const float* W2  = (const float*)d_in[3];
    const float* b3  = (const float*)d_in[6];
    const float* W3  = (const float*)d_in[5];
    const float* Wd1 = (const float*)d_in[7];
    const float* bd1 = (const float*)d_in[8];
    const float* Wd2 = (const float*)d_in[9];
    const float* bd2 = (const float*)d_in[10];
    const float* Wo  = (const float*)d_in[11];
    const float* bo  = (const float*)d_in[12];
    float* out = (float*)d_out;

    cudaFuncSetAttribute(gemm_mma, cudaFuncAttributeMaxDynamicSharedMemorySize, SMEM_BYTES);

    __half *hhi, *hlo, *hhi2, *hlo2, *gthi, *gtlo, *w3hi, *w3lo;
    __half *wd1hi, *wd1lo, *wd2hi, *wd2lo, *dhi, *dlo, *thi, *tlo;
    float *z, *p, *g2, *dec, *zbias;
    cudaGetSymbolAddress((void**)&hhi, g_hhi);     cudaGetSymbolAddress((void**)&hlo, g_hlo);
    cudaGetSymbolAddress((void**)&hhi2, g_hhi2);   cudaGetSymbolAddress((void**)&hlo2, g_hlo2);
    cudaGetSymbolAddress((void**)&z, g_z);         cudaGetSymbolAddress((void**)&p, g_p);
    cudaGetSymbolAddress((void**)&g2, g_g2);       cudaGetSymbolAddress((void**)&dec, g_dec);
    cudaGetSymbolAddress((void**)&gthi, g_gthi);   cudaGetSymbolAddress((void**)&gtlo, g_gtlo);
    cudaGetSymbolAddress((void**)&w3hi, g_w3hi);   cudaGetSymbolAddress((void**)&w3lo, g_w3lo);
    cudaGetSymbolAddress((void**)&wd1hi, g_wd1hi); cudaGetSymbolAddress((void**)&wd1lo, g_wd1lo);
    cudaGetSymbolAddress((void**)&wd2hi, g_wd2hi); cudaGetSymbolAddress((void**)&wd2lo, g_wd2lo);
    cudaGetSymbolAddress((void**)&dhi, g_dhi);     cudaGetSymbolAddress((void**)&dlo, g_dlo);
    cudaGetSymbolAddress((void**)&thi, g_thi);     cudaGetSymbolAddress((void**)&tlo, g_tlo);
    cudaGetSymbolAddress((void**)&zbias, g_zero_bias);

    // precompute + conversions
    convert_x_kernel<<<(int)(((size_t)BROWS * KPAD_CAP + 255) / 256), 256>>>(x, hhi, hlo, hhi2, hlo2);
    int wcap = NPAD_CAP * KPAD_CAP;
    compute_gt<<<(wcap + 255) / 256, 256>>>(W1, W2, b1, gthi, gtlo, g2, zbias);
    convert_w_kernel<<<(wcap + 255) / 256, 256>>>(W3, FV, FV, w3hi, w3lo, NPAD_CAP, KPAD_CAP);
    int wdec = FEAT * FEAT;
    convert_w_kernel<<<(wdec + 255) / 256, 256>>>(Wd1, FEAT, FEAT, wd1hi, wd1lo, FEAT, FEAT);
    convert_w_kernel<<<(wdec + 255) / 256, 256>>>(Wd2, FEAT, FEAT, wd2hi, wd2lo, FEAT, FEAT);

    // capsule iterations (h double-buffered: read cur, write nxt)
    const dim3 gcap(2, BROWS / 128);
    for (int it = 0; it < NITER; it++) {
        __half* chi = (it & 1) ? hhi2 : hhi;
        __half* clo = (it & 1) ? hlo2 : hlo;
        __half* nhi = (it & 1) ? hhi : hhi2;
        __half* nlo = (it & 1) ? hlo : hlo2;
        int last = (it == NITER - 1);
        // z = v @ (W1^T W2)
        gemm_mma<<<gcap, 256, SMEM_BYTES>>>(chi, clo, KPAD_CAP, gthi, gtlo, KPAD_CAP, zbias,
                                            z, nullptr, nullptr, FV, KPAD_CAP, FV, 0,
                                            nullptr, nullptr, nullptr, nullptr, nullptr);
        score_kernel<<<BATCH / 8, dim3(32, 8)>>>(z, chi, clo, g2, p);
        // u GEMM with fused h = probs @ (u + b3)
        gemm_mma<<<gcap, 256, SMEM_BYTES>>>(chi, clo, KPAD_CAP, w3hi, w3lo, KPAD_CAP, b3,
                                            nullptr, nullptr, nullptr, 0, KPAD_CAP, FV, 0,
                                            p, nhi, nlo,
                                            last ? dhi : nullptr, last ? dlo : nullptr);
    }

    // decoder
    const dim3 gdec(7, BATCH / 128);
    gemm_mma<<<gdec, 256, SMEM_BYTES>>>(dhi, dlo, FEAT, wd1hi, wd1lo, FEAT, bd1,
                                        nullptr, thi, tlo, FEAT, FEAT, FEAT, 1,
                                        nullptr, nullptr, nullptr, nullptr, nullptr);
    gemm_mma<<<gdec, 256, SMEM_BYTES>>>(thi, tlo, FEAT, wd2hi, wd2lo, FEAT, bd2,
                                        dec, nullptr, nullptr, FEAT, FEAT, FEAT, 0,
                                        nullptr, nullptr, nullptr, nullptr, nullptr);
    head_kernel<<<BATCH / 8, dim3(32, 8)>>>(dec, Wo, bo, out);
}

// round 6
// speedup vs baseline: 1.3467x; 1.0682x over previous
#include <cuda_runtime.h>
#include <cuda_fp16.h>
#include <math.h>
#include <stdint.h>

#define BATCH 32768
#define FEAT  784
#define FV    196
#define NITER 8
#define BROWS (BATCH * 4)        // 131072 capsule rows

#define KPAD_CAP 208             // capsule K padded (13*16)
#define NPAD_CAP 224             // capsule N padded (2*112)

// ----------------------------- scratch ------------------------------------
__device__ __align__(256) __half g_hhi [(size_t)BROWS * KPAD_CAP];
__device__ __align__(256) __half g_hlo [(size_t)BROWS * KPAD_CAP];
__device__ __align__(256) __half g_hhi2[(size_t)BROWS * KPAD_CAP];
__device__ __align__(256) __half g_hlo2[(size_t)BROWS * KPAD_CAP];
__device__ __align__(256) float  g_z[(size_t)BROWS * FV];
__device__ __align__(256) float  g_p[(size_t)BATCH * 16];
__device__ __align__(256) __half g_gthi[NPAD_CAP * KPAD_CAP], g_gtlo[NPAD_CAP * KPAD_CAP];
__device__ __align__(256) float  g_g2[FV];
__device__ __align__(256) __half g_w3hi[NPAD_CAP * KPAD_CAP], g_w3lo[NPAD_CAP * KPAD_CAP];
__device__ __align__(256) __half g_wd1hi[FEAT * FEAT], g_wd1lo[FEAT * FEAT];
__device__ __align__(256) __half g_wd2hi[FEAT * FEAT], g_wd2lo[FEAT * FEAT];
__device__ __align__(256) __half g_dhi[(size_t)BATCH * FEAT], g_dlo[(size_t)BATCH * FEAT];
__device__ __align__(256) __half g_thi[(size_t)BATCH * FEAT], g_tlo[(size_t)BATCH * FEAT];
__device__ __align__(256) float  g_dec[(size_t)BATCH * FEAT];
__device__ __align__(256) float  g_zero_bias[NPAD_CAP];

// ----------------------------- PTX helpers --------------------------------
__device__ __forceinline__ uint32_t smem_u32(const void* p) {
    uint32_t a;
    asm("{ .reg .u64 t; cvta.to.shared.u64 t, %1; cvt.u32.u64 %0, t; }" : "=r"(a) : "l"(p));
    return a;
}
__device__ __forceinline__ void cp_async16(uint32_t dst, const void* src) {
    asm volatile("cp.async.cg.shared.global [%0], [%1], 16;" :: "r"(dst), "l"(src));
}
__device__ __forceinline__ void ldsm_x4(uint32_t* r, uint32_t addr) {
    asm volatile("ldmatrix.sync.aligned.m8n8.x4.shared.b16 {%0,%1,%2,%3}, [%4];"
                 : "=r"(r[0]), "=r"(r[1]), "=r"(r[2]), "=r"(r[3]) : "r"(addr));
}
__device__ __forceinline__ void ldsm_x2(uint32_t* r, uint32_t addr) {
    asm volatile("ldmatrix.sync.aligned.m8n8.x2.shared.b16 {%0,%1}, [%2];"
                 : "=r"(r[0]), "=r"(r[1]) : "r"(addr));
}
__device__ __forceinline__ void mma16816(float* c, const uint32_t* a, const uint32_t* b) {
    asm volatile("mma.sync.aligned.m16n8k16.row.col.f32.f16.f16.f32 "
                 "{%0,%1,%2,%3}, {%4,%5,%6,%7}, {%8,%9}, {%0,%1,%2,%3};"
                 : "+f"(c[0]), "+f"(c[1]), "+f"(c[2]), "+f"(c[3])
                 : "r"(a[0]), "r"(a[1]), "r"(a[2]), "r"(a[3]), "r"(b[0]), "r"(b[1]));
}
// swizzle for 128B rows, 16B granules
__device__ __forceinline__ uint32_t swz(int r, int g) {
    return (uint32_t)r * 128u + ((uint32_t)(g ^ (r & 7)) << 4);
}

// ----------------------------- GEMM (fp16 emulated-fp32 mma.sync) ---------
// C[M, n_real] = (Ahi+Alo) @ (Whi[+Wlo])^T + bias, fp32 accumulation.
// WLO=1: 3-pass (hi*hi + lo*hi + hi*lo). WLO=0: 2-pass (hi*hi + lo*hi).
// block 128 x 112, BK=64, single-buffered (2 CTAs/SM overlap). 8 warps 4x2.
// If probs != null: capsule-u mode; epilogue computes h = probs @ (u + bias)
// and writes Hhi/Hlo (stride KPAD_CAP) and optionally Dhi/Dlo (decoder layout).
#define OFF_ALO 16384u
#define OFF_WHI 32768u
#define OFF_WLO 47104u
#define SMEM_BYTES 61440

template <int WLO>
__global__ __launch_bounds__(256, 2)
void gemm_mma(const __half* __restrict__ Ahi, const __half* __restrict__ Alo, int lda,
              const __half* __restrict__ Whi, const __half* __restrict__ Wlo, int ldw,
              const float* __restrict__ bias,
              float* __restrict__ Cf, __half* __restrict__ Chi, __half* __restrict__ Clo,
              int ldc, int K, int n_real, int relu,
              const float* __restrict__ probs,
              __half* __restrict__ Hhi, __half* __restrict__ Hlo,
              __half* __restrict__ Dhi, __half* __restrict__ Dlo)
{
    extern __shared__ char smem[];
    const uint32_t sb = smem_u32(smem);
    const int tid = threadIdx.x;
    const int lane = tid & 31;
    const int wid = tid >> 5;
    const int wm = wid & 3;
    const int wn = wid >> 2;
    const int m0 = blockIdx.y * 128;
    const int n0 = blockIdx.x * 112;

    float acc[2][7][4];
#pragma unroll
    for (int i = 0; i < 2; i++)
#pragma unroll
        for (int j = 0; j < 7; j++)
#pragma unroll
            for (int v = 0; v < 4; v++) acc[i][j][v] = 0.f;

    for (int kc = 0; kc < K; kc += 64) {
        const int cur = min(64, K - kc);
        const int gc = cur >> 3;               // granules/row: 8 or 2
        const int gsh = (gc == 8) ? 3 : 1;
        const int gm = gc - 1;

        if (kc > 0) __syncthreads();

        for (int idx = tid; idx < 128 * gc; idx += 256) {
            int r = idx >> gsh, g = idx & gm;
            size_t src = (size_t)(m0 + r) * lda + kc + g * 8;
            uint32_t d = sb + swz(r, g);
            cp_async16(d, Ahi + src);
            cp_async16(d + OFF_ALO, Alo + src);
        }
        for (int idx = tid; idx < 112 * gc; idx += 256) {
            int r = idx >> gsh, g = idx & gm;
            size_t src = (size_t)(n0 + r) * ldw + kc + g * 8;
            uint32_t d = sb + OFF_WHI + swz(r, g);
            cp_async16(d, Whi + src);
            if (WLO) cp_async16(d + (OFF_WLO - OFF_WHI), Wlo + src);
        }
        asm volatile("cp.async.commit_group;");
        asm volatile("cp.async.wait_group 0;");
        __syncthreads();

        const int nks = cur >> 4;
        const uint32_t sw = sb + OFF_WHI;

        for (int ks = 0; ks < nks; ks++) {
            uint32_t ah[2][4], al[2][4], bh[7][2], bl[7][2];
#pragma unroll
            for (int mf = 0; mf < 2; mf++) {
                int r = wm * 32 + mf * 16 + (lane & 15);
                int g = ks * 2 + (lane >> 4);
                uint32_t off = swz(r, g);
                ldsm_x4(ah[mf], sb + off);
                ldsm_x4(al[mf], sb + OFF_ALO + off);
            }
#pragma unroll
            for (int p = 0; p < 3; p++) {
                int r = wn * 56 + p * 16 + (lane & 7) + ((lane >> 4) & 1) * 8;
                int g = ks * 2 + ((lane >> 3) & 1);
                uint32_t off = swz(r, g);
                uint32_t t4[4];
                ldsm_x4(t4, sw + off);
                bh[2*p][0] = t4[0]; bh[2*p][1] = t4[1];
                bh[2*p+1][0] = t4[2]; bh[2*p+1][1] = t4[3];
                if (WLO) {
                    ldsm_x4(t4, sw + (OFF_WLO - OFF_WHI) + off);
                    bl[2*p][0] = t4[0]; bl[2*p][1] = t4[1];
                    bl[2*p+1][0] = t4[2]; bl[2*p+1][1] = t4[3];
                }
            }
            {
                int l15 = lane & 15;
                int r = wn * 56 + 48 + (l15 & 7);
                int g = ks * 2 + ((l15 >> 3) & 1);
                uint32_t off = swz(r, g);
                ldsm_x2(bh[6], sw + off);
                if (WLO) ldsm_x2(bl[6], sw + (OFF_WLO - OFF_WHI) + off);
            }
#pragma unroll
            for (int mf = 0; mf < 2; mf++)
#pragma unroll
                for (int nf = 0; nf < 7; nf++) {
                    mma16816(acc[mf][nf], ah[mf], bh[nf]);          // hi*hi
                    mma16816(acc[mf][nf], al[mf], bh[nf]);          // lo*hi
                    if (WLO) mma16816(acc[mf][nf], ah[mf], bl[nf]); // hi*lo
                }
        }
    }

    if (probs) {
        // fused attention epilogue: u in acc; h[t] = sum_s p[t][s] * (u[s]+bias)
#pragma unroll
        for (int mf = 0; mf < 2; mf++)
#pragma unroll
        for (int hf = 0; hf < 2; hf++) {
            int row = m0 + wm * 32 + mf * 16 + hf * 8 + (lane >> 2);
            int batch = row >> 2, t = row & 3;
            float4 pv = *(const float4*)(probs + (size_t)batch * 16 + t * 4);
            int base = (lane >> 2) & 4;
#pragma unroll
            for (int nf = 0; nf < 7; nf++)
#pragma unroll
            for (int e = 0; e < 2; e++) {
                int c = n0 + wn * 56 + nf * 8 + ((lane & 3) << 1) + e;
                float uv = acc[mf][nf][hf * 2 + e] + ((c < n_real) ? bias[c] : 0.f);
                float h = 0.f;
#pragma unroll
                for (int s = 0; s < 4; s++) {
                    float us = __shfl_sync(0xffffffffu, uv, ((base + s) << 2) | (lane & 3));
                    float ps = (s == 0) ? pv.x : (s == 1) ? pv.y : (s == 2) ? pv.z : pv.w;
                    h = fmaf(ps, us, h);
                }
                if (c < n_real) {
                    __half hi = __float2half_rn(h);
                    __half lo = __float2half_rn(h - __half2float(hi));
                    size_t ho = (size_t)row * KPAD_CAP + c;
                    Hhi[ho] = hi; Hlo[ho] = lo;
                    if (Dhi) {
                        size_t dof = (size_t)batch * FEAT + t * FV + c;
                        Dhi[dof] = hi; Dlo[dof] = lo;
                    }
                }
            }
        }
    } else {
#pragma unroll
        for (int mf = 0; mf < 2; mf++)
#pragma unroll
        for (int nf = 0; nf < 7; nf++) {
            int r = m0 + wm * 32 + mf * 16 + (lane >> 2);
            int c = n0 + wn * 56 + nf * 8 + ((lane & 3) << 1);
#pragma unroll
            for (int hf = 0; hf < 2; hf++) {
                int rr = r + hf * 8;
#pragma unroll
                for (int e = 0; e < 2; e++) {
                    int cc = c + e;
                    if (cc >= n_real) continue;
                    float v = acc[mf][nf][hf * 2 + e] + bias[cc];
                    if (relu) v = fmaxf(v, 0.f);
                    size_t o = (size_t)rr * ldc + cc;
                    if (Cf) Cf[o] = v;
                    if (Chi) {
                        __half hi = __float2half_rn(v);
                        Chi[o] = hi;
                        Clo[o] = __float2half_rn(v - __half2float(hi));
                    }
                }
            }
        }
    }
}

// ----------------------------- precompute ----------------------------------
// Gt[n,k] = sum_j W1[j,k] * W2[j,n]   (so z = v @ Gt^T = v @ (W1^T W2))
// g2[k]   = sum_j b1[j] * W2[j,k]
__global__ void compute_gt(const float* __restrict__ W1, const float* __restrict__ W2,
                           const float* __restrict__ b1,
                           __half* __restrict__ gthi, __half* __restrict__ gtlo,
                           float* __restrict__ g2, float* __restrict__ zbias)
{
    int idx = blockIdx.x * blockDim.x + threadIdx.x;
    if (idx < FV) {
        float s = 0.f;
        for (int j = 0; j < FV; j++) s = fmaf(b1[j], W2[(size_t)j * FV + idx], s);
        g2[idx] = s;
    }
    if (idx < NPAD_CAP) zbias[idx] = 0.f;
    if (idx >= NPAD_CAP * KPAD_CAP) return;
    int n = idx / KPAD_CAP, k = idx % KPAD_CAP;
    float s = 0.f;
    if (n < FV && k < FV) {
        for (int j = 0; j < FV; j++)
            s = fmaf(W1[(size_t)j * FV + k], W2[(size_t)j * FV + n], s);
    }
    __half hi = __float2half_rn(s);
    gthi[idx] = hi;
    gtlo[idx] = __float2half_rn(s - __half2float(hi));
}

// ----------------------------- conversions --------------------------------
__global__ void convert_x_kernel(const float* __restrict__ x,
                                 __half* __restrict__ hhi, __half* __restrict__ hlo,
                                 __half* __restrict__ hhi2, __half* __restrict__ hlo2)
{
    size_t idx = (size_t)blockIdx.x * blockDim.x + threadIdx.x;
    if (idx >= (size_t)BROWS * KPAD_CAP) return;
    size_t R = idx / KPAD_CAP;
    int f = (int)(idx % KPAD_CAP);
    float v = (f < FV) ? x[R * FV + f] : 0.f;
    __half hi = __float2half_rn(v);
    __half lo = __float2half_rn(v - __half2float(hi));
    hhi[idx] = hi;  hlo[idx] = lo;
    hhi2[idx] = hi; hlo2[idx] = lo;   // pad columns zero in both buffers
}

__global__ void convert_w_kernel(const float* __restrict__ W, int rin, int cin,
                                 __half* __restrict__ hi, __half* __restrict__ lo,
                                 int rout, int cout)
{
    int idx = blockIdx.x * blockDim.x + threadIdx.x;
    if (idx >= rout * cout) return;
    int r = idx / cout, c = idx % cout;
    float v = (r < rin && c < cin) ? W[(size_t)r * cin + c] : 0.f;
    __half h = __float2half_rn(v);
    hi[idx] = h;
    lo[idx] = __float2half_rn(v - __half2float(h));
}

// ----------------------------- scores (fp32) -------------------------------
// probs[b,t,s] = softmax_s( z_t . v_s + beta_s ),  beta_s = v_s . g2
__global__ __launch_bounds__(256)
void score_kernel(const float* __restrict__ z,
                  const __half* __restrict__ hhi, const __half* __restrict__ hlo,
                  const float* __restrict__ g2, float* __restrict__ probs)
{
    const int b    = blockIdx.x * 8 + threadIdx.y;
    const int lane = threadIdx.x;
    const float* zb = z + (size_t)b * 4 * FV;
    const __half* vhi = hhi + (size_t)b * 4 * KPAD_CAP;
    const __half* vlo = hlo + (size_t)b * 4 * KPAD_CAP;

    float s[4][4], beta[4];
#pragma unroll
    for (int t = 0; t < 4; t++) {
        beta[t] = 0.f;
#pragma unroll
        for (int r = 0; r < 4; r++) s[t][r] = 0.f;
    }

    for (int f = lane; f < FV; f += 32) {
        float zt[4], vs[4];
        float g2f = g2[f];
#pragma unroll
        for (int t = 0; t < 4; t++) {
            zt[t] = zb[t * FV + f];
            vs[t] = __half2float(vhi[t * KPAD_CAP + f]) + __half2float(vlo[t * KPAD_CAP + f]);
        }
#pragma unroll
        for (int t = 0; t < 4; t++) {
            beta[t] = fmaf(vs[t], g2f, beta[t]);
#pragma unroll
            for (int r = 0; r < 4; r++)
                s[t][r] = fmaf(zt[t], vs[r], s[t][r]);
        }
    }
#pragma unroll
    for (int t = 0; t < 4; t++) {
#pragma unroll
        for (int off = 16; off > 0; off >>= 1)
            beta[t] += __shfl_xor_sync(0xffffffffu, beta[t], off);
#pragma unroll
        for (int r = 0; r < 4; r++)
#pragma unroll
            for (int off = 16; off > 0; off >>= 1)
                s[t][r] += __shfl_xor_sync(0xffffffffu, s[t][r], off);
    }

    float p[4][4];
#pragma unroll
    for (int t = 0; t < 4; t++) {
        float sc[4];
#pragma unroll
        for (int r = 0; r < 4; r++) sc[r] = s[t][r] + beta[r];
        float m = fmaxf(fmaxf(sc[0], sc[1]), fmaxf(sc[2], sc[3]));
        float e0 = expf(sc[0] - m), e1 = expf(sc[1] - m);
        float e2 = expf(sc[2] - m), e3 = expf(sc[3] - m);
        float inv = 1.f / (e0 + e1 + e2 + e3);
        p[t][0] = e0 * inv; p[t][1] = e1 * inv; p[t][2] = e2 * inv; p[t][3] = e3 * inv;
    }
    if (lane < 16)
        probs[(size_t)b * 16 + lane] = p[lane >> 2][lane & 3];
}

// ----------------------------- head ----------------------------------------
__global__ __launch_bounds__(256)
void head_kernel(const float* __restrict__ A, const float* __restrict__ Wo,
                 const float* __restrict__ bo, float* __restrict__ out)
{
    const int b    = blockIdx.x * 8 + threadIdx.y;
    const int lane = threadIdx.x;
    const float* a = A + (size_t)b * FEAT;

    float acc[10];
#pragma unroll
    for (int j = 0; j < 10; j++) acc[j] = 0.f;
    for (int kk = lane; kk < FEAT; kk += 32) {
        float av = a[kk];
#pragma unroll
        for (int j = 0; j < 10; j++)
            acc[j] = fmaf(av, Wo[j * FEAT + kk], acc[j]);
    }
#pragma unroll
    for (int j = 0; j < 10; j++)
#pragma unroll
        for (int off = 16; off > 0; off >>= 1)
            acc[j] += __shfl_xor_sync(0xffffffffu, acc[j], off);

    if (lane == 0) {
        float v[10], m = -1e30f;
#pragma unroll
        for (int j = 0; j < 10; j++) { v[j] = acc[j] + bo[j]; m = fmaxf(m, v[j]); }
        float ssum = 0.f;
#pragma unroll
        for (int j = 0; j < 10; j++) { v[j] = expf(v[j] - m); ssum += v[j]; }
        float inv = 1.f / ssum;
#pragma unroll
        for (int j = 0; j < 10; j++) out[(size_t)b * 10 + j] = v[j] * inv;
    }
}

// ---------------------------------------------------------------------------
extern "C" void kernel_launch(void* const* d_in, const int* in_sizes, int n_in,
                              void* d_out, int out_size)
{
    const float* x   = (const float*)d_in[0];
    const float* W1  = (const float*)d_in[1];
    const float* b1  = (const float*)d_in[2];
    const float* W2  = (const float*)d_in[3];
    const float* W3  = (const float*)d_in[5];
    const float* b3  = (const float*)d_in[6];
    const float* Wd1 = (const float*)d_in[7];
    const float* bd1 = (const float*)d_in[8];
    const float* Wd2 = (const float*)d_in[9];
    const float* bd2 = (const float*)d_in[10];
    const float* Wo  = (const float*)d_in[11];
    const float* bo  = (const float*)d_in[12];
    float* out = (float*)d_out;

    cudaFuncSetAttribute(gemm_mma<0>, cudaFuncAttributeMaxDynamicSharedMemorySize, SMEM_BYTES);
    cudaFuncSetAttribute(gemm_mma<1>, cudaFuncAttributeMaxDynamicSharedMemorySize, SMEM_BYTES);

    __half *hhi, *hlo, *hhi2, *hlo2, *gthi, *gtlo, *w3hi, *w3lo;
    __half *wd1hi, *wd1lo, *wd2hi, *wd2lo, *dhi, *dlo, *thi, *tlo;
    float *z, *p, *g2, *dec, *zbias;
    cudaGetSymbolAddress((void**)&hhi, g_hhi);     cudaGetSymbolAddress((void**)&hlo, g_hlo);
    cudaGetSymbolAddress((void**)&hhi2, g_hhi2);   cudaGetSymbolAddress((void**)&hlo2, g_hlo2);
    cudaGetSymbolAddress((void**)&z, g_z);         cudaGetSymbolAddress((void**)&p, g_p);
    cudaGetSymbolAddress((void**)&g2, g_g2);       cudaGetSymbolAddress((void**)&dec, g_dec);
    cudaGetSymbolAddress((void**)&gthi, g_gthi);   cudaGetSymbolAddress((void**)&gtlo, g_gtlo);
    cudaGetSymbolAddress((void**)&w3hi, g_w3hi);   cudaGetSymbolAddress((void**)&w3lo, g_w3lo);
    cudaGetSymbolAddress((void**)&wd1hi, g_wd1hi); cudaGetSymbolAddress((void**)&wd1lo, g_wd1lo);
    cudaGetSymbolAddress((void**)&wd2hi, g_wd2hi); cudaGetSymbolAddress((void**)&wd2lo, g_wd2lo);
    cudaGetSymbolAddress((void**)&dhi, g_dhi);     cudaGetSymbolAddress((void**)&dlo, g_dlo);
    cudaGetSymbolAddress((void**)&thi, g_thi);     cudaGetSymbolAddress((void**)&tlo, g_tlo);
    cudaGetSymbolAddress((void**)&zbias, g_zero_bias);

    // precompute + conversions
    convert_x_kernel<<<(int)(((size_t)BROWS * KPAD_CAP + 255) / 256), 256>>>(x, hhi, hlo, hhi2, hlo2);
    int wcap = NPAD_CAP * KPAD_CAP;
    compute_gt<<<(wcap + 255) / 256, 256>>>(W1, W2, b1, gthi, gtlo, g2, zbias);
    convert_w_kernel<<<(wcap + 255) / 256, 256>>>(W3, FV, FV, w3hi, w3lo, NPAD_CAP, KPAD_CAP);
    int wdec = FEAT * FEAT;
    convert_w_kernel<<<(wdec + 255) / 256, 256>>>(Wd1, FEAT, FEAT, wd1hi, wd1lo, FEAT, FEAT);
    convert_w_kernel<<<(wdec + 255) / 256, 256>>>(Wd2, FEAT, FEAT, wd2hi, wd2lo, FEAT, FEAT);

    // capsule iterations (h double-buffered; 2-pass emulation)
    const dim3 gcap(2, BROWS / 128);
    for (int it = 0; it < NITER; it++) {
        __half* chi = (it & 1) ? hhi2 : hhi;
        __half* clo = (it & 1) ? hlo2 : hlo;
        __half* nhi = (it & 1) ? hhi : hhi2;
        __half* nlo = (it & 1) ? hlo : hlo2;
        int last = (it == NITER - 1);
        // z = v @ (W1^T W2)
        gemm_mma<0><<<gcap, 256, SMEM_BYTES>>>(chi, clo, KPAD_CAP, gthi, gtlo, KPAD_CAP, zbias,
                                               z, nullptr, nullptr, FV, KPAD_CAP, FV, 0,
                                               nullptr, nullptr, nullptr, nullptr, nullptr);
        score_kernel<<<BATCH / 8, dim3(32, 8)>>>(z, chi, clo, g2, p);
        // u GEMM with fused h = probs @ (u + b3)
        gemm_mma<0><<<gcap, 256, SMEM_BYTES>>>(chi, clo, KPAD_CAP, w3hi, w3lo, KPAD_CAP, b3,
                                               nullptr, nullptr, nullptr, 0, KPAD_CAP, FV, 0,
                                               p, nhi, nlo,
                                               last ? dhi : nullptr, last ? dlo : nullptr);
    }

    // decoder (3-pass for final precision)
    const dim3 gdec(7, BATCH / 128);
    gemm_mma<1><<<gdec, 256, SMEM_BYTES>>>(dhi, dlo, FEAT, wd1hi, wd1lo, FEAT, bd1,
                                           nullptr, thi, tlo, FEAT, FEAT, FEAT, 1,
                                           nullptr, nullptr, nullptr, nullptr, nullptr);
    gemm_mma<1><<<gdec, 256, SMEM_BYTES>>>(thi, tlo, FEAT, wd2hi, wd2lo, FEAT, bd2,
                                           dec, nullptr, nullptr, FEAT, FEAT, FEAT, 0,
                                           nullptr, nullptr, nullptr, nullptr, nullptr);
    head_kernel<<<BATCH / 8, dim3(32, 8)>>>(dec, Wo, bo, out);
}

// round 7
// speedup vs baseline: 1.7854x; 1.3258x over previous
#include <cuda_runtime.h>
#include <cuda_fp16.h>
#include <math.h>
#include <stdint.h>

#define BATCH 32768
#define FEAT  784
#define FV    196
#define NITER 8
#define BROWS (BATCH * 4)        // 131072 capsule rows

#define KPAD_CAP 208             // capsule K padded (13*16)
#define NPAD_CAP 224             // capsule N padded (2*112)

// ----------------------------- scratch ------------------------------------
__device__ __align__(256) __half g_hhi [(size_t)BROWS * KPAD_CAP];
__device__ __align__(256) __half g_hhi2[(size_t)BROWS * KPAD_CAP];
__device__ __align__(256) float  g_z[(size_t)BROWS * FV];
__device__ __align__(256) float  g_p[(size_t)BATCH * 16];
__device__ __align__(256) __half g_gthi[NPAD_CAP * KPAD_CAP];
__device__ __align__(256) float  g_g2[FV];
__device__ __align__(256) __half g_w3hi[NPAD_CAP * KPAD_CAP];
__device__ __align__(256) __half g_wd1hi[FEAT * FEAT];
__device__ __align__(256) __half g_wd2hi[FEAT * FEAT];
__device__ __align__(256) __half g_dhi[(size_t)BATCH * FEAT], g_dlo[(size_t)BATCH * FEAT];
__device__ __align__(256) __half g_thi[(size_t)BATCH * FEAT], g_tlo[(size_t)BATCH * FEAT];
__device__ __align__(256) float  g_dec[(size_t)BATCH * FEAT];
__device__ __align__(256) float  g_zero_bias[NPAD_CAP];

// ----------------------------- PTX helpers --------------------------------
__device__ __forceinline__ uint32_t smem_u32(const void* p) {
    uint32_t a;
    asm("{ .reg .u64 t; cvta.to.shared.u64 t, %1; cvt.u32.u64 %0, t; }" : "=r"(a) : "l"(p));
    return a;
}
__device__ __forceinline__ void cp_async16(uint32_t dst, const void* src) {
    asm volatile("cp.async.cg.shared.global [%0], [%1], 16;" :: "r"(dst), "l"(src));
}
__device__ __forceinline__ void ldsm_x4(uint32_t* r, uint32_t addr) {
    asm volatile("ldmatrix.sync.aligned.m8n8.x4.shared.b16 {%0,%1,%2,%3}, [%4];"
                 : "=r"(r[0]), "=r"(r[1]), "=r"(r[2]), "=r"(r[3]) : "r"(addr));
}
__device__ __forceinline__ void ldsm_x2(uint32_t* r, uint32_t addr) {
    asm volatile("ldmatrix.sync.aligned.m8n8.x2.shared.b16 {%0,%1}, [%2];"
                 : "=r"(r[0]), "=r"(r[1]) : "r"(addr));
}
__device__ __forceinline__ void mma16816(float* c, const uint32_t* a, const uint32_t* b) {
    asm volatile("mma.sync.aligned.m16n8k16.row.col.f32.f16.f16.f32 "
                 "{%0,%1,%2,%3}, {%4,%5,%6,%7}, {%8,%9}, {%0,%1,%2,%3};"
                 : "+f"(c[0]), "+f"(c[1]), "+f"(c[2]), "+f"(c[3])
                 : "r"(a[0]), "r"(a[1]), "r"(a[2]), "r"(a[3]), "r"(b[0]), "r"(b[1]));
}
// swizzle for 128B rows, 16B granules
__device__ __forceinline__ uint32_t swz(int r, int g) {
    return (uint32_t)r * 128u + ((uint32_t)(g ^ (r & 7)) << 4);
}

// ----------------------------- GEMM (fp16 emulated mma.sync) --------------
// C[M, n_real] = (Ahi[+Alo]) @ (Whi[+Wlo])^T + bias, fp32 accumulation.
// passes: hi*hi always; +lo*hi if ALO; +hi*lo if WLO.
// block 128 x 112, BK=64, single-buffered (2 CTAs/SM overlap). 8 warps 4x2.
// If probs != null: capsule-u mode; epilogue computes h = probs @ (u + bias)
// writes Hhi (stride KPAD_CAP) and optionally Dhi/Dlo (decoder layout).
#define OFF_ALO 16384u
#define OFF_WHI 32768u
#define OFF_WLO 47104u
#define SMEM_BYTES 61440

template <int ALO, int WLO>
__global__ __launch_bounds__(256, 2)
void gemm_mma(const __half* __restrict__ Ahi, const __half* __restrict__ Alo, int lda,
              const __half* __restrict__ Whi, const __half* __restrict__ Wlo, int ldw,
              const float* __restrict__ bias,
              float* __restrict__ Cf, __half* __restrict__ Chi, __half* __restrict__ Clo,
              int ldc, int K, int n_real, int relu,
              const float* __restrict__ probs, __half* __restrict__ Hhi,
              __half* __restrict__ Dhi, __half* __restrict__ Dlo)
{
    extern __shared__ char smem[];
    const uint32_t sb = smem_u32(smem);
    const int tid = threadIdx.x;
    const int lane = tid & 31;
    const int wid = tid >> 5;
    const int wm = wid & 3;
    const int wn = wid >> 2;
    const int m0 = blockIdx.y * 128;
    const int n0 = blockIdx.x * 112;

    float acc[2][7][4];
#pragma unroll
    for (int i = 0; i < 2; i++)
#pragma unroll
        for (int j = 0; j < 7; j++)
#pragma unroll
            for (int v = 0; v < 4; v++) acc[i][j][v] = 0.f;

    for (int kc = 0; kc < K; kc += 64) {
        const int cur = min(64, K - kc);
        const int gc = cur >> 3;               // granules/row: 8 or 2
        const int gsh = (gc == 8) ? 3 : 1;
        const int gm = gc - 1;

        if (kc > 0) __syncthreads();

        for (int idx = tid; idx < 128 * gc; idx += 256) {
            int r = idx >> gsh, g = idx & gm;
            size_t src = (size_t)(m0 + r) * lda + kc + g * 8;
            uint32_t d = sb + swz(r, g);
            cp_async16(d, Ahi + src);
            if (ALO) cp_async16(d + OFF_ALO, Alo + src);
        }
        for (int idx = tid; idx < 112 * gc; idx += 256) {
            int r = idx >> gsh, g = idx & gm;
            size_t src = (size_t)(n0 + r) * ldw + kc + g * 8;
            uint32_t d = sb + OFF_WHI + swz(r, g);
            cp_async16(d, Whi + src);
            if (WLO) cp_async16(d + (OFF_WLO - OFF_WHI), Wlo + src);
        }
        asm volatile("cp.async.commit_group;");
        asm volatile("cp.async.wait_group 0;");
        __syncthreads();

        const int nks = cur >> 4;
        const uint32_t sw = sb + OFF_WHI;

        for (int ks = 0; ks < nks; ks++) {
            uint32_t ah[2][4], al[2][4], bh[7][2], bl[7][2];
#pragma unroll
            for (int mf = 0; mf < 2; mf++) {
                int r = wm * 32 + mf * 16 + (lane & 15);
                int g = ks * 2 + (lane >> 4);
                uint32_t off = swz(r, g);
                ldsm_x4(ah[mf], sb + off);
                if (ALO) ldsm_x4(al[mf], sb + OFF_ALO + off);
            }
#pragma unroll
            for (int p = 0; p < 3; p++) {
                int r = wn * 56 + p * 16 + (lane & 7) + ((lane >> 4) & 1) * 8;
                int g = ks * 2 + ((lane >> 3) & 1);
                uint32_t off = swz(r, g);
                uint32_t t4[4];
                ldsm_x4(t4, sw + off);
                bh[2*p][0] = t4[0]; bh[2*p][1] = t4[1];
                bh[2*p+1][0] = t4[2]; bh[2*p+1][1] = t4[3];
                if (WLO) {
                    ldsm_x4(t4, sw + (OFF_WLO - OFF_WHI) + off);
                    bl[2*p][0] = t4[0]; bl[2*p][1] = t4[1];
                    bl[2*p+1][0] = t4[2]; bl[2*p+1][1] = t4[3];
                }
            }
            {
                int l15 = lane & 15;
                int r = wn * 56 + 48 + (l15 & 7);
                int g = ks * 2 + ((l15 >> 3) & 1);
                uint32_t off = swz(r, g);
                ldsm_x2(bh[6], sw + off);
                if (WLO) ldsm_x2(bl[6], sw + (OFF_WLO - OFF_WHI) + off);
            }
#pragma unroll
            for (int mf = 0; mf < 2; mf++)
#pragma unroll
                for (int nf = 0; nf < 7; nf++) {
                    mma16816(acc[mf][nf], ah[mf], bh[nf]);          // hi*hi
                    if (ALO) mma16816(acc[mf][nf], al[mf], bh[nf]); // lo*hi
                    if (WLO) mma16816(acc[mf][nf], ah[mf], bl[nf]); // hi*lo
                }
        }
    }

    if (probs) {
        // fused attention epilogue: u in acc; h[t] = sum_s p[t][s] * (u[s]+bias)
#pragma unroll
        for (int mf = 0; mf < 2; mf++)
#pragma unroll
        for (int hf = 0; hf < 2; hf++) {
            int row = m0 + wm * 32 + mf * 16 + hf * 8 + (lane >> 2);
            int batch = row >> 2, t = row & 3;
            float4 pv = *(const float4*)(probs + (size_t)batch * 16 + t * 4);
            int base = (lane >> 2) & 4;
#pragma unroll
            for (int nf = 0; nf < 7; nf++)
#pragma unroll
            for (int e = 0; e < 2; e++) {
                int c = n0 + wn * 56 + nf * 8 + ((lane & 3) << 1) + e;
                float uv = acc[mf][nf][hf * 2 + e] + ((c < n_real) ? bias[c] : 0.f);
                float h = 0.f;
#pragma unroll
                for (int s = 0; s < 4; s++) {
                    float us = __shfl_sync(0xffffffffu, uv, ((base + s) << 2) | (lane & 3));
                    float ps = (s == 0) ? pv.x : (s == 1) ? pv.y : (s == 2) ? pv.z : pv.w;
                    h = fmaf(ps, us, h);
                }
                if (c < n_real) {
                    __half hi = __float2half_rn(h);
                    Hhi[(size_t)row * KPAD_CAP + c] = hi;
                    if (Dhi) {
                        size_t dof = (size_t)batch * FEAT + t * FV + c;
                        Dhi[dof] = hi;
                        Dlo[dof] = __float2half_rn(h - __half2float(hi));
                    }
                }
            }
        }
    } else {
#pragma unroll
        for (int mf = 0; mf < 2; mf++)
#pragma unroll
        for (int nf = 0; nf < 7; nf++) {
            int r = m0 + wm * 32 + mf * 16 + (lane >> 2);
            int c = n0 + wn * 56 + nf * 8 + ((lane & 3) << 1);
#pragma unroll
            for (int hf = 0; hf < 2; hf++) {
                int rr = r + hf * 8;
#pragma unroll
                for (int e = 0; e < 2; e++) {
                    int cc = c + e;
                    if (cc >= n_real) continue;
                    float v = acc[mf][nf][hf * 2 + e] + bias[cc];
                    if (relu) v = fmaxf(v, 0.f);
                    size_t o = (size_t)rr * ldc + cc;
                    if (Cf) Cf[o] = v;
                    if (Chi) {
                        __half hi = __float2half_rn(v);
                        Chi[o] = hi;
                        Clo[o] = __float2half_rn(v - __half2float(hi));
                    }
                }
            }
        }
    }
}

// ----------------------------- precompute ----------------------------------
// Gt[n,k] = sum_j W1[j,k] * W2[j,n]   (so z = v @ Gt^T = v @ (W1^T W2))
// g2[k]   = sum_j b1[j] * W2[j,k]
__global__ void compute_gt(const float* __restrict__ W1, const float* __restrict__ W2,
                           const float* __restrict__ b1,
                           __half* __restrict__ gthi,
                           float* __restrict__ g2, float* __restrict__ zbias)
{
    int idx = blockIdx.x * blockDim.x + threadIdx.x;
    if (idx < FV) {
        float s = 0.f;
        for (int j = 0; j < FV; j++) s = fmaf(b1[j], W2[(size_t)j * FV + idx], s);
        g2[idx] = s;
    }
    if (idx < NPAD_CAP) zbias[idx] = 0.f;
    if (idx >= NPAD_CAP * KPAD_CAP) return;
    int n = idx / KPAD_CAP, k = idx % KPAD_CAP;
    float s = 0.f;
    if (n < FV && k < FV) {
        for (int j = 0; j < FV; j++)
            s = fmaf(W1[(size_t)j * FV + k], W2[(size_t)j * FV + n], s);
    }
    gthi[idx] = __float2half_rn(s);
}

// ----------------------------- conversions --------------------------------
__global__ void convert_x_kernel(const float* __restrict__ x,
                                 __half* __restrict__ hhi, __half* __restrict__ hhi2)
{
    size_t idx = (size_t)blockIdx.x * blockDim.x + threadIdx.x;
    if (idx >= (size_t)BROWS * KPAD_CAP) return;
    size_t R = idx / KPAD_CAP;
    int f = (int)(idx % KPAD_CAP);
    float v = (f < FV) ? x[R * FV + f] : 0.f;
    __half hi = __float2half_rn(v);
    hhi[idx] = hi;
    hhi2[idx] = hi;   // pad columns zero in both buffers
}

__global__ void convert_w_kernel(const float* __restrict__ W, int rin, int cin,
                                 __half* __restrict__ hi, int rout, int cout)
{
    int idx = blockIdx.x * blockDim.x + threadIdx.x;
    if (idx >= rout * cout) return;
    int r = idx / cout, c = idx % cout;
    float v = (r < rin && c < cin) ? W[(size_t)r * cin + c] : 0.f;
    hi[idx] = __float2half_rn(v);
}

// ----------------------------- scores (fp32) -------------------------------
// probs[b,t,s] = softmax_s( z_t . v_s + beta_s ),  beta_s = v_s . g2
__global__ __launch_bounds__(256)
void score_kernel(const float* __restrict__ z,
                  const __half* __restrict__ hhi,
                  const float* __restrict__ g2, float* __restrict__ probs)
{
    const int b    = blockIdx.x * 8 + threadIdx.y;
    const int lane = threadIdx.x;
    const float* zb = z + (size_t)b * 4 * FV;
    const __half* vhi = hhi + (size_t)b * 4 * KPAD_CAP;

    float s[4][4], beta[4];
#pragma unroll
    for (int t = 0; t < 4; t++) {
        beta[t] = 0.f;
#pragma unroll
        for (int r = 0; r < 4; r++) s[t][r] = 0.f;
    }

    for (int f = lane; f < FV; f += 32) {
        float zt[4], vs[4];
        float g2f = g2[f];
#pragma unroll
        for (int t = 0; t < 4; t++) {
            zt[t] = zb[t * FV + f];
            vs[t] = __half2float(vhi[t * KPAD_CAP + f]);
        }
#pragma unroll
        for (int t = 0; t < 4; t++) {
            beta[t] = fmaf(vs[t], g2f, beta[t]);
#pragma unroll
            for (int r = 0; r < 4; r++)
                s[t][r] = fmaf(zt[t], vs[r], s[t][r]);
        }
    }
#pragma unroll
    for (int t = 0; t < 4; t++) {
#pragma unroll
        for (int off = 16; off > 0; off >>= 1)
            beta[t] += __shfl_xor_sync(0xffffffffu, beta[t], off);
#pragma unroll
        for (int r = 0; r < 4; r++)
#pragma unroll
            for (int off = 16; off > 0; off >>= 1)
                s[t][r] += __shfl_xor_sync(0xffffffffu, s[t][r], off);
    }

    float p[4][4];
#pragma unroll
    for (int t = 0; t < 4; t++) {
        float sc[4];
#pragma unroll
        for (int r = 0; r < 4; r++) sc[r] = s[t][r] + beta[r];
        float m = fmaxf(fmaxf(sc[0], sc[1]), fmaxf(sc[2], sc[3]));
        float e0 = expf(sc[0] - m), e1 = expf(sc[1] - m);
        float e2 = expf(sc[2] - m), e3 = expf(sc[3] - m);
        float inv = 1.f / (e0 + e1 + e2 + e3);
        p[t][0] = e0 * inv; p[t][1] = e1 * inv; p[t][2] = e2 * inv; p[t][3] = e3 * inv;
    }
    if (lane < 16)
        probs[(size_t)b * 16 + lane] = p[lane >> 2][lane & 3];
}

// ----------------------------- head ----------------------------------------
__global__ __launch_bounds__(256)
void head_kernel(const float* __restrict__ A, const float* __restrict__ Wo,
                 const float* __restrict__ bo, float* __restrict__ out)
{
    const int b    = blockIdx.x * 8 + threadIdx.y;
    const int lane = threadIdx.x;
    const float* a = A + (size_t)b * FEAT;

    float acc[10];
#pragma unroll
    for (int j = 0; j < 10; j++) acc[j] = 0.f;
    for (int kk = lane; kk < FEAT; kk += 32) {
        float av = a[kk];
#pragma unroll
        for (int j = 0; j < 10; j++)
            acc[j] = fmaf(av, Wo[j * FEAT + kk], acc[j]);
    }
#pragma unroll
    for (int j = 0; j < 10; j++)
#pragma unroll
        for (int off = 16; off > 0; off >>= 1)
            acc[j] += __shfl_xor_sync(0xffffffffu, acc[j], off);

    if (lane == 0) {
        float v[10], m = -1e30f;
#pragma unroll
        for (int j = 0; j < 10; j++) { v[j] = acc[j] + bo[j]; m = fmaxf(m, v[j]); }
        float ssum = 0.f;
#pragma unroll
        for (int j = 0; j < 10; j++) { v[j] = expf(v[j] - m); ssum += v[j]; }
        float inv = 1.f / ssum;
#pragma unroll
        for (int j = 0; j < 10; j++) out[(size_t)b * 10 + j] = v[j] * inv;
    }
}

// ---------------------------------------------------------------------------
extern "C" void kernel_launch(void* const* d_in, const int* in_sizes, int n_in,
                              void* d_out, int out_size)
{
    const float* x   = (const float*)d_in[0];
    const float* W1  = (const float*)d_in[1];
    const float* b1  = (const float*)d_in[2];
    const float* W2  = (const float*)d_in[3];
    const float* W3  = (const float*)d_in[5];
    const float* b3  = (const float*)d_in[6];
    const float* Wd1 = (const float*)d_in[7];
    const float* bd1 = (const float*)d_in[8];
    const float* Wd2 = (const float*)d_in[9];
    const float* bd2 = (const float*)d_in[10];
    const float* Wo  = (const float*)d_in[11];
    const float* bo  = (const float*)d_in[12];
    float* out = (float*)d_out;

    cudaFuncSetAttribute(gemm_mma<0,0>, cudaFuncAttributeMaxDynamicSharedMemorySize, SMEM_BYTES);
    cudaFuncSetAttribute(gemm_mma<1,0>, cudaFuncAttributeMaxDynamicSharedMemorySize, SMEM_BYTES);

    __half *hhi, *hhi2, *gthi, *w3hi, *wd1hi, *wd2hi, *dhi, *dlo, *thi, *tlo;
    float *z, *p, *g2, *dec, *zbias;
    cudaGetSymbolAddress((void**)&hhi, g_hhi);
    cudaGetSymbolAddress((void**)&hhi2, g_hhi2);
    cudaGetSymbolAddress((void**)&z, g_z);         cudaGetSymbolAddress((void**)&p, g_p);
    cudaGetSymbolAddress((void**)&g2, g_g2);       cudaGetSymbolAddress((void**)&dec, g_dec);
    cudaGetSymbolAddress((void**)&gthi, g_gthi);
    cudaGetSymbolAddress((void**)&w3hi, g_w3hi);
    cudaGetSymbolAddress((void**)&wd1hi, g_wd1hi);
    cudaGetSymbolAddress((void**)&wd2hi, g_wd2hi);
    cudaGetSymbolAddress((void**)&dhi, g_dhi);     cudaGetSymbolAddress((void**)&dlo, g_dlo);
    cudaGetSymbolAddress((void**)&thi, g_thi);     cudaGetSymbolAddress((void**)&tlo, g_tlo);
    cudaGetSymbolAddress((void**)&zbias, g_zero_bias);

    // precompute + conversions
    convert_x_kernel<<<(int)(((size_t)BROWS * KPAD_CAP + 255) / 256), 256>>>(x, hhi, hhi2);
    int wcap = NPAD_CAP * KPAD_CAP;
    compute_gt<<<(wcap + 255) / 256, 256>>>(W1, W2, b1, gthi, g2, zbias);
    convert_w_kernel<<<(wcap + 255) / 256, 256>>>(W3, FV, FV, w3hi, NPAD_CAP, KPAD_CAP);
    int wdec = FEAT * FEAT;
    convert_w_kernel<<<(wdec + 255) / 256, 256>>>(Wd1, FEAT, FEAT, wd1hi, FEAT, FEAT);
    convert_w_kernel<<<(wdec + 255) / 256, 256>>>(Wd2, FEAT, FEAT, wd2hi, FEAT, FEAT);

    // capsule iterations (h double-buffered; 1-pass fp16 GEMMs)
    const dim3 gcap(2, BROWS / 128);
    for (int it = 0; it < NITER; it++) {
        __half* chi = (it & 1) ? hhi2 : hhi;
        __half* nhi = (it & 1) ? hhi : hhi2;
        int last = (it == NITER - 1);
        // z = v @ (W1^T W2)
        gemm_mma<0,0><<<gcap, 256, SMEM_BYTES>>>(chi, nullptr, KPAD_CAP, gthi, nullptr, KPAD_CAP,
                                                 zbias, z, nullptr, nullptr, FV, KPAD_CAP, FV, 0,
                                                 nullptr, nullptr, nullptr, nullptr);
        score_kernel<<<BATCH / 8, dim3(32, 8)>>>(z, chi, g2, p);
        // u GEMM with fused h = probs @ (u + b3)
        gemm_mma<0,0><<<gcap, 256, SMEM_BYTES>>>(chi, nullptr, KPAD_CAP, w3hi, nullptr, KPAD_CAP,
                                                 b3, nullptr, nullptr, nullptr, 0, KPAD_CAP, FV, 0,
                                                 p, nhi,
                                                 last ? dhi : nullptr, last ? dlo : nullptr);
    }

    // decoder (2-pass: activation hi+lo, weights fp16)
    const dim3 gdec(7, BATCH / 128);
    gemm_mma<1,0><<<gdec, 256, SMEM_BYTES>>>(dhi, dlo, FEAT, wd1hi, nullptr, FEAT, bd1,
                                             nullptr, thi, tlo, FEAT, FEAT, FEAT, 1,
                                             nullptr, nullptr, nullptr, nullptr);
    gemm_mma<1,0><<<gdec, 256, SMEM_BYTES>>>(thi, tlo, FEAT, wd2hi, nullptr, FEAT, bd2,
                                             dec, nullptr, nullptr, FEAT, FEAT, FEAT, 0,
                                             nullptr, nullptr, nullptr, nullptr);
    head_kernel<<<BATCH / 8, dim3(32, 8)>>>(dec, Wo, bo, out);
}

// round 8
// speedup vs baseline: 1.9399x; 1.0865x over previous
#include <cuda_runtime.h>
#include <cuda_fp16.h>
#include <math.h>
#include <stdint.h>

#define BATCH 32768
#define FEAT  784
#define FV    196
#define NITER 8
#define BROWS (BATCH * 4)        // 131072 capsule rows

#define KPAD_CAP 208             // capsule K padded (13*16)
#define NPAD_CAP 224             // capsule N padded (2*112)

// ----------------------------- scratch ------------------------------------
__device__ __align__(256) __half g_hhi [(size_t)BROWS * KPAD_CAP];
__device__ __align__(256) __half g_hhi2[(size_t)BROWS * KPAD_CAP];
__device__ __align__(256) __half g_z[(size_t)BROWS * FV];
__device__ __align__(256) float  g_p[(size_t)BATCH * 16];
__device__ __align__(256) __half g_gthi[NPAD_CAP * KPAD_CAP];
__device__ __align__(256) float  g_g2[FV];
__device__ __align__(256) __half g_w3hi[NPAD_CAP * KPAD_CAP];
__device__ __align__(256) __half g_wd1hi[FEAT * FEAT];
__device__ __align__(256) __half g_wd2hi[FEAT * FEAT];
__device__ __align__(256) __half g_dhi[(size_t)BATCH * FEAT];
__device__ __align__(256) __half g_thi[(size_t)BATCH * FEAT];
__device__ __align__(256) float  g_dec[(size_t)BATCH * FEAT];
__device__ __align__(256) float  g_zero_bias[NPAD_CAP];

// ----------------------------- PTX helpers --------------------------------
__device__ __forceinline__ uint32_t smem_u32(const void* p) {
    uint32_t a;
    asm("{ .reg .u64 t; cvta.to.shared.u64 t, %1; cvt.u32.u64 %0, t; }" : "=r"(a) : "l"(p));
    return a;
}
__device__ __forceinline__ void cp_async16(uint32_t dst, const void* src) {
    asm volatile("cp.async.cg.shared.global [%0], [%1], 16;" :: "r"(dst), "l"(src));
}
__device__ __forceinline__ void ldsm_x4(uint32_t* r, uint32_t addr) {
    asm volatile("ldmatrix.sync.aligned.m8n8.x4.shared.b16 {%0,%1,%2,%3}, [%4];"
                 : "=r"(r[0]), "=r"(r[1]), "=r"(r[2]), "=r"(r[3]) : "r"(addr));
}
__device__ __forceinline__ void ldsm_x2(uint32_t* r, uint32_t addr) {
    asm volatile("ldmatrix.sync.aligned.m8n8.x2.shared.b16 {%0,%1}, [%2];"
                 : "=r"(r[0]), "=r"(r[1]) : "r"(addr));
}
__device__ __forceinline__ void mma16816(float* c, const uint32_t* a, const uint32_t* b) {
    asm volatile("mma.sync.aligned.m16n8k16.row.col.f32.f16.f16.f32 "
                 "{%0,%1,%2,%3}, {%4,%5,%6,%7}, {%8,%9}, {%0,%1,%2,%3};"
                 : "+f"(c[0]), "+f"(c[1]), "+f"(c[2]), "+f"(c[3])
                 : "r"(a[0]), "r"(a[1]), "r"(a[2]), "r"(a[3]), "r"(b[0]), "r"(b[1]));
}
// swizzle for 128B rows, 16B granules
__device__ __forceinline__ uint32_t swz(int r, int g) {
    return (uint32_t)r * 128u + ((uint32_t)(g ^ (r & 7)) << 4);
}

// ----------------------------- GEMM (fp16 mma.sync) -----------------------
// C[M, n_real] = A @ W^T + bias, fp32 accumulation, fp16 inputs.
// block 128 x 112, BK=64, single-buffered. 8 warps 4x2, warp tile 32x56.
// If probs != null: capsule-u mode; epilogue computes h = probs @ (u + bias)
// writes Hhi (stride KPAD_CAP) and optionally Dhi (decoder layout).
// Else writes Cf (fp32) and/or Ch (fp16), optional relu.
#define OFF_W 16384u
#define SMEM_BYTES 30720

__global__ __launch_bounds__(256, 2)
void gemm_mma(const __half* __restrict__ A, int lda,
              const __half* __restrict__ W, int ldw,
              const float* __restrict__ bias,
              float* __restrict__ Cf, __half* __restrict__ Ch,
              int ldc, int K, int n_real, int relu,
              const float* __restrict__ probs, __half* __restrict__ Hhi,
              __half* __restrict__ Dhi)
{
    extern __shared__ char smem[];
    const uint32_t sb = smem_u32(smem);
    const int tid = threadIdx.x;
    const int lane = tid & 31;
    const int wid = tid >> 5;
    const int wm = wid & 3;
    const int wn = wid >> 2;
    const int m0 = blockIdx.y * 128;
    const int n0 = blockIdx.x * 112;

    float acc[2][7][4];
#pragma unroll
    for (int i = 0; i < 2; i++)
#pragma unroll
        for (int j = 0; j < 7; j++)
#pragma unroll
            for (int v = 0; v < 4; v++) acc[i][j][v] = 0.f;

    for (int kc = 0; kc < K; kc += 64) {
        const int cur = min(64, K - kc);
        const int gc = cur >> 3;               // granules/row: 8 or 2
        const int gsh = (gc == 8) ? 3 : 1;
        const int gm = gc - 1;

        if (kc > 0) __syncthreads();

        for (int idx = tid; idx < 128 * gc; idx += 256) {
            int r = idx >> gsh, g = idx & gm;
            cp_async16(sb + swz(r, g), A + (size_t)(m0 + r) * lda + kc + g * 8);
        }
        for (int idx = tid; idx < 112 * gc; idx += 256) {
            int r = idx >> gsh, g = idx & gm;
            cp_async16(sb + OFF_W + swz(r, g), W + (size_t)(n0 + r) * ldw + kc + g * 8);
        }
        asm volatile("cp.async.commit_group;");
        asm volatile("cp.async.wait_group 0;");
        __syncthreads();

        const int nks = cur >> 4;
        const uint32_t sw = sb + OFF_W;

        for (int ks = 0; ks < nks; ks++) {
            uint32_t ah[2][4], bh[7][2];
#pragma unroll
            for (int mf = 0; mf < 2; mf++) {
                int r = wm * 32 + mf * 16 + (lane & 15);
                int g = ks * 2 + (lane >> 4);
                ldsm_x4(ah[mf], sb + swz(r, g));
            }
#pragma unroll
            for (int p = 0; p < 3; p++) {
                int r = wn * 56 + p * 16 + (lane & 7) + ((lane >> 4) & 1) * 8;
                int g = ks * 2 + ((lane >> 3) & 1);
                uint32_t t4[4];
                ldsm_x4(t4, sw + swz(r, g));
                bh[2*p][0] = t4[0]; bh[2*p][1] = t4[1];
                bh[2*p+1][0] = t4[2]; bh[2*p+1][1] = t4[3];
            }
            {
                int l15 = lane & 15;
                int r = wn * 56 + 48 + (l15 & 7);
                int g = ks * 2 + ((l15 >> 3) & 1);
                ldsm_x2(bh[6], sw + swz(r, g));
            }
#pragma unroll
            for (int mf = 0; mf < 2; mf++)
#pragma unroll
                for (int nf = 0; nf < 7; nf++)
                    mma16816(acc[mf][nf], ah[mf], bh[nf]);
        }
    }

    if (probs) {
        // fused attention epilogue: u in acc; h[t] = sum_s p[t][s] * (u[s]+bias)
#pragma unroll
        for (int mf = 0; mf < 2; mf++)
#pragma unroll
        for (int hf = 0; hf < 2; hf++) {
            int row = m0 + wm * 32 + mf * 16 + hf * 8 + (lane >> 2);
            int batch = row >> 2, t = row & 3;
            float4 pv = *(const float4*)(probs + (size_t)batch * 16 + t * 4);
            int base = (lane >> 2) & 4;
#pragma unroll
            for (int nf = 0; nf < 7; nf++)
#pragma unroll
            for (int e = 0; e < 2; e++) {
                int c = n0 + wn * 56 + nf * 8 + ((lane & 3) << 1) + e;
                float uv = acc[mf][nf][hf * 2 + e] + ((c < n_real) ? bias[c] : 0.f);
                float h = 0.f;
#pragma unroll
                for (int s = 0; s < 4; s++) {
                    float us = __shfl_sync(0xffffffffu, uv, ((base + s) << 2) | (lane & 3));
                    float ps = (s == 0) ? pv.x : (s == 1) ? pv.y : (s == 2) ? pv.z : pv.w;
                    h = fmaf(ps, us, h);
                }
                if (c < n_real) {
                    __half hv = __float2half_rn(h);
                    Hhi[(size_t)row * KPAD_CAP + c] = hv;
                    if (Dhi) Dhi[(size_t)batch * FEAT + t * FV + c] = hv;
                }
            }
        }
    } else {
#pragma unroll
        for (int mf = 0; mf < 2; mf++)
#pragma unroll
        for (int nf = 0; nf < 7; nf++) {
            int r = m0 + wm * 32 + mf * 16 + (lane >> 2);
            int c = n0 + wn * 56 + nf * 8 + ((lane & 3) << 1);
#pragma unroll
            for (int hf = 0; hf < 2; hf++) {
                int rr = r + hf * 8;
#pragma unroll
                for (int e = 0; e < 2; e++) {
                    int cc = c + e;
                    if (cc >= n_real) continue;
                    float v = acc[mf][nf][hf * 2 + e] + bias[cc];
                    if (relu) v = fmaxf(v, 0.f);
                    size_t o = (size_t)rr * ldc + cc;
                    if (Cf) Cf[o] = v;
                    if (Ch) Ch[o] = __float2half_rn(v);
                }
            }
        }
    }
}

// ----------------------------- precompute ----------------------------------
// Gt[n,k] = sum_j W1[j,k] * W2[j,n]   (so z = v @ Gt^T = v @ (W1^T W2))
// g2[k]   = sum_j b1[j] * W2[j,k]
__global__ void compute_gt(const float* __restrict__ W1, const float* __restrict__ W2,
                           const float* __restrict__ b1,
                           __half* __restrict__ gthi,
                           float* __restrict__ g2, float* __restrict__ zbias)
{
    int idx = blockIdx.x * blockDim.x + threadIdx.x;
    if (idx < FV) {
        float s = 0.f;
        for (int j = 0; j < FV; j++) s = fmaf(b1[j], W2[(size_t)j * FV + idx], s);
        g2[idx] = s;
    }
    if (idx < NPAD_CAP) zbias[idx] = 0.f;
    if (idx >= NPAD_CAP * KPAD_CAP) return;
    int n = idx / KPAD_CAP, k = idx % KPAD_CAP;
    float s = 0.f;
    if (n < FV && k < FV) {
        for (int j = 0; j < FV; j++)
            s = fmaf(W1[(size_t)j * FV + k], W2[(size_t)j * FV + n], s);
    }
    gthi[idx] = __float2half_rn(s);
}

// ----------------------------- conversions --------------------------------
__global__ void convert_x_kernel(const float* __restrict__ x,
                                 __half* __restrict__ hhi, __half* __restrict__ hhi2)
{
    size_t idx = (size_t)blockIdx.x * blockDim.x + threadIdx.x;
    if (idx >= (size_t)BROWS * KPAD_CAP) return;
    size_t R = idx / KPAD_CAP;
    int f = (int)(idx % KPAD_CAP);
    float v = (f < FV) ? x[R * FV + f] : 0.f;
    __half hi = __float2half_rn(v);
    hhi[idx] = hi;
    hhi2[idx] = hi;   // pad columns zero in both buffers
}

__global__ void convert_w_kernel(const float* __restrict__ W, int rin, int cin,
                                 __half* __restrict__ hi, int rout, int cout)
{
    int idx = blockIdx.x * blockDim.x + threadIdx.x;
    if (idx >= rout * cout) return;
    int r = idx / cout, c = idx % cout;
    float v = (r < rin && c < cin) ? W[(size_t)r * cin + c] : 0.f;
    hi[idx] = __float2half_rn(v);
}

// ----------------------------- scores (fp32) -------------------------------
// probs[b,t,s] = softmax_s( z_t . v_s + beta_s ),  beta_s = v_s . g2
__global__ __launch_bounds__(256)
void score_kernel(const __half* __restrict__ z,
                  const __half* __restrict__ hhi,
                  const float* __restrict__ g2, float* __restrict__ probs)
{
    const int b    = blockIdx.x * 8 + threadIdx.y;
    const int lane = threadIdx.x;
    const __half* zb = z + (size_t)b * 4 * FV;
    const __half* vhi = hhi + (size_t)b * 4 * KPAD_CAP;

    float s[4][4], beta[4];
#pragma unroll
    for (int t = 0; t < 4; t++) {
        beta[t] = 0.f;
#pragma unroll
        for (int r = 0; r < 4; r++) s[t][r] = 0.f;
    }

    for (int f = lane; f < FV; f += 32) {
        float zt[4], vs[4];
        float g2f = g2[f];
#pragma unroll
        for (int t = 0; t < 4; t++) {
            zt[t] = __half2float(zb[t * FV + f]);
            vs[t] = __half2float(vhi[t * KPAD_CAP + f]);
        }
#pragma unroll
        for (int t = 0; t < 4; t++) {
            beta[t] = fmaf(vs[t], g2f, beta[t]);
#pragma unroll
            for (int r = 0; r < 4; r++)
                s[t][r] = fmaf(zt[t], vs[r], s[t][r]);
        }
    }
#pragma unroll
    for (int t = 0; t < 4; t++) {
#pragma unroll
        for (int off = 16; off > 0; off >>= 1)
            beta[t] += __shfl_xor_sync(0xffffffffu, beta[t], off);
#pragma unroll
        for (int r = 0; r < 4; r++)
#pragma unroll
            for (int off = 16; off > 0; off >>= 1)
                s[t][r] += __shfl_xor_sync(0xffffffffu, s[t][r], off);
    }

    float p[4][4];
#pragma unroll
    for (int t = 0; t < 4; t++) {
        float sc[4];
#pragma unroll
        for (int r = 0; r < 4; r++) sc[r] = s[t][r] + beta[r];
        float m = fmaxf(fmaxf(sc[0], sc[1]), fmaxf(sc[2], sc[3]));
        float e0 = expf(sc[0] - m), e1 = expf(sc[1] - m);
        float e2 = expf(sc[2] - m), e3 = expf(sc[3] - m);
        float inv = 1.f / (e0 + e1 + e2 + e3);
        p[t][0] = e0 * inv; p[t][1] = e1 * inv; p[t][2] = e2 * inv; p[t][3] = e3 * inv;
    }
    if (lane < 16)
        probs[(size_t)b * 16 + lane] = p[lane >> 2][lane & 3];
}

// ----------------------------- head ----------------------------------------
__global__ __launch_bounds__(256)
void head_kernel(const float* __restrict__ A, const float* __restrict__ Wo,
                 const float* __restrict__ bo, float* __restrict__ out)
{
    const int b    = blockIdx.x * 8 + threadIdx.y;
    const int lane = threadIdx.x;
    const float* a = A + (size_t)b * FEAT;

    float acc[10];
#pragma unroll
    for (int j = 0; j < 10; j++) acc[j] = 0.f;
    for (int kk = lane; kk < FEAT; kk += 32) {
        float av = a[kk];
#pragma unroll
        for (int j = 0; j < 10; j++)
            acc[j] = fmaf(av, Wo[j * FEAT + kk], acc[j]);
    }
#pragma unroll
    for (int j = 0; j < 10; j++)
#pragma unroll
        for (int off = 16; off > 0; off >>= 1)
            acc[j] += __shfl_xor_sync(0xffffffffu, acc[j], off);

    if (lane == 0) {
        float v[10], m = -1e30f;
#pragma unroll
        for (int j = 0; j < 10; j++) { v[j] = acc[j] + bo[j]; m = fmaxf(m, v[j]); }
        float ssum = 0.f;
#pragma unroll
        for (int j = 0; j < 10; j++) { v[j] = expf(v[j] - m); ssum += v[j]; }
        float inv = 1.f / ssum;
#pragma unroll
        for (int j = 0; j < 10; j++) out[(size_t)b * 10 + j] = v[j] * inv;
    }
}

// ---------------------------------------------------------------------------
extern "C" void kernel_launch(void* const* d_in, const int* in_sizes, int n_in,
                              void* d_out, int out_size)
{
    const float* x   = (const float*)d_in[0];
    const float* W1  = (const float*)d_in[1];
    const float* b1  = (const float*)d_in[2];
    const float* W2  = (const float*)d_in[3];
    const float* W3  = (const float*)d_in[5];
    const float* b3  = (const float*)d_in[6];
    const float* Wd1 = (const float*)d_in[7];
    const float* bd1 = (const float*)d_in[8];
    const float* Wd2 = (const float*)d_in[9];
    const float* bd2 = (const float*)d_in[10];
    const float* Wo  = (const float*)d_in[11];
    const float* bo  = (const float*)d_in[12];
    float* out = (float*)d_out;

    cudaFuncSetAttribute(gemm_mma, cudaFuncAttributeMaxDynamicSharedMemorySize, SMEM_BYTES);

    __half *hhi, *hhi2, *z, *gthi, *w3hi, *wd1hi, *wd2hi, *dhi, *thi;
    float *p, *g2, *dec, *zbias;
    cudaGetSymbolAddress((void**)&hhi, g_hhi);
    cudaGetSymbolAddress((void**)&hhi2, g_hhi2);
    cudaGetSymbolAddress((void**)&z, g_z);         cudaGetSymbolAddress((void**)&p, g_p);
    cudaGetSymbolAddress((void**)&g2, g_g2);       cudaGetSymbolAddress((void**)&dec, g_dec);
    cudaGetSymbolAddress((void**)&gthi, g_gthi);
    cudaGetSymbolAddress((void**)&w3hi, g_w3hi);
    cudaGetSymbolAddress((void**)&wd1hi, g_wd1hi);
    cudaGetSymbolAddress((void**)&wd2hi, g_wd2hi);
    cudaGetSymbolAddress((void**)&dhi, g_dhi);
    cudaGetSymbolAddress((void**)&thi, g_thi);
    cudaGetSymbolAddress((void**)&zbias, g_zero_bias);

    // precompute + conversions
    convert_x_kernel<<<(int)(((size_t)BROWS * KPAD_CAP + 255) / 256), 256>>>(x, hhi, hhi2);
    int wcap = NPAD_CAP * KPAD_CAP;
    compute_gt<<<(wcap + 255) / 256, 256>>>(W1, W2, b1, gthi, g2, zbias);
    convert_w_kernel<<<(wcap + 255) / 256, 256>>>(W3, FV, FV, w3hi, NPAD_CAP, KPAD_CAP);
    int wdec = FEAT * FEAT;
    convert_w_kernel<<<(wdec + 255) / 256, 256>>>(Wd1, FEAT, FEAT, wd1hi, FEAT, FEAT);
    convert_w_kernel<<<(wdec + 255) / 256, 256>>>(Wd2, FEAT, FEAT, wd2hi, FEAT, FEAT);

    // capsule iterations (h double-buffered; pure fp16 GEMMs)
    const dim3 gcap(2, BROWS / 128);
    for (int it = 0; it < NITER; it++) {
        __half* chi = (it & 1) ? hhi2 : hhi;
        __half* nhi = (it & 1) ? hhi : hhi2;
        int last = (it == NITER - 1);
        // z = v @ (W1^T W2), stored fp16
        gemm_mma<<<gcap, 256, SMEM_BYTES>>>(chi, KPAD_CAP, gthi, KPAD_CAP, zbias,
                                            nullptr, z, FV, KPAD_CAP, FV, 0,
                                            nullptr, nullptr, nullptr);
        score_kernel<<<BATCH / 8, dim3(32, 8)>>>(z, chi, g2, p);
        // u GEMM with fused h = probs @ (u + b3)
        gemm_mma<<<gcap, 256, SMEM_BYTES>>>(chi, KPAD_CAP, w3hi, KPAD_CAP, b3,
                                            nullptr, nullptr, 0, KPAD_CAP, FV, 0,
                                            p, nhi, last ? dhi : nullptr);
    }

    // decoder (1-pass fp16)
    const dim3 gdec(7, BATCH / 128);
    gemm_mma<<<gdec, 256, SMEM_BYTES>>>(dhi, FEAT, wd1hi, FEAT, bd1,
                                        nullptr, thi, FEAT, FEAT, FEAT, 1,
                                        nullptr, nullptr, nullptr);
    gemm_mma<<<gdec, 256, SMEM_BYTES>>>(thi, FEAT, wd2hi, FEAT, bd2,
                                        dec, nullptr, FEAT, FEAT, FEAT, 0,
                                        nullptr, nullptr, nullptr);
    head_kernel<<<BATCH / 8, dim3(32, 8)>>>(dec, Wo, bo, out);
}

// round 9
// speedup vs baseline: 2.1589x; 1.1129x over previous
#include <cuda_runtime.h>
#include <cuda_fp16.h>
#include <math.h>
#include <stdint.h>

#define BATCH 32768
#define FEAT  784
#define FV    196
#define NITER 8
#define BROWS (BATCH * 4)        // 131072 capsule rows

#define KPAD_CAP 208             // capsule K padded (13*16)
#define NPAD_CAP 224             // capsule N padded (2*112)

// ----------------------------- scratch ------------------------------------
__device__ __align__(256) __half g_hhi [(size_t)BROWS * KPAD_CAP];
__device__ __align__(256) __half g_hhi2[(size_t)BROWS * KPAD_CAP];
__device__ __align__(256) __half g_z[(size_t)BROWS * KPAD_CAP];   // padded stride, pads stay 0
__device__ __align__(256) float  g_p[(size_t)BATCH * 16];
__device__ __align__(256) __half g_gthi[NPAD_CAP * KPAD_CAP];
__device__ __align__(256) float  g_g2[KPAD_CAP];                  // pads stay 0
__device__ __align__(256) __half g_w3hi[NPAD_CAP * KPAD_CAP];
__device__ __align__(256) __half g_wd1hi[FEAT * FEAT];
__device__ __align__(256) float  g_wop[10 * FEAT];
__device__ __align__(256) float  g_bop[16];
__device__ __align__(256) __half g_dhi[(size_t)BATCH * FEAT];
__device__ __align__(256) __half g_thi[(size_t)BATCH * FEAT];
__device__ __align__(256) float  g_zero_bias[NPAD_CAP];

// ----------------------------- PTX helpers --------------------------------
__device__ __forceinline__ uint32_t smem_u32(const void* p) {
    uint32_t a;
    asm("{ .reg .u64 t; cvta.to.shared.u64 t, %1; cvt.u32.u64 %0, t; }" : "=r"(a) : "l"(p));
    return a;
}
__device__ __forceinline__ void cp_async16(uint32_t dst, const void* src) {
    asm volatile("cp.async.cg.shared.global [%0], [%1], 16;" :: "r"(dst), "l"(src));
}
__device__ __forceinline__ void ldsm_x4(uint32_t* r, uint32_t addr) {
    asm volatile("ldmatrix.sync.aligned.m8n8.x4.shared.b16 {%0,%1,%2,%3}, [%4];"
                 : "=r"(r[0]), "=r"(r[1]), "=r"(r[2]), "=r"(r[3]) : "r"(addr));
}
__device__ __forceinline__ void ldsm_x2(uint32_t* r, uint32_t addr) {
    asm volatile("ldmatrix.sync.aligned.m8n8.x2.shared.b16 {%0,%1}, [%2];"
                 : "=r"(r[0]), "=r"(r[1]) : "r"(addr));
}
__device__ __forceinline__ void mma16816(float* c, const uint32_t* a, const uint32_t* b) {
    asm volatile("mma.sync.aligned.m16n8k16.row.col.f32.f16.f16.f32 "
                 "{%0,%1,%2,%3}, {%4,%5,%6,%7}, {%8,%9}, {%0,%1,%2,%3};"
                 : "+f"(c[0]), "+f"(c[1]), "+f"(c[2]), "+f"(c[3])
                 : "r"(a[0]), "r"(a[1]), "r"(a[2]), "r"(a[3]), "r"(b[0]), "r"(b[1]));
}
// swizzle for 128B rows, 16B granules
__device__ __forceinline__ uint32_t swz(int r, int g) {
    return (uint32_t)r * 128u + ((uint32_t)(g ^ (r & 7)) << 4);
}
// load 8 halves -> 8 floats
__device__ __forceinline__ void ld8h(float* f, const __half* p) {
    uint4 q = *(const uint4*)p;
    const __half2* h = reinterpret_cast<const __half2*>(&q);
#pragma unroll
    for (int i = 0; i < 4; i++) {
        float2 a = __half22float2(h[i]);
        f[2*i] = a.x; f[2*i+1] = a.y;
    }
}

// ----------------------------- GEMM (fp16 mma.sync) -----------------------
// C[M, n_real] = A @ W^T + bias, fp32 accumulation, fp16 inputs.
// block 128 x 112, BK=64, single-buffered. 8 warps 4x2, warp tile 32x56.
// If probs != null: capsule-u mode; epilogue computes h = probs @ (u + bias)
// writes Hhi (stride KPAD_CAP) and optionally Dhi (decoder layout).
// Else writes Cf (fp32) and/or Ch (fp16), optional relu.
#define OFF_W 16384u
#define SMEM_BYTES 30720

__global__ __launch_bounds__(256, 2)
void gemm_mma(const __half* __restrict__ A, int lda,
              const __half* __restrict__ W, int ldw,
              const float* __restrict__ bias,
              float* __restrict__ Cf, __half* __restrict__ Ch,
              int ldc, int K, int n_real, int relu,
              const float* __restrict__ probs, __half* __restrict__ Hhi,
              __half* __restrict__ Dhi)
{
    extern __shared__ char smem[];
    const uint32_t sb = smem_u32(smem);
    const int tid = threadIdx.x;
    const int lane = tid & 31;
    const int wid = tid >> 5;
    const int wm = wid & 3;
    const int wn = wid >> 2;
    const int m0 = blockIdx.y * 128;
    const int n0 = blockIdx.x * 112;

    float acc[2][7][4];
#pragma unroll
    for (int i = 0; i < 2; i++)
#pragma unroll
        for (int j = 0; j < 7; j++)
#pragma unroll
            for (int v = 0; v < 4; v++) acc[i][j][v] = 0.f;

    for (int kc = 0; kc < K; kc += 64) {
        const int cur = min(64, K - kc);
        const int gc = cur >> 3;               // granules/row: 8 or 2
        const int gsh = (gc == 8) ? 3 : 1;
        const int gm = gc - 1;

        if (kc > 0) __syncthreads();

        for (int idx = tid; idx < 128 * gc; idx += 256) {
            int r = idx >> gsh, g = idx & gm;
            cp_async16(sb + swz(r, g), A + (size_t)(m0 + r) * lda + kc + g * 8);
        }
        for (int idx = tid; idx < 112 * gc; idx += 256) {
            int r = idx >> gsh, g = idx & gm;
            cp_async16(sb + OFF_W + swz(r, g), W + (size_t)(n0 + r) * ldw + kc + g * 8);
        }
        asm volatile("cp.async.commit_group;");
        asm volatile("cp.async.wait_group 0;");
        __syncthreads();

        const int nks = cur >> 4;
        const uint32_t sw = sb + OFF_W;

        for (int ks = 0; ks < nks; ks++) {
            uint32_t ah[2][4], bh[7][2];
#pragma unroll
            for (int mf = 0; mf < 2; mf++) {
                int r = wm * 32 + mf * 16 + (lane & 15);
                int g = ks * 2 + (lane >> 4);
                ldsm_x4(ah[mf], sb + swz(r, g));
            }
#pragma unroll
            for (int p = 0; p < 3; p++) {
                int r = wn * 56 + p * 16 + (lane & 7) + ((lane >> 4) & 1) * 8;
                int g = ks * 2 + ((lane >> 3) & 1);
                uint32_t t4[4];
                ldsm_x4(t4, sw + swz(r, g));
                bh[2*p][0] = t4[0]; bh[2*p][1] = t4[1];
                bh[2*p+1][0] = t4[2]; bh[2*p+1][1] = t4[3];
            }
            {
                int l15 = lane & 15;
                int r = wn * 56 + 48 + (l15 & 7);
                int g = ks * 2 + ((l15 >> 3) & 1);
                ldsm_x2(bh[6], sw + swz(r, g));
            }
#pragma unroll
            for (int mf = 0; mf < 2; mf++)
#pragma unroll
                for (int nf = 0; nf < 7; nf++)
                    mma16816(acc[mf][nf], ah[mf], bh[nf]);
        }
    }

    if (probs) {
        // fused attention epilogue: u in acc; h[t] = sum_s p[t][s] * (u[s]+bias)
#pragma unroll
        for (int mf = 0; mf < 2; mf++)
#pragma unroll
        for (int hf = 0; hf < 2; hf++) {
            int row = m0 + wm * 32 + mf * 16 + hf * 8 + (lane >> 2);
            int batch = row >> 2, t = row & 3;
            float4 pv = *(const float4*)(probs + (size_t)batch * 16 + t * 4);
            int base = (lane >> 2) & 4;
#pragma unroll
            for (int nf = 0; nf < 7; nf++)
#pragma unroll
            for (int e = 0; e < 2; e++) {
                int c = n0 + wn * 56 + nf * 8 + ((lane & 3) << 1) + e;
                float uv = acc[mf][nf][hf * 2 + e] + ((c < n_real) ? bias[c] : 0.f);
                float h = 0.f;
#pragma unroll
                for (int s = 0; s < 4; s++) {
                    float us = __shfl_sync(0xffffffffu, uv, ((base + s) << 2) | (lane & 3));
                    float ps = (s == 0) ? pv.x : (s == 1) ? pv.y : (s == 2) ? pv.z : pv.w;
                    h = fmaf(ps, us, h);
                }
                if (c < n_real) {
                    __half hv = __float2half_rn(h);
                    Hhi[(size_t)row * KPAD_CAP + c] = hv;
                    if (Dhi) Dhi[(size_t)batch * FEAT + t * FV + c] = hv;
                }
            }
        }
    } else {
#pragma unroll
        for (int mf = 0; mf < 2; mf++)
#pragma unroll
        for (int nf = 0; nf < 7; nf++) {
            int r = m0 + wm * 32 + mf * 16 + (lane >> 2);
            int c = n0 + wn * 56 + nf * 8 + ((lane & 3) << 1);
#pragma unroll
            for (int hf = 0; hf < 2; hf++) {
                int rr = r + hf * 8;
#pragma unroll
                for (int e = 0; e < 2; e++) {
                    int cc = c + e;
                    if (cc >= n_real) continue;
                    float v = acc[mf][nf][hf * 2 + e] + bias[cc];
                    if (relu) v = fmaxf(v, 0.f);
                    size_t o = (size_t)rr * ldc + cc;
                    if (Cf) Cf[o] = v;
                    if (Ch) Ch[o] = __float2half_rn(v);
                }
            }
        }
    }
}

// ----------------------------- precompute ----------------------------------
// Gt[n,k] = sum_j W1[j,k] * W2[j,n]   (so z = v @ Gt^T = v @ (W1^T W2))
// g2[k]   = sum_j b1[j] * W2[j,k]
__global__ void compute_gt(const float* __restrict__ W1, const float* __restrict__ W2,
                           const float* __restrict__ b1,
                           __half* __restrict__ gthi,
                           float* __restrict__ g2, float* __restrict__ zbias)
{
    int idx = blockIdx.x * blockDim.x + threadIdx.x;
    if (idx < FV) {
        float s = 0.f;
        for (int j = 0; j < FV; j++) s = fmaf(b1[j], W2[(size_t)j * FV + idx], s);
        g2[idx] = s;
    }
    if (idx < NPAD_CAP) zbias[idx] = 0.f;
    if (idx >= NPAD_CAP * KPAD_CAP) return;
    int n = idx / KPAD_CAP, k = idx % KPAD_CAP;
    float s = 0.f;
    if (n < FV && k < FV) {
        for (int j = 0; j < FV; j++)
            s = fmaf(W1[(size_t)j * FV + k], W2[(size_t)j * FV + n], s);
    }
    gthi[idx] = __float2half_rn(s);
}

// Wop = Wo @ Wd2 (10 x 784, exact fp32); bop = Wo @ bd2 + bo
__global__ void fold_head(const float* __restrict__ Wo, const float* __restrict__ Wd2,
                          const float* __restrict__ bd2, const float* __restrict__ bo,
                          float* __restrict__ Wop, float* __restrict__ bop)
{
    int idx = blockIdx.x * blockDim.x + threadIdx.x;
    if (idx < 10) {
        float s = bo[idx];
        for (int i = 0; i < FEAT; i++) s = fmaf(Wo[(size_t)idx * FEAT + i], bd2[i], s);
        bop[idx] = s;
    }
    if (idx >= 10 * FEAT) return;
    int j = idx / FEAT, k = idx % FEAT;
    float s = 0.f;
    for (int i = 0; i < FEAT; i++)
        s = fmaf(Wo[(size_t)j * FEAT + i], Wd2[(size_t)i * FEAT + k], s);
    Wop[idx] = s;
}

// ----------------------------- conversions --------------------------------
__global__ void convert_x_kernel(const float* __restrict__ x,
                                 __half* __restrict__ hhi, __half* __restrict__ hhi2)
{
    size_t idx = (size_t)blockIdx.x * blockDim.x + threadIdx.x;
    if (idx >= (size_t)BROWS * KPAD_CAP) return;
    size_t R = idx / KPAD_CAP;
    int f = (int)(idx % KPAD_CAP);
    if (f < FV) {
        hhi[idx] = __float2half_rn(x[R * FV + f]);
    } else {
        hhi[idx]  = __float2half_rn(0.f);   // pad cols zero in both buffers
        hhi2[idx] = __float2half_rn(0.f);
    }
}

__global__ void convert_w_kernel(const float* __restrict__ W, int rin, int cin,
                                 __half* __restrict__ hi, int rout, int cout)
{
    int idx = blockIdx.x * blockDim.x + threadIdx.x;
    if (idx >= rout * cout) return;
    int r = idx / cout, c = idx % cout;
    float v = (r < rin && c < cin) ? W[(size_t)r * cin + c] : 0.f;
    hi[idx] = __float2half_rn(v);
}

// ----------------------------- scores (fp32, vectorized) -------------------
// probs[b,t,s] = softmax_s( z_t . v_s + beta_s ),  beta_s = v_s . g2
// one warp per batch; lane j<26 owns 16B granule j of each row (208 halves).
__global__ __launch_bounds__(256)
void score_kernel(const __half* __restrict__ z,
                  const __half* __restrict__ hhi,
                  const float* __restrict__ g2, float* __restrict__ probs)
{
    const int b    = blockIdx.x * 8 + threadIdx.y;
    const int lane = threadIdx.x;
    const __half* zb = z + (size_t)b * 4 * KPAD_CAP;
    const __half* vb = hhi + (size_t)b * 4 * KPAD_CAP;

    float s[4][4], beta[4];
#pragma unroll
    for (int t = 0; t < 4; t++) {
        beta[t] = 0.f;
#pragma unroll
        for (int r = 0; r < 4; r++) s[t][r] = 0.f;
    }

    if (lane < 26) {
        float zf[4][8], vf[4][8], gf[8];
#pragma unroll
        for (int t = 0; t < 4; t++) {
            ld8h(zf[t], zb + t * KPAD_CAP + lane * 8);
            ld8h(vf[t], vb + t * KPAD_CAP + lane * 8);
        }
        float4 ga = *(const float4*)(g2 + lane * 8);
        float4 gb = *(const float4*)(g2 + lane * 8 + 4);
        gf[0]=ga.x; gf[1]=ga.y; gf[2]=ga.z; gf[3]=ga.w;
        gf[4]=gb.x; gf[5]=gb.y; gf[6]=gb.z; gf[7]=gb.w;
#pragma unroll
        for (int t = 0; t < 4; t++) {
#pragma unroll
            for (int e = 0; e < 8; e++)
                beta[t] = fmaf(vf[t][e], gf[e], beta[t]);
#pragma unroll
            for (int r = 0; r < 4; r++) {
                float acc = 0.f;
#pragma unroll
                for (int e = 0; e < 8; e++)
                    acc = fmaf(zf[t][e], vf[r][e], acc);
                s[t][r] = acc;
            }
        }
    }
#pragma unroll
    for (int t = 0; t < 4; t++) {
#pragma unroll
        for (int off = 16; off > 0; off >>= 1)
            beta[t] += __shfl_xor_sync(0xffffffffu, beta[t], off);
#pragma unroll
        for (int r = 0; r < 4; r++)
#pragma unroll
            for (int off = 16; off > 0; off >>= 1)
                s[t][r] += __shfl_xor_sync(0xffffffffu, s[t][r], off);
    }

    float p[4][4];
#pragma unroll
    for (int t = 0; t < 4; t++) {
        float sc[4];
#pragma unroll
        for (int r = 0; r < 4; r++) sc[r] = s[t][r] + beta[r];
        float m = fmaxf(fmaxf(sc[0], sc[1]), fmaxf(sc[2], sc[3]));
        float e0 = expf(sc[0] - m), e1 = expf(sc[1] - m);
        float e2 = expf(sc[2] - m), e3 = expf(sc[3] - m);
        float inv = 1.f / (e0 + e1 + e2 + e3);
        p[t][0] = e0 * inv; p[t][1] = e1 * inv; p[t][2] = e2 * inv; p[t][3] = e3 * inv;
    }
    if (lane < 16)
        probs[(size_t)b * 16 + lane] = p[lane >> 2][lane & 3];
}

// ----------------------------- head (fp16 activations, folded Wd2) ---------
__global__ __launch_bounds__(256)
void head_kernel(const __half* __restrict__ T, const float* __restrict__ Wop,
                 const float* __restrict__ bop, float* __restrict__ out)
{
    const int b    = blockIdx.x * 8 + threadIdx.y;
    const int lane = threadIdx.x;
    const __half* a = T + (size_t)b * FEAT;

    float acc[10];
#pragma unroll
    for (int j = 0; j < 10; j++) acc[j] = 0.f;
    for (int kk = lane; kk < FEAT; kk += 32) {
        float av = __half2float(a[kk]);
#pragma unroll
        for (int j = 0; j < 10; j++)
            acc[j] = fmaf(av, Wop[j * FEAT + kk], acc[j]);
    }
#pragma unroll
    for (int j = 0; j < 10; j++)
#pragma unroll
        for (int off = 16; off > 0; off >>= 1)
            acc[j] += __shfl_xor_sync(0xffffffffu, acc[j], off);

    if (lane == 0) {
        float v[10], m = -1e30f;
#pragma unroll
        for (int j = 0; j < 10; j++) { v[j] = acc[j] + bop[j]; m = fmaxf(m, v[j]); }
        float ssum = 0.f;
#pragma unroll
        for (int j = 0; j < 10; j++) { v[j] = expf(v[j] - m); ssum += v[j]; }
        float inv = 1.f / ssum;
#pragma unroll
        for (int j = 0; j < 10; j++) out[(size_t)b * 10 + j] = v[j] * inv;
    }
}

// ---------------------------------------------------------------------------
extern "C" void kernel_launch(void* const* d_in, const int* in_sizes, int n_in,
                              void* d_out, int out_size)
{
    const float* x   = (const float*)d_in[0];
    const float* W1  = (const float*)d_in[1];
    const float* b1  = (const float*)d_in[2];
    const float* W2  = (const float*)d_in[3];
    const float* W3  = (const float*)d_in[5];
    const float* b3  = (const float*)d_in[6];
    const float* Wd1 = (const float*)d_in[7];
    const float* bd1 = (const float*)d_in[8];
    const float* Wd2 = (const float*)d_in[9];
    const float* bd2 = (const float*)d_in[10];
    const float* Wo  = (const float*)d_in[11];
    const float* bo  = (const float*)d_in[12];
    float* out = (float*)d_out;

    cudaFuncSetAttribute(gemm_mma, cudaFuncAttributeMaxDynamicSharedMemorySize, SMEM_BYTES);

    __half *hhi, *hhi2, *z, *gthi, *w3hi, *wd1hi, *dhi, *thi;
    float *p, *g2, *zbias, *wop, *bop;
    cudaGetSymbolAddress((void**)&hhi, g_hhi);
    cudaGetSymbolAddress((void**)&hhi2, g_hhi2);
    cudaGetSymbolAddress((void**)&z, g_z);         cudaGetSymbolAddress((void**)&p, g_p);
    cudaGetSymbolAddress((void**)&g2, g_g2);
    cudaGetSymbolAddress((void**)&gthi, g_gthi);
    cudaGetSymbolAddress((void**)&w3hi, g_w3hi);
    cudaGetSymbolAddress((void**)&wd1hi, g_wd1hi);
    cudaGetSymbolAddress((void**)&wop, g_wop);     cudaGetSymbolAddress((void**)&bop, g_bop);
    cudaGetSymbolAddress((void**)&dhi, g_dhi);
    cudaGetSymbolAddress((void**)&thi, g_thi);
    cudaGetSymbolAddress((void**)&zbias, g_zero_bias);

    // precompute + conversions needed by the capsule loop
    convert_x_kernel<<<(int)(((size_t)BROWS * KPAD_CAP + 255) / 256), 256>>>(x, hhi, hhi2);
    int wcap = NPAD_CAP * KPAD_CAP;
    compute_gt<<<(wcap + 255) / 256, 256>>>(W1, W2, b1, gthi, g2, zbias);
    convert_w_kernel<<<(wcap + 255) / 256, 256>>>(W3, FV, FV, w3hi, NPAD_CAP, KPAD_CAP);

    // capsule iterations (h double-buffered; pure fp16 GEMMs)
    const dim3 gcap(2, BROWS / 128);
    for (int it = 0; it < NITER; it++) {
        __half* chi = (it & 1) ? hhi2 : hhi;
        __half* nhi = (it & 1) ? hhi : hhi2;
        int last = (it == NITER - 1);
        // z = v @ (W1^T W2), stored fp16, padded stride
        gemm_mma<<<gcap, 256, SMEM_BYTES>>>(chi, KPAD_CAP, gthi, KPAD_CAP, zbias,
                                            nullptr, z, KPAD_CAP, KPAD_CAP, FV, 0,
                                            nullptr, nullptr, nullptr);
        score_kernel<<<BATCH / 8, dim3(32, 8)>>>(z, chi, g2, p);
        // u GEMM with fused h = probs @ (u + b3)
        gemm_mma<<<gcap, 256, SMEM_BYTES>>>(chi, KPAD_CAP, w3hi, KPAD_CAP, b3,
                                            nullptr, nullptr, 0, KPAD_CAP, FV, 0,
                                            p, nhi, last ? dhi : nullptr);
    }

    // decoder precompute (off capsule critical path for profiling clarity)
    int wdec = FEAT * FEAT;
    convert_w_kernel<<<(wdec + 255) / 256, 256>>>(Wd1, FEAT, FEAT, wd1hi, FEAT, FEAT);
    fold_head<<<(10 * FEAT + 255) / 256, 256>>>(Wo, Wd2, bd2, bo, wop, bop);

    // decoder layer 1 (fp16) + folded head
    const dim3 gdec(7, BATCH / 128);
    gemm_mma<<<gdec, 256, SMEM_BYTES>>>(dhi, FEAT, wd1hi, FEAT, bd1,
                                        nullptr, thi, FEAT, FEAT, FEAT, 1,
                                        nullptr, nullptr, nullptr);
    head_kernel<<<BATCH / 8, dim3(32, 8)>>>(thi, wop, bop, out);
}

// round 10
// speedup vs baseline: 2.3892x; 1.1067x over previous
#include <cuda_runtime.h>
#include <cuda_fp16.h>
#include <math.h>
#include <stdint.h>

#define BATCH 32768
#define FEAT  784
#define FV    196
#define NITER 8
#define BROWS (BATCH * 4)        // 131072 capsule rows

#define KPAD_CAP 208             // capsule K padded (3*64 + 16)
#define NPAD_CAP 224             // capsule N padded (2*112)

// ----------------------------- scratch ------------------------------------
__device__ __align__(256) __half g_hhi [(size_t)BROWS * KPAD_CAP];
__device__ __align__(256) __half g_hhi2[(size_t)BROWS * KPAD_CAP];
__device__ __align__(256) __half g_z[(size_t)BROWS * KPAD_CAP];   // padded stride, pads stay 0
__device__ __align__(256) float  g_p[(size_t)BATCH * 16];
__device__ __align__(256) __half g_gthi[NPAD_CAP * KPAD_CAP];
__device__ __align__(256) float  g_g2[KPAD_CAP];                  // pads stay 0
__device__ __align__(256) __half g_w3hi[NPAD_CAP * KPAD_CAP];
__device__ __align__(256) __half g_wd1hi[FEAT * FEAT];
__device__ __align__(256) float  g_wop[10 * FEAT];
__device__ __align__(256) float  g_bop[16];
__device__ __align__(256) __half g_dhi[(size_t)BATCH * FEAT];
__device__ __align__(256) __half g_thi[(size_t)BATCH * FEAT];
__device__ __align__(256) float  g_zero_bias[NPAD_CAP];

// ----------------------------- PTX helpers --------------------------------
__device__ __forceinline__ uint32_t smem_u32(const void* p) {
    uint32_t a;
    asm("{ .reg .u64 t; cvta.to.shared.u64 t, %1; cvt.u32.u64 %0, t; }" : "=r"(a) : "l"(p));
    return a;
}
__device__ __forceinline__ void cp_async16(uint32_t dst, const void* src) {
    asm volatile("cp.async.cg.shared.global [%0], [%1], 16;" :: "r"(dst), "l"(src));
}
__device__ __forceinline__ void ldsm_x4(uint32_t* r, uint32_t addr) {
    asm volatile("ldmatrix.sync.aligned.m8n8.x4.shared.b16 {%0,%1,%2,%3}, [%4];"
                 : "=r"(r[0]), "=r"(r[1]), "=r"(r[2]), "=r"(r[3]) : "r"(addr));
}
__device__ __forceinline__ void ldsm_x2(uint32_t* r, uint32_t addr) {
    asm volatile("ldmatrix.sync.aligned.m8n8.x2.shared.b16 {%0,%1}, [%2];"
                 : "=r"(r[0]), "=r"(r[1]) : "r"(addr));
}
__device__ __forceinline__ void mma16816(float* c, const uint32_t* a, const uint32_t* b) {
    asm volatile("mma.sync.aligned.m16n8k16.row.col.f32.f16.f16.f32 "
                 "{%0,%1,%2,%3}, {%4,%5,%6,%7}, {%8,%9}, {%0,%1,%2,%3};"
                 : "+f"(c[0]), "+f"(c[1]), "+f"(c[2]), "+f"(c[3])
                 : "r"(a[0]), "r"(a[1]), "r"(a[2]), "r"(a[3]), "r"(b[0]), "r"(b[1]));
}
// swizzle for 128B rows, 16B granules
__device__ __forceinline__ uint32_t swz(int r, int g) {
    return (uint32_t)r * 128u + ((uint32_t)(g ^ (r & 7)) << 4);
}
// load 8 halves -> 8 floats
__device__ __forceinline__ void ld8h(float* f, const __half* p) {
    uint4 q = *(const uint4*)p;
    const __half2* h = reinterpret_cast<const __half2*>(&q);
#pragma unroll
    for (int i = 0; i < 4; i++) {
        float2 a = __half22float2(h[i]);
        f[2*i] = a.x; f[2*i+1] = a.y;
    }
}

// ----------------------------- GEMM (fp16 mma.sync, 2-stage pipeline) -----
// C[M, n_real] = A @ W^T + bias, fp32 accumulation, fp16 inputs.
// block 128 x 112, BK=64 full chunks + one 16-wide tail (K = 64*n + 16).
// Double-buffered smem stages; cp.async of chunk ch+1 overlaps MMA of ch.
// 8 warps 4x2, warp tile 32x56.
// probs != null: capsule-u mode; epilogue h = probs @ (u + bias) -> Hhi/Dhi.
// Else writes Cf (fp32) and/or Ch (fp16), optional relu.
#define OFF_W 16384u
#define STAGE_BYTES 30720u
#define SMEM_BYTES 61440

__global__ __launch_bounds__(256, 2)
void gemm_mma(const __half* __restrict__ A, int lda,
              const __half* __restrict__ W, int ldw,
              const float* __restrict__ bias,
              float* __restrict__ Cf, __half* __restrict__ Ch,
              int ldc, int K, int n_real, int relu,
              const float* __restrict__ probs, __half* __restrict__ Hhi,
              __half* __restrict__ Dhi)
{
    extern __shared__ char smem[];
    const uint32_t sb = smem_u32(smem);
    const int tid = threadIdx.x;
    const int lane = tid & 31;
    const int wid = tid >> 5;
    const int wm = wid & 3;
    const int wn = wid >> 2;
    const int m0 = blockIdx.y * 128;
    const int n0 = blockIdx.x * 112;
    const int nfull = K >> 6;            // 3 (capsule) or 12 (decoder)
    const int nch = nfull + 1;           // + 16-wide tail

    float acc[2][7][4];
#pragma unroll
    for (int i = 0; i < 2; i++)
#pragma unroll
        for (int j = 0; j < 7; j++)
#pragma unroll
            for (int v = 0; v < 4; v++) acc[i][j][v] = 0.f;

    // ---- chunk loaders (stage = ch & 1) ----
    auto load_full = [&](int ch) {
        const uint32_t s = sb + (uint32_t)(ch & 1) * STAGE_BYTES;
        const int kc = ch << 6;
#pragma unroll
        for (int i = 0; i < 4; i++) {           // A: 128 rows x 8 granules
            int idx = tid + i * 256;
            int r = idx >> 3, g = idx & 7;
            cp_async16(s + swz(r, g), A + (size_t)(m0 + r) * lda + kc + g * 8);
        }
#pragma unroll
        for (int i = 0; i < 3; i++) {           // W: 112 rows x 8 granules = 896
            int idx = tid + i * 256;
            int r = idx >> 3, g = idx & 7;
            cp_async16(s + OFF_W + swz(r, g), W + (size_t)(n0 + r) * ldw + kc + g * 8);
        }
        {
            int idx = tid + 768;
            if (idx < 896) {
                int r = idx >> 3, g = idx & 7;
                cp_async16(s + OFF_W + swz(r, g), W + (size_t)(n0 + r) * ldw + kc + g * 8);
            }
        }
        asm volatile("cp.async.commit_group;");
    };
    auto load_tail = [&](int ch) {
        const uint32_t s = sb + (uint32_t)(ch & 1) * STAGE_BYTES;
        const int kc = ch << 6;
        {
            int r = tid >> 1, g = tid & 1;      // A: 128 x 2 granules = 256
            cp_async16(s + swz(r, g), A + (size_t)(m0 + r) * lda + kc + g * 8);
        }
        if (tid < 224) {                        // W: 112 x 2 granules
            int r = tid >> 1, g = tid & 1;
            cp_async16(s + OFF_W + swz(r, g), W + (size_t)(n0 + r) * ldw + kc + g * 8);
        }
        asm volatile("cp.async.commit_group;");
    };
    // ---- one k-step (16 cols) of MMAs from stage s ----
    auto compute_ks = [&](uint32_t s, int ks) {
        uint32_t ah[2][4], bh[7][2];
        const uint32_t sw = s + OFF_W;
#pragma unroll
        for (int mf = 0; mf < 2; mf++) {
            int r = wm * 32 + mf * 16 + (lane & 15);
            int g = ks * 2 + (lane >> 4);
            ldsm_x4(ah[mf], s + swz(r, g));
        }
#pragma unroll
        for (int p = 0; p < 3; p++) {
            int r = wn * 56 + p * 16 + (lane & 7) + ((lane >> 4) & 1) * 8;
            int g = ks * 2 + ((lane >> 3) & 1);
            uint32_t t4[4];
            ldsm_x4(t4, sw + swz(r, g));
            bh[2*p][0] = t4[0]; bh[2*p][1] = t4[1];
            bh[2*p+1][0] = t4[2]; bh[2*p+1][1] = t4[3];
        }
        {
            int l15 = lane & 15;
            int r = wn * 56 + 48 + (l15 & 7);
            int g = ks * 2 + ((l15 >> 3) & 1);
            ldsm_x2(bh[6], sw + swz(r, g));
        }
#pragma unroll
        for (int mf = 0; mf < 2; mf++)
#pragma unroll
            for (int nf = 0; nf < 7; nf++)
                mma16816(acc[mf][nf], ah[mf], bh[nf]);
    };

    // ---- pipelined mainloop ----
    if (nfull > 0) load_full(0); else load_tail(0);
    for (int ch = 0; ch < nch; ch++) {
        if (ch + 1 < nch) {
            if (ch + 1 < nfull) load_full(ch + 1); else load_tail(ch + 1);
            asm volatile("cp.async.wait_group 1;");
        } else {
            asm volatile("cp.async.wait_group 0;");
        }
        __syncthreads();
        const uint32_t s = sb + (uint32_t)(ch & 1) * STAGE_BYTES;
        if (ch < nfull) {
#pragma unroll
            for (int ks = 0; ks < 4; ks++) compute_ks(s, ks);
        } else {
            compute_ks(s, 0);
        }
        if (ch + 1 < nch) __syncthreads();
    }

    if (probs) {
        // fused attention epilogue: u in acc; h[t] = sum_s p[t][s] * (u[s]+bias)
#pragma unroll
        for (int mf = 0; mf < 2; mf++)
#pragma unroll
        for (int hf = 0; hf < 2; hf++) {
            int row = m0 + wm * 32 + mf * 16 + hf * 8 + (lane >> 2);
            int batch = row >> 2, t = row & 3;
            float4 pv = *(const float4*)(probs + (size_t)batch * 16 + t * 4);
            int base = (lane >> 2) & 4;
#pragma unroll
            for (int nf = 0; nf < 7; nf++)
#pragma unroll
            for (int e = 0; e < 2; e++) {
                int c = n0 + wn * 56 + nf * 8 + ((lane & 3) << 1) + e;
                float uv = acc[mf][nf][hf * 2 + e] + ((c < n_real) ? bias[c] : 0.f);
                float h = 0.f;
#pragma unroll
                for (int s2 = 0; s2 < 4; s2++) {
                    float us = __shfl_sync(0xffffffffu, uv, ((base + s2) << 2) | (lane & 3));
                    float ps = (s2 == 0) ? pv.x : (s2 == 1) ? pv.y : (s2 == 2) ? pv.z : pv.w;
                    h = fmaf(ps, us, h);
                }
                if (c < n_real) {
                    __half hv = __float2half_rn(h);
                    Hhi[(size_t)row * KPAD_CAP + c] = hv;
                    if (Dhi) Dhi[(size_t)batch * FEAT + t * FV + c] = hv;
                }
            }
        }
    } else {
#pragma unroll
        for (int mf = 0; mf < 2; mf++)
#pragma unroll
        for (int nf = 0; nf < 7; nf++) {
            int r = m0 + wm * 32 + mf * 16 + (lane >> 2);
            int c = n0 + wn * 56 + nf * 8 + ((lane & 3) << 1);
#pragma unroll
            for (int hf = 0; hf < 2; hf++) {
                int rr = r + hf * 8;
#pragma unroll
                for (int e = 0; e < 2; e++) {
                    int cc = c + e;
                    if (cc >= n_real) continue;
                    float v = acc[mf][nf][hf * 2 + e] + bias[cc];
                    if (relu) v = fmaxf(v, 0.f);
                    size_t o = (size_t)rr * ldc + cc;
                    if (Cf) Cf[o] = v;
                    if (Ch) Ch[o] = __float2half_rn(v);
                }
            }
        }
    }
}

// ----------------------------- precompute ----------------------------------
// Gt[n,k] = sum_j W1[j,k] * W2[j,n]   (so z = v @ Gt^T = v @ (W1^T W2))
// g2[k]   = sum_j b1[j] * W2[j,k]
__global__ void compute_gt(const float* __restrict__ W1, const float* __restrict__ W2,
                           const float* __restrict__ b1,
                           __half* __restrict__ gthi,
                           float* __restrict__ g2, float* __restrict__ zbias)
{
    int idx = blockIdx.x * blockDim.x + threadIdx.x;
    if (idx < FV) {
        float s = 0.f;
        for (int j = 0; j < FV; j++) s = fmaf(b1[j], W2[(size_t)j * FV + idx], s);
        g2[idx] = s;
    }
    if (idx < NPAD_CAP) zbias[idx] = 0.f;
    if (idx >= NPAD_CAP * KPAD_CAP) return;
    int n = idx / KPAD_CAP, k = idx % KPAD_CAP;
    float s = 0.f;
    if (n < FV && k < FV) {
        for (int j = 0; j < FV; j++)
            s = fmaf(W1[(size_t)j * FV + k], W2[(size_t)j * FV + n], s);
    }
    gthi[idx] = __float2half_rn(s);
}

// Wop = Wo @ Wd2 (10 x 784, exact fp32); bop = Wo @ bd2 + bo
__global__ void fold_head(const float* __restrict__ Wo, const float* __restrict__ Wd2,
                          const float* __restrict__ bd2, const float* __restrict__ bo,
                          float* __restrict__ Wop, float* __restrict__ bop)
{
    int idx = blockIdx.x * blockDim.x + threadIdx.x;
    if (idx < 10) {
        float s = bo[idx];
        for (int i = 0; i < FEAT; i++) s = fmaf(Wo[(size_t)idx * FEAT + i], bd2[i], s);
        bop[idx] = s;
    }
    if (idx >= 10 * FEAT) return;
    int j = idx / FEAT, k = idx % FEAT;
    float s = 0.f;
    for (int i = 0; i < FEAT; i++)
        s = fmaf(Wo[(size_t)j * FEAT + i], Wd2[(size_t)i * FEAT + k], s);
    Wop[idx] = s;
}

// ----------------------------- conversions --------------------------------
__global__ void convert_x_kernel(const float* __restrict__ x,
                                 __half* __restrict__ hhi, __half* __restrict__ hhi2)
{
    size_t idx = (size_t)blockIdx.x * blockDim.x + threadIdx.x;
    if (idx >= (size_t)BROWS * KPAD_CAP) return;
    size_t R = idx / KPAD_CAP;
    int f = (int)(idx % KPAD_CAP);
    if (f < FV) {
        hhi[idx] = __float2half_rn(x[R * FV + f]);
    } else {
        hhi[idx]  = __float2half_rn(0.f);   // pad cols zero in both buffers
        hhi2[idx] = __float2half_rn(0.f);
    }
}

__global__ void convert_w_kernel(const float* __restrict__ W, int rin, int cin,
                                 __half* __restrict__ hi, int rout, int cout)
{
    int idx = blockIdx.x * blockDim.x + threadIdx.x;
    if (idx >= rout * cout) return;
    int r = idx / cout, c = idx % cout;
    float v = (r < rin && c < cin) ? W[(size_t)r * cin + c] : 0.f;
    hi[idx] = __float2half_rn(v);
}

// ----------------------------- scores (fp32, vectorized) -------------------
// probs[b,t,s] = softmax_s( z_t . v_s + beta_s ),  beta_s = v_s . g2
// one warp per batch; lane j<26 owns 16B granule j of each row (208 halves).
__global__ __launch_bounds__(256)
void score_kernel(const __half* __restrict__ z,
                  const __half* __restrict__ hhi,
                  const float* __restrict__ g2, float* __restrict__ probs)
{
    const int b    = blockIdx.x * 8 + threadIdx.y;
    const int lane = threadIdx.x;
    const __half* zb = z + (size_t)b * 4 * KPAD_CAP;
    const __half* vb = hhi + (size_t)b * 4 * KPAD_CAP;

    float s[4][4], beta[4];
#pragma unroll
    for (int t = 0; t < 4; t++) {
        beta[t] = 0.f;
#pragma unroll
        for (int r = 0; r < 4; r++) s[t][r] = 0.f;
    }

    if (lane < 26) {
        float zf[4][8], vf[4][8], gf[8];
#pragma unroll
        for (int t = 0; t < 4; t++) {
            ld8h(zf[t], zb + t * KPAD_CAP + lane * 8);
            ld8h(vf[t], vb + t * KPAD_CAP + lane * 8);
        }
        float4 ga = *(const float4*)(g2 + lane * 8);
        float4 gb = *(const float4*)(g2 + lane * 8 + 4);
        gf[0]=ga.x; gf[1]=ga.y; gf[2]=ga.z; gf[3]=ga.w;
        gf[4]=gb.x; gf[5]=gb.y; gf[6]=gb.z; gf[7]=gb.w;
#pragma unroll
        for (int t = 0; t < 4; t++) {
#pragma unroll
            for (int e = 0; e < 8; e++)
                beta[t] = fmaf(vf[t][e], gf[e], beta[t]);
#pragma unroll
            for (int r = 0; r < 4; r++) {
                float acc = 0.f;
#pragma unroll
                for (int e = 0; e < 8; e++)
                    acc = fmaf(zf[t][e], vf[r][e], acc);
                s[t][r] = acc;
            }
        }
    }
#pragma unroll
    for (int t = 0; t < 4; t++) {
#pragma unroll
        for (int off = 16; off > 0; off >>= 1)
            beta[t] += __shfl_xor_sync(0xffffffffu, beta[t], off);
#pragma unroll
        for (int r = 0; r < 4; r++)
#pragma unroll
            for (int off = 16; off > 0; off >>= 1)
                s[t][r] += __shfl_xor_sync(0xffffffffu, s[t][r], off);
    }

    float p[4][4];
#pragma unroll
    for (int t = 0; t < 4; t++) {
        float sc[4];
#pragma unroll
        for (int r = 0; r < 4; r++) sc[r] = s[t][r] + beta[r];
        float m = fmaxf(fmaxf(sc[0], sc[1]), fmaxf(sc[2], sc[3]));
        float e0 = expf(sc[0] - m), e1 = expf(sc[1] - m);
        float e2 = expf(sc[2] - m), e3 = expf(sc[3] - m);
        float inv = 1.f / (e0 + e1 + e2 + e3);
        p[t][0] = e0 * inv; p[t][1] = e1 * inv; p[t][2] = e2 * inv; p[t][3] = e3 * inv;
    }
    if (lane < 16)
        probs[(size_t)b * 16 + lane] = p[lane >> 2][lane & 3];
}

// ----------------------------- head (fp16 activations, folded Wd2) ---------
__global__ __launch_bounds__(256)
void head_kernel(const __half* __restrict__ T, const float* __restrict__ Wop,
                 const float* __restrict__ bop, float* __restrict__ out)
{
    const int b    = blockIdx.x * 8 + threadIdx.y;
    const int lane = threadIdx.x;
    const __half* a = T + (size_t)b * FEAT;

    float acc[10];
#pragma unroll
    for (int j = 0; j < 10; j++) acc[j] = 0.f;
    for (int kk = lane; kk < FEAT; kk += 32) {
        float av = __half2float(a[kk]);
#pragma unroll
        for (int j = 0; j < 10; j++)
            acc[j] = fmaf(av, Wop[j * FEAT + kk], acc[j]);
    }
#pragma unroll
    for (int j = 0; j < 10; j++)
#pragma unroll
        for (int off = 16; off > 0; off >>= 1)
            acc[j] += __shfl_xor_sync(0xffffffffu, acc[j], off);

    if (lane == 0) {
        float v[10], m = -1e30f;
#pragma unroll
        for (int j = 0; j < 10; j++) { v[j] = acc[j] + bop[j]; m = fmaxf(m, v[j]); }
        float ssum = 0.f;
#pragma unroll
        for (int j = 0; j < 10; j++) { v[j] = expf(v[j] - m); ssum += v[j]; }
        float inv = 1.f / ssum;
#pragma unroll
        for (int j = 0; j < 10; j++) out[(size_t)b * 10 + j] = v[j] * inv;
    }
}

// ---------------------------------------------------------------------------
extern "C" void kernel_launch(void* const* d_in, const int* in_sizes, int n_in,
                              void* d_out, int out_size)
{
    const float* x   = (const float*)d_in[0];
    const float* W1  = (const float*)d_in[1];
    const float* b1  = (const float*)d_in[2];
    const float* W2  = (const float*)d_in[3];
    const float* W3  = (const float*)d_in[5];
    const float* b3  = (const float*)d_in[6];
    const float* Wd1 = (const float*)d_in[7];
    const float* bd1 = (const float*)d_in[8];
    const float* Wd2 = (const float*)d_in[9];
    const float* bd2 = (const float*)d_in[10];
    const float* Wo  = (const float*)d_in[11];
    const float* bo  = (const float*)d_in[12];
    float* out = (float*)d_out;

    cudaFuncSetAttribute(gemm_mma, cudaFuncAttributeMaxDynamicSharedMemorySize, SMEM_BYTES);

    __half *hhi, *hhi2, *z, *gthi, *w3hi, *wd1hi, *dhi, *thi;
    float *p, *g2, *zbias, *wop, *bop;
    cudaGetSymbolAddress((void**)&hhi, g_hhi);
    cudaGetSymbolAddress((void**)&hhi2, g_hhi2);
    cudaGetSymbolAddress((void**)&z, g_z);         cudaGetSymbolAddress((void**)&p, g_p);
    cudaGetSymbolAddress((void**)&g2, g_g2);
    cudaGetSymbolAddress((void**)&gthi, g_gthi);
    cudaGetSymbolAddress((void**)&w3hi, g_w3hi);
    cudaGetSymbolAddress((void**)&wd1hi, g_wd1hi);
    cudaGetSymbolAddress((void**)&wop, g_wop);     cudaGetSymbolAddress((void**)&bop, g_bop);
    cudaGetSymbolAddress((void**)&dhi, g_dhi);
    cudaGetSymbolAddress((void**)&thi, g_thi);
    cudaGetSymbolAddress((void**)&zbias, g_zero_bias);

    // precompute + conversions needed by the capsule loop
    convert_x_kernel<<<(int)(((size_t)BROWS * KPAD_CAP + 255) / 256), 256>>>(x, hhi, hhi2);
    int wcap = NPAD_CAP * KPAD_CAP;
    compute_gt<<<(wcap + 255) / 256, 256>>>(W1, W2, b1, gthi, g2, zbias);
    convert_w_kernel<<<(wcap + 255) / 256, 256>>>(W3, FV, FV, w3hi, NPAD_CAP, KPAD_CAP);

    // capsule iterations (h double-buffered; pure fp16 GEMMs)
    const dim3 gcap(2, BROWS / 128);
    for (int it = 0; it < NITER; it++) {
        __half* chi = (it & 1) ? hhi2 : hhi;
        __half* nhi = (it & 1) ? hhi : hhi2;
        int last = (it == NITER - 1);
        // z = v @ (W1^T W2), stored fp16, padded stride
        gemm_mma<<<gcap, 256, SMEM_BYTES>>>(chi, KPAD_CAP, gthi, KPAD_CAP, zbias,
                                            nullptr, z, KPAD_CAP, KPAD_CAP, FV, 0,
                                            nullptr, nullptr, nullptr);
        score_kernel<<<BATCH / 8, dim3(32, 8)>>>(z, chi, g2, p);
        // u GEMM with fused h = probs @ (u + b3)
        gemm_mma<<<gcap, 256, SMEM_BYTES>>>(chi, KPAD_CAP, w3hi, KPAD_CAP, b3,
                                            nullptr, nullptr, 0, KPAD_CAP, FV, 0,
                                            p, nhi, last ? dhi : nullptr);
    }

    // decoder precompute (off capsule critical path for profiling clarity)
    int wdec = FEAT * FEAT;
    convert_w_kernel<<<(wdec + 255) / 256, 256>>>(Wd1, FEAT, FEAT, wd1hi, FEAT, FEAT);
    fold_head<<<(10 * FEAT + 255) / 256, 256>>>(Wo, Wd2, bd2, bo, wop, bop);

    // decoder layer 1 (fp16) + folded head
    const dim3 gdec(7, BATCH / 128);
    gemm_mma<<<gdec, 256, SMEM_BYTES>>>(dhi, FEAT, wd1hi, FEAT, bd1,
                                        nullptr, thi, FEAT, FEAT, FEAT, 1,
                                        nullptr, nullptr, nullptr);
    head_kernel<<<BATCH / 8, dim3(32, 8)>>>(thi, wop, bop, out);
}

// round 11
// speedup vs baseline: 2.7707x; 1.1597x over previous
#include <cuda_runtime.h>
#include <cuda_fp16.h>
#include <math.h>
#include <stdint.h>

#define BATCH 32768
#define FEAT  784
#define FV    196
#define NITER 8
#define BROWS (BATCH * 4)        // 131072 capsule rows

#define KPAD_CAP 208             // capsule K padded (3*64 + 16)
#define NPAD_CAP 224             // capsule N padded (4*56)

// ----------------------------- scratch ------------------------------------
__device__ __align__(256) __half g_hhi [(size_t)BROWS * KPAD_CAP];
__device__ __align__(256) __half g_hhi2[(size_t)BROWS * KPAD_CAP];
__device__ __align__(256) __half g_gthi[NPAD_CAP * KPAD_CAP];
__device__ __align__(256) float  g_g2[KPAD_CAP];                  // pads stay 0
__device__ __align__(256) __half g_w3hi[NPAD_CAP * KPAD_CAP];
__device__ __align__(256) __half g_wd1hi[FEAT * FEAT];
__device__ __align__(256) float  g_wop[10 * FEAT];
__device__ __align__(256) float  g_bop[16];
__device__ __align__(256) __half g_dhi[(size_t)BATCH * FEAT];
__device__ __align__(256) __half g_thi[(size_t)BATCH * FEAT];

// ----------------------------- PTX helpers --------------------------------
__device__ __forceinline__ uint32_t smem_u32(const void* p) {
    uint32_t a;
    asm("{ .reg .u64 t; cvta.to.shared.u64 t, %1; cvt.u32.u64 %0, t; }" : "=r"(a) : "l"(p));
    return a;
}
__device__ __forceinline__ void cp_async16(uint32_t dst, const void* src) {
    asm volatile("cp.async.cg.shared.global [%0], [%1], 16;" :: "r"(dst), "l"(src));
}
__device__ __forceinline__ void ldsm_x4(uint32_t* r, uint32_t addr) {
    asm volatile("ldmatrix.sync.aligned.m8n8.x4.shared.b16 {%0,%1,%2,%3}, [%4];"
                 : "=r"(r[0]), "=r"(r[1]), "=r"(r[2]), "=r"(r[3]) : "r"(addr));
}
__device__ __forceinline__ void ldsm_x2(uint32_t* r, uint32_t addr) {
    asm volatile("ldmatrix.sync.aligned.m8n8.x2.shared.b16 {%0,%1}, [%2];"
                 : "=r"(r[0]), "=r"(r[1]) : "r"(addr));
}
__device__ __forceinline__ void mma16816(float* c, const uint32_t* a, const uint32_t* b) {
    asm volatile("mma.sync.aligned.m16n8k16.row.col.f32.f16.f16.f32 "
                 "{%0,%1,%2,%3}, {%4,%5,%6,%7}, {%8,%9}, {%0,%1,%2,%3};"
                 : "+f"(c[0]), "+f"(c[1]), "+f"(c[2]), "+f"(c[3])
                 : "r"(a[0]), "r"(a[1]), "r"(a[2]), "r"(a[3]), "r"(b[0]), "r"(b[1]));
}
// swizzle for 128B rows, 16B granules
__device__ __forceinline__ uint32_t swz(int r, int g) {
    return (uint32_t)r * 128u + ((uint32_t)(g ^ (r & 7)) << 4);
}
// load 8 halves -> 8 floats (works on global or shared generic pointers)
__device__ __forceinline__ void ld8h(float* f, const __half* p) {
    uint4 q = *(const uint4*)p;
    const __half2* h = reinterpret_cast<const __half2*>(&q);
#pragma unroll
    for (int i = 0; i < 4; i++) {
        float2 a = __half22float2(h[i]);
        f[2*i] = a.x; f[2*i+1] = a.y;
    }
}

// ======================= fused capsule iteration ===========================
// One 512-thread block owns 128 rows (32 batches). A resident in smem.
// Phase 1: z = A @ Gt^T (224 cols) -> smem. Phase 2: scores+softmax in-block.
// Phase 3: u = A @ W3^T, epilogue h = probs @ (u + b3) -> global.
#define SMEM_A_OFF 0u
#define A_CHUNK    16384u               // one 64-col chunk of A (swz layout)
#define SMEM_W_OFF 65536u
#define W_STAGE    28672u               // 224 rows x 128B
#define SMEM_Z_OFF 122880u              // 128 x 224 fp16, row stride 448B
#define SMEM_P_OFF 180224u              // 32 batches x 16 floats
#define CAP_SMEM   182272

__global__ __launch_bounds__(512, 1)
void capsule_iter(const __half* __restrict__ A,
                  const __half* __restrict__ Gt,
                  const __half* __restrict__ W3,
                  const float* __restrict__ g2,
                  const float* __restrict__ b3,
                  __half* __restrict__ H,
                  __half* __restrict__ D)
{
    extern __shared__ char smem[];
    const uint32_t sb = smem_u32(smem);
    const int tid = threadIdx.x;
    const int lane = tid & 31;
    const int wid = tid >> 5;        // 0..15
    const int wm = wid & 3;          // rows wm*32
    const int wn = wid >> 2;         // cols wn*56 (0..3)
    const int m0 = blockIdx.x * 128;

    float acc[2][7][4];

    // ---- W chunk loader (stage = ch & 1) ----
    auto load_w = [&](const __half* Wp, int ch) {
        const uint32_t s = sb + SMEM_W_OFF + (uint32_t)(ch & 1) * W_STAGE;
        if (ch < 3) {
#pragma unroll
            for (int i = 0; i < 4; i++) {          // 224 rows x 8 granules = 1792
                int idx = tid + i * 512;
                if (idx < 1792) {
                    int r = idx >> 3, g = idx & 7;
                    cp_async16(s + swz(r, g), Wp + (size_t)r * KPAD_CAP + (ch << 6) + g * 8);
                }
            }
        } else {
            if (tid < 448) {                       // tail: 224 x 2 granules
                int r = tid >> 1, g = tid & 1;
                cp_async16(s + swz(r, g), Wp + (size_t)r * KPAD_CAP + 192 + g * 8);
            }
        }
        asm volatile("cp.async.commit_group;");
    };

    // ---- one 16-col k-step of MMAs ----
    auto compute_ks = [&](uint32_t sA, uint32_t sW, int ks) {
        uint32_t ah[2][4], bh[7][2];
#pragma unroll
        for (int mf = 0; mf < 2; mf++) {
            int r = wm * 32 + mf * 16 + (lane & 15);
            int g = ks * 2 + (lane >> 4);
            ldsm_x4(ah[mf], sA + swz(r, g));
        }
#pragma unroll
        for (int p = 0; p < 3; p++) {
            int r = wn * 56 + p * 16 + (lane & 7) + ((lane >> 4) & 1) * 8;
            int g = ks * 2 + ((lane >> 3) & 1);
            uint32_t t4[4];
            ldsm_x4(t4, sW + swz(r, g));
            bh[2*p][0] = t4[0]; bh[2*p][1] = t4[1];
            bh[2*p+1][0] = t4[2]; bh[2*p+1][1] = t4[3];
        }
        {
            int l15 = lane & 15;
            int r = wn * 56 + 48 + (l15 & 7);
            int g = ks * 2 + ((l15 >> 3) & 1);
            ldsm_x2(bh[6], sW + swz(r, g));
        }
#pragma unroll
        for (int mf = 0; mf < 2; mf++)
#pragma unroll
            for (int nf = 0; nf < 7; nf++)
                mma16816(acc[mf][nf], ah[mf], bh[nf]);
    };

    auto zero_acc = [&]() {
#pragma unroll
        for (int i = 0; i < 2; i++)
#pragma unroll
            for (int j = 0; j < 7; j++)
#pragma unroll
                for (int v = 0; v < 4; v++) acc[i][j][v] = 0.f;
    };

    // ---- load A fully (4 chunks) ----
    for (int i = 0; i < 7; i++) {
        int idx = tid + i * 512;
        if (idx < 128 * 26) {
            int r = idx / 26, gg = idx - r * 26;
            int c = gg >> 3, g = gg & 7;
            cp_async16(sb + SMEM_A_OFF + (uint32_t)c * A_CHUNK + swz(r, g),
                       A + (size_t)(m0 + r) * KPAD_CAP + gg * 8);
        }
    }
    asm volatile("cp.async.commit_group;");

    // ================= phase 1: z = A @ Gt^T =================
    zero_acc();
    load_w(Gt, 0);
    for (int ch = 0; ch < 4; ch++) {
        if (ch < 3) { load_w(Gt, ch + 1); asm volatile("cp.async.wait_group 1;"); }
        else        { asm volatile("cp.async.wait_group 0;"); }
        __syncthreads();
        const uint32_t sA = sb + SMEM_A_OFF + (uint32_t)ch * A_CHUNK;
        const uint32_t sW = sb + SMEM_W_OFF + (uint32_t)(ch & 1) * W_STAGE;
        if (ch < 3) {
#pragma unroll
            for (int ks = 0; ks < 4; ks++) compute_ks(sA, sW, ks);
        } else compute_ks(sA, sW, 0);
        __syncthreads();
    }

    // z -> smem (fp16, row stride 448B). Gt pad rows are zero -> z pads zero.
#pragma unroll
    for (int mf = 0; mf < 2; mf++)
#pragma unroll
    for (int nf = 0; nf < 7; nf++)
#pragma unroll
    for (int hf = 0; hf < 2; hf++) {
        int row = wm * 32 + mf * 16 + hf * 8 + (lane >> 2);
        int col = wn * 56 + nf * 8 + ((lane & 3) << 1);
        __half2 hv = __floats2half2_rn(acc[mf][nf][hf * 2], acc[mf][nf][hf * 2 + 1]);
        *(__half2*)(smem + SMEM_Z_OFF + (uint32_t)row * 448u + (uint32_t)col * 2u) = hv;
    }
    __syncthreads();

    // prefetch W3 chunk 0 while scores compute
    load_w(W3, 0);

    // ================= phase 2: scores + softmax =================
    // warp w handles batches 2w, 2w+1 (block-local)
#pragma unroll
    for (int bi = 0; bi < 2; bi++) {
        int bb = wid * 2 + bi;
        float s[4][4], beta[4];
#pragma unroll
        for (int t = 0; t < 4; t++) {
            beta[t] = 0.f;
#pragma unroll
            for (int r = 0; r < 4; r++) s[t][r] = 0.f;
        }
        if (lane < 26) {
            float zf[4][8], vf[4][8], gf[8];
            int c = lane >> 3, g = lane & 7;
#pragma unroll
            for (int t = 0; t < 4; t++) {
                int row = bb * 4 + t;
                ld8h(zf[t], (const __half*)(smem + SMEM_Z_OFF + (uint32_t)row * 448u + (uint32_t)lane * 16u));
                ld8h(vf[t], (const __half*)(smem + SMEM_A_OFF + (uint32_t)c * A_CHUNK + swz(row, g)));
            }
            float4 ga = *(const float4*)(g2 + lane * 8);
            float4 gb = *(const float4*)(g2 + lane * 8 + 4);
            gf[0]=ga.x; gf[1]=ga.y; gf[2]=ga.z; gf[3]=ga.w;
            gf[4]=gb.x; gf[5]=gb.y; gf[6]=gb.z; gf[7]=gb.w;
#pragma unroll
            for (int t = 0; t < 4; t++) {
#pragma unroll
                for (int e = 0; e < 8; e++)
                    beta[t] = fmaf(vf[t][e], gf[e], beta[t]);
#pragma unroll
                for (int r = 0; r < 4; r++) {
                    float a2 = 0.f;
#pragma unroll
                    for (int e = 0; e < 8; e++)
                        a2 = fmaf(zf[t][e], vf[r][e], a2);
                    s[t][r] = a2;
                }
            }
        }
#pragma unroll
        for (int t = 0; t < 4; t++) {
#pragma unroll
            for (int off = 16; off > 0; off >>= 1)
                beta[t] += __shfl_xor_sync(0xffffffffu, beta[t], off);
#pragma unroll
            for (int r = 0; r < 4; r++)
#pragma unroll
                for (int off = 16; off > 0; off >>= 1)
                    s[t][r] += __shfl_xor_sync(0xffffffffu, s[t][r], off);
        }
        if (lane < 16) {
            int t = lane >> 2;
            float sc[4];
#pragma unroll
            for (int r = 0; r < 4; r++) sc[r] = s[t][r] + beta[r];
            float m = fmaxf(fmaxf(sc[0], sc[1]), fmaxf(sc[2], sc[3]));
            float e0 = expf(sc[0] - m), e1 = expf(sc[1] - m);
            float e2 = expf(sc[2] - m), e3 = expf(sc[3] - m);
            float inv = 1.f / (e0 + e1 + e2 + e3);
            float pe = (lane & 3) == 0 ? e0 : (lane & 3) == 1 ? e1 : (lane & 3) == 2 ? e2 : e3;
            *(float*)(smem + SMEM_P_OFF + (uint32_t)bb * 64u + (uint32_t)lane * 4u) = pe * inv;
        }
    }

    // ================= phase 3: u GEMM + attention mix =================
    zero_acc();
    for (int ch = 0; ch < 4; ch++) {
        if (ch < 3) { load_w(W3, ch + 1); asm volatile("cp.async.wait_group 1;"); }
        else        { asm volatile("cp.async.wait_group 0;"); }
        __syncthreads();   // also makes probs smem visible on first pass
        const uint32_t sA = sb + SMEM_A_OFF + (uint32_t)ch * A_CHUNK;
        const uint32_t sW = sb + SMEM_W_OFF + (uint32_t)(ch & 1) * W_STAGE;
        if (ch < 3) {
#pragma unroll
            for (int ks = 0; ks < 4; ks++) compute_ks(sA, sW, ks);
        } else compute_ks(sA, sW, 0);
        if (ch < 3) __syncthreads();
    }

    // epilogue: h[t] = sum_s p[t][s] * (u[s] + b3)
#pragma unroll
    for (int mf = 0; mf < 2; mf++)
#pragma unroll
    for (int hf = 0; hf < 2; hf++) {
        int br = wm * 32 + mf * 16 + hf * 8 + (lane >> 2);
        int bb = br >> 2, t = br & 3;
        float4 pv = *(const float4*)(smem + SMEM_P_OFF + (uint32_t)bb * 64u + (uint32_t)t * 16u);
        int base = (lane >> 2) & 4;
#pragma unroll
        for (int nf = 0; nf < 7; nf++)
#pragma unroll
        for (int e = 0; e < 2; e++) {
            int c = wn * 56 + nf * 8 + ((lane & 3) << 1) + e;
            float uv = acc[mf][nf][hf * 2 + e] + ((c < FV) ? b3[c] : 0.f);
            float h = 0.f;
#pragma unroll
            for (int s2 = 0; s2 < 4; s2++) {
                float us = __shfl_sync(0xffffffffu, uv, ((base + s2) << 2) | (lane & 3));
                float ps = (s2 == 0) ? pv.x : (s2 == 1) ? pv.y : (s2 == 2) ? pv.z : pv.w;
                h = fmaf(ps, us, h);
            }
            if (c < FV) {
                __half hv = __float2half_rn(h);
                int grow = m0 + br;
                H[(size_t)grow * KPAD_CAP + c] = hv;
                if (D) D[(size_t)(grow >> 2) * FEAT + t * FV + c] = hv;
            }
        }
    }
}

// ----------------------- decoder GEMM (fp16 mma.sync, 2-stage) -------------
#define OFF_W 16384u
#define STAGE_BYTES 30720u
#define SMEM_BYTES 61440

__global__ __launch_bounds__(256, 2)
void gemm_mma(const __half* __restrict__ A, int lda,
              const __half* __restrict__ W, int ldw,
              const float* __restrict__ bias,
              __half* __restrict__ Ch, int ldc, int K, int n_real, int relu)
{
    extern __shared__ char smem[];
    const uint32_t sb = smem_u32(smem);
    const int tid = threadIdx.x;
    const int lane = tid & 31;
    const int wid = tid >> 5;
    const int wm = wid & 3;
    const int wn = wid >> 2;
    const int m0 = blockIdx.y * 128;
    const int n0 = blockIdx.x * 112;
    const int nfull = K >> 6;
    const int nch = nfull + 1;

    float acc[2][7][4];
#pragma unroll
    for (int i = 0; i < 2; i++)
#pragma unroll
        for (int j = 0; j < 7; j++)
#pragma unroll
            for (int v = 0; v < 4; v++) acc[i][j][v] = 0.f;

    auto load_full = [&](int ch) {
        const uint32_t s = sb + (uint32_t)(ch & 1) * STAGE_BYTES;
        const int kc = ch << 6;
#pragma unroll
        for (int i = 0; i < 4; i++) {
            int idx = tid + i * 256;
            int r = idx >> 3, g = idx & 7;
            cp_async16(s + swz(r, g), A + (size_t)(m0 + r) * lda + kc + g * 8);
        }
#pragma unroll
        for (int i = 0; i < 3; i++) {
            int idx = tid + i * 256;
            int r = idx >> 3, g = idx & 7;
            cp_async16(s + OFF_W + swz(r, g), W + (size_t)(n0 + r) * ldw + kc + g * 8);
        }
        {
            int idx = tid + 768;
            if (idx < 896) {
                int r = idx >> 3, g = idx & 7;
                cp_async16(s + OFF_W + swz(r, g), W + (size_t)(n0 + r) * ldw + kc + g * 8);
            }
        }
        asm volatile("cp.async.commit_group;");
    };
    auto load_tail = [&](int ch) {
        const uint32_t s = sb + (uint32_t)(ch & 1) * STAGE_BYTES;
        const int kc = ch << 6;
        {
            int r = tid >> 1, g = tid & 1;
            cp_async16(s + swz(r, g), A + (size_t)(m0 + r) * lda + kc + g * 8);
        }
        if (tid < 224) {
            int r = tid >> 1, g = tid & 1;
            cp_async16(s + OFF_W + swz(r, g), W + (size_t)(n0 + r) * ldw + kc + g * 8);
        }
        asm volatile("cp.async.commit_group;");
    };
    auto compute_ks = [&](uint32_t s, int ks) {
        uint32_t ah[2][4], bh[7][2];
        const uint32_t sw = s + OFF_W;
#pragma unroll
        for (int mf = 0; mf < 2; mf++) {
            int r = wm * 32 + mf * 16 + (lane & 15);
            int g = ks * 2 + (lane >> 4);
            ldsm_x4(ah[mf], s + swz(r, g));
        }
#pragma unroll
        for (int p = 0; p < 3; p++) {
            int r = wn * 56 + p * 16 + (lane & 7) + ((lane >> 4) & 1) * 8;
            int g = ks * 2 + ((lane >> 3) & 1);
            uint32_t t4[4];
            ldsm_x4(t4, sw + swz(r, g));
            bh[2*p][0] = t4[0]; bh[2*p][1] = t4[1];
            bh[2*p+1][0] = t4[2]; bh[2*p+1][1] = t4[3];
        }
        {
            int l15 = lane & 15;
            int r = wn * 56 + 48 + (l15 & 7);
            int g = ks * 2 + ((l15 >> 3) & 1);
            ldsm_x2(bh[6], sw + swz(r, g));
        }
#pragma unroll
        for (int mf = 0; mf < 2; mf++)
#pragma unroll
            for (int nf = 0; nf < 7; nf++)
                mma16816(acc[mf][nf], ah[mf], bh[nf]);
    };

    if (nfull > 0) load_full(0); else load_tail(0);
    for (int ch = 0; ch < nch; ch++) {
        if (ch + 1 < nch) {
            if (ch + 1 < nfull) load_full(ch + 1); else load_tail(ch + 1);
            asm volatile("cp.async.wait_group 1;");
        } else {
            asm volatile("cp.async.wait_group 0;");
        }
        __syncthreads();
        const uint32_t s = sb + (uint32_t)(ch & 1) * STAGE_BYTES;
        if (ch < nfull) {
#pragma unroll
            for (int ks = 0; ks < 4; ks++) compute_ks(s, ks);
        } else {
            compute_ks(s, 0);
        }
        if (ch + 1 < nch) __syncthreads();
    }

#pragma unroll
    for (int mf = 0; mf < 2; mf++)
#pragma unroll
    for (int nf = 0; nf < 7; nf++) {
        int r = m0 + wm * 32 + mf * 16 + (lane >> 2);
        int c = n0 + wn * 56 + nf * 8 + ((lane & 3) << 1);
#pragma unroll
        for (int hf = 0; hf < 2; hf++) {
            int rr = r + hf * 8;
#pragma unroll
            for (int e = 0; e < 2; e++) {
                int cc = c + e;
                if (cc >= n_real) continue;
                float v = acc[mf][nf][hf * 2 + e] + bias[cc];
                if (relu) v = fmaxf(v, 0.f);
                Ch[(size_t)rr * ldc + cc] = __float2half_rn(v);
            }
        }
    }
}

// ----------------------------- precompute ----------------------------------
__global__ void compute_gt(const float* __restrict__ W1, const float* __restrict__ W2,
                           const float* __restrict__ b1,
                           __half* __restrict__ gthi, float* __restrict__ g2)
{
    int idx = blockIdx.x * blockDim.x + threadIdx.x;
    if (idx < KPAD_CAP) {
        float s = 0.f;
        if (idx < FV)
            for (int j = 0; j < FV; j++) s = fmaf(b1[j], W2[(size_t)j * FV + idx], s);
        g2[idx] = s;
    }
    if (idx >= NPAD_CAP * KPAD_CAP) return;
    int n = idx / KPAD_CAP, k = idx % KPAD_CAP;
    float s = 0.f;
    if (n < FV && k < FV) {
        for (int j = 0; j < FV; j++)
            s = fmaf(W1[(size_t)j * FV + k], W2[(size_t)j * FV + n], s);
    }
    gthi[idx] = __float2half_rn(s);
}

__global__ void fold_head(const float* __restrict__ Wo, const float* __restrict__ Wd2,
                          const float* __restrict__ bd2, const float* __restrict__ bo,
                          float* __restrict__ Wop, float* __restrict__ bop)
{
    int idx = blockIdx.x * blockDim.x + threadIdx.x;
    if (idx < 10) {
        float s = bo[idx];
        for (int i = 0; i < FEAT; i++) s = fmaf(Wo[(size_t)idx * FEAT + i], bd2[i], s);
        bop[idx] = s;
    }
    if (idx >= 10 * FEAT) return;
    int j = idx / FEAT, k = idx % FEAT;
    float s = 0.f;
    for (int i = 0; i < FEAT; i++)
        s = fmaf(Wo[(size_t)j * FEAT + i], Wd2[(size_t)i * FEAT + k], s);
    Wop[idx] = s;
}

// ----------------------------- conversions --------------------------------
__global__ void convert_x_kernel(const float* __restrict__ x,
                                 __half* __restrict__ hhi, __half* __restrict__ hhi2)
{
    size_t idx = (size_t)blockIdx.x * blockDim.x + threadIdx.x;
    if (idx >= (size_t)BROWS * KPAD_CAP) return;
    size_t R = idx / KPAD_CAP;
    int f = (int)(idx % KPAD_CAP);
    if (f < FV) {
        hhi[idx] = __float2half_rn(x[R * FV + f]);
    } else {
        hhi[idx]  = __float2half_rn(0.f);
        hhi2[idx] = __float2half_rn(0.f);
    }
}

__global__ void convert_w_kernel(const float* __restrict__ W, int rin, int cin,
                                 __half* __restrict__ hi, int rout, int cout)
{
    int idx = blockIdx.x * blockDim.x + threadIdx.x;
    if (idx >= rout * cout) return;
    int r = idx / cout, c = idx % cout;
    float v = (r < rin && c < cin) ? W[(size_t)r * cin + c] : 0.f;
    hi[idx] = __float2half_rn(v);
}

// ----------------------------- head (fp16 activations, folded Wd2) ---------
__global__ __launch_bounds__(256)
void head_kernel(const __half* __restrict__ T, const float* __restrict__ Wop,
                 const float* __restrict__ bop, float* __restrict__ out)
{
    const int b    = blockIdx.x * 8 + threadIdx.y;
    const int lane = threadIdx.x;
    const __half* a = T + (size_t)b * FEAT;

    float acc[10];
#pragma unroll
    for (int j = 0; j < 10; j++) acc[j] = 0.f;
    for (int kk = lane; kk < FEAT; kk += 32) {
        float av = __half2float(a[kk]);
#pragma unroll
        for (int j = 0; j < 10; j++)
            acc[j] = fmaf(av, Wop[j * FEAT + kk], acc[j]);
    }
#pragma unroll
    for (int j = 0; j < 10; j++)
#pragma unroll
        for (int off = 16; off > 0; off >>= 1)
            acc[j] += __shfl_xor_sync(0xffffffffu, acc[j], off);

    if (lane == 0) {
        float v[10], m = -1e30f;
#pragma unroll
        for (int j = 0; j < 10; j++) { v[j] = acc[j] + bop[j]; m = fmaxf(m, v[j]); }
        float ssum = 0.f;
#pragma unroll
        for (int j = 0; j < 10; j++) { v[j] = expf(v[j] - m); ssum += v[j]; }
        float inv = 1.f / ssum;
#pragma unroll
        for (int j = 0; j < 10; j++) out[(size_t)b * 10 + j] = v[j] * inv;
    }
}

// ---------------------------------------------------------------------------
extern "C" void kernel_launch(void* const* d_in, const int* in_sizes, int n_in,
                              void* d_out, int out_size)
{
    const float* x   = (const float*)d_in[0];
    const float* W1  = (const float*)d_in[1];
    const float* b1  = (const float*)d_in[2];
    const float* W2  = (const float*)d_in[3];
    const float* W3  = (const float*)d_in[5];
    const float* b3  = (const float*)d_in[6];
    const float* Wd1 = (const float*)d_in[7];
    const float* bd1 = (const float*)d_in[8];
    const float* Wd2 = (const float*)d_in[9];
    const float* bd2 = (const float*)d_in[10];
    const float* Wo  = (const float*)d_in[11];
    const float* bo  = (const float*)d_in[12];
    float* out = (float*)d_out;

    cudaFuncSetAttribute(capsule_iter, cudaFuncAttributeMaxDynamicSharedMemorySize, CAP_SMEM);
    cudaFuncSetAttribute(gemm_mma, cudaFuncAttributeMaxDynamicSharedMemorySize, SMEM_BYTES);

    __half *hhi, *hhi2, *gthi, *w3hi, *wd1hi, *dhi, *thi;
    float *g2, *wop, *bop;
    cudaGetSymbolAddress((void**)&hhi, g_hhi);
    cudaGetSymbolAddress((void**)&hhi2, g_hhi2);
    cudaGetSymbolAddress((void**)&g2, g_g2);
    cudaGetSymbolAddress((void**)&gthi, g_gthi);
    cudaGetSymbolAddress((void**)&w3hi, g_w3hi);
    cudaGetSymbolAddress((void**)&wd1hi, g_wd1hi);
    cudaGetSymbolAddress((void**)&wop, g_wop);
    cudaGetSymbolAddress((void**)&bop, g_bop);
    cudaGetSymbolAddress((void**)&dhi, g_dhi);
    cudaGetSymbolAddress((void**)&thi, g_thi);

    // precompute + conversions
    convert_x_kernel<<<(int)(((size_t)BROWS * KPAD_CAP + 255) / 256), 256>>>(x, hhi, hhi2);
    int wcap = NPAD_CAP * KPAD_CAP;
    compute_gt<<<(wcap + 255) / 256, 256>>>(W1, W2, b1, gthi, g2);
    convert_w_kernel<<<(wcap + 255) / 256, 256>>>(W3, FV, FV, w3hi, NPAD_CAP, KPAD_CAP);

    // fused capsule iterations
    for (int it = 0; it < NITER; it++) {
        __half* chi = (it & 1) ? hhi2 : hhi;
        __half* nhi = (it & 1) ? hhi : hhi2;
        int last = (it == NITER - 1);
        capsule_iter<<<BROWS / 128, 512, CAP_SMEM>>>(chi, gthi, w3hi, g2, b3,
                                                     nhi, last ? dhi : nullptr);
    }

    // decoder precompute
    int wdec = FEAT * FEAT;
    convert_w_kernel<<<(wdec + 255) / 256, 256>>>(Wd1, FEAT, FEAT, wd1hi, FEAT, FEAT);
    fold_head<<<(10 * FEAT + 255) / 256, 256>>>(Wo, Wd2, bd2, bo, wop, bop);

    // decoder layer 1 (fp16) + folded head
    const dim3 gdec(7, BATCH / 128);
    gemm_mma<<<gdec, 256, SMEM_BYTES>>>(dhi, FEAT, wd1hi, FEAT, bd1,
                                        thi, FEAT, FEAT, FEAT, 1);
    head_kernel<<<BATCH / 8, dim3(32, 8)>>>(thi, wop, bop, out);
}

// round 12
// speedup vs baseline: 3.6123x; 1.3037x over previous
#include <cuda_runtime.h>
#include <cuda_fp16.h>
#include <math.h>
#include <stdint.h>

#define BATCH 32768
#define FEAT  784
#define FV    196
#define NITER 8
#define BROWS (BATCH * 4)        // 131072 capsule rows

#define KPAD_CAP 208             // capsule K padded (3*64 + 16)
#define NPAD_CAP 224             // capsule N padded (4*56)

// ----------------------------- scratch ------------------------------------
__device__ __align__(256) __half g_hhi [(size_t)BROWS * KPAD_CAP];
__device__ __align__(256) __half g_gthi[NPAD_CAP * KPAD_CAP];
__device__ __align__(256) float  g_g2[KPAD_CAP];                  // pads stay 0
__device__ __align__(256) __half g_w3hi[NPAD_CAP * KPAD_CAP];
__device__ __align__(256) __half g_wd1hi[FEAT * FEAT];
__device__ __align__(256) float  g_wop[10 * FEAT];
__device__ __align__(256) float  g_bop[16];
__device__ __align__(256) __half g_dhi[(size_t)BATCH * FEAT];
__device__ __align__(256) __half g_thi[(size_t)BATCH * FEAT];

// ----------------------------- PTX helpers --------------------------------
__device__ __forceinline__ uint32_t smem_u32(const void* p) {
    uint32_t a;
    asm("{ .reg .u64 t; cvta.to.shared.u64 t, %1; cvt.u32.u64 %0, t; }" : "=r"(a) : "l"(p));
    return a;
}
__device__ __forceinline__ void cp_async16(uint32_t dst, const void* src) {
    asm volatile("cp.async.cg.shared.global [%0], [%1], 16;" :: "r"(dst), "l"(src));
}
__device__ __forceinline__ void ldsm_x4(uint32_t* r, uint32_t addr) {
    asm volatile("ldmatrix.sync.aligned.m8n8.x4.shared.b16 {%0,%1,%2,%3}, [%4];"
                 : "=r"(r[0]), "=r"(r[1]), "=r"(r[2]), "=r"(r[3]) : "r"(addr));
}
__device__ __forceinline__ void ldsm_x2(uint32_t* r, uint32_t addr) {
    asm volatile("ldmatrix.sync.aligned.m8n8.x2.shared.b16 {%0,%1}, [%2];"
                 : "=r"(r[0]), "=r"(r[1]) : "r"(addr));
}
__device__ __forceinline__ void mma16816(float* c, const uint32_t* a, const uint32_t* b) {
    asm volatile("mma.sync.aligned.m16n8k16.row.col.f32.f16.f16.f32 "
                 "{%0,%1,%2,%3}, {%4,%5,%6,%7}, {%8,%9}, {%0,%1,%2,%3};"
                 : "+f"(c[0]), "+f"(c[1]), "+f"(c[2]), "+f"(c[3])
                 : "r"(a[0]), "r"(a[1]), "r"(a[2]), "r"(a[3]), "r"(b[0]), "r"(b[1]));
}
// swizzle for 128B rows, 16B granules
__device__ __forceinline__ uint32_t swz(int r, int g) {
    return (uint32_t)r * 128u + ((uint32_t)(g ^ (r & 7)) << 4);
}
// load 8 halves -> 8 floats (generic pointer)
__device__ __forceinline__ void ld8h(float* f, const __half* p) {
    uint4 q = *(const uint4*)p;
    const __half2* h = reinterpret_cast<const __half2*>(&q);
#pragma unroll
    for (int i = 0; i < 4; i++) {
        float2 a = __half22float2(h[i]);
        f[2*i] = a.x; f[2*i+1] = a.y;
    }
}

// ================== persistent fused capsule (all 8 iterations) ============
// One 512-thread block owns 128 rows (32 batches). A resident in smem for the
// whole kernel; h written back into A smem each iteration (never to DRAM).
// Per iteration: phase1 z = A@Gt^T -> smem; phase2 scores+softmax; phase3
// u = A@W3^T with epilogue h = probs@(u+b3) -> A smem. Last iter -> D global.
#define SMEM_A_OFF 0u
#define A_CHUNK    16384u               // one 64-col chunk of A (swz layout)
#define SMEM_W_OFF 65536u
#define W_STAGE    28672u               // 224 rows x 128B
#define SMEM_Z_OFF 122880u              // 128 x 224 fp16, row stride 448B
#define SMEM_P_OFF 180224u              // 32 batches x 16 floats
#define CAP_SMEM   182272

__global__ __launch_bounds__(512, 1)
void capsule_persist(const __half* __restrict__ A,
                     const __half* __restrict__ Gt,
                     const __half* __restrict__ W3,
                     const float* __restrict__ g2,
                     const float* __restrict__ b3,
                     __half* __restrict__ D)
{
    extern __shared__ char smem[];
    const uint32_t sb = smem_u32(smem);
    const int tid = threadIdx.x;
    const int lane = tid & 31;
    const int wid = tid >> 5;        // 0..15
    const int wm = wid & 3;          // rows wm*32
    const int wn = wid >> 2;         // cols wn*56 (0..3)
    const int m0 = blockIdx.x * 128;

    float acc[2][7][4];

    auto load_w = [&](const __half* Wp, int ch) {
        const uint32_t s = sb + SMEM_W_OFF + (uint32_t)(ch & 1) * W_STAGE;
        if (ch < 3) {
#pragma unroll
            for (int i = 0; i < 4; i++) {          // 224 rows x 8 granules = 1792
                int idx = tid + i * 512;
                if (idx < 1792) {
                    int r = idx >> 3, g = idx & 7;
                    cp_async16(s + swz(r, g), Wp + (size_t)r * KPAD_CAP + (ch << 6) + g * 8);
                }
            }
        } else {
            if (tid < 448) {                       // tail: 224 x 2 granules
                int r = tid >> 1, g = tid & 1;
                cp_async16(s + swz(r, g), Wp + (size_t)r * KPAD_CAP + 192 + g * 8);
            }
        }
        asm volatile("cp.async.commit_group;");
    };

    auto compute_ks = [&](uint32_t sA, uint32_t sW, int ks) {
        uint32_t ah[2][4], bh[7][2];
#pragma unroll
        for (int mf = 0; mf < 2; mf++) {
            int r = wm * 32 + mf * 16 + (lane & 15);
            int g = ks * 2 + (lane >> 4);
            ldsm_x4(ah[mf], sA + swz(r, g));
        }
#pragma unroll
        for (int p = 0; p < 3; p++) {
            int r = wn * 56 + p * 16 + (lane & 7) + ((lane >> 4) & 1) * 8;
            int g = ks * 2 + ((lane >> 3) & 1);
            uint32_t t4[4];
            ldsm_x4(t4, sW + swz(r, g));
            bh[2*p][0] = t4[0]; bh[2*p][1] = t4[1];
            bh[2*p+1][0] = t4[2]; bh[2*p+1][1] = t4[3];
        }
        {
            int l15 = lane & 15;
            int r = wn * 56 + 48 + (l15 & 7);
            int g = ks * 2 + ((l15 >> 3) & 1);
            ldsm_x2(bh[6], sW + swz(r, g));
        }
#pragma unroll
        for (int mf = 0; mf < 2; mf++)
#pragma unroll
            for (int nf = 0; nf < 7; nf++)
                mma16816(acc[mf][nf], ah[mf], bh[nf]);
    };

    auto zero_acc = [&]() {
#pragma unroll
        for (int i = 0; i < 2; i++)
#pragma unroll
            for (int j = 0; j < 7; j++)
#pragma unroll
                for (int v = 0; v < 4; v++) acc[i][j][v] = 0.f;
    };

    // ---- load A once (4 chunks, 26 granules per row) ----
    for (int i = 0; i < 7; i++) {
        int idx = tid + i * 512;
        if (idx < 128 * 26) {
            int r = idx / 26, gg = idx - r * 26;
            int c = gg >> 3, g = gg & 7;
            cp_async16(sb + SMEM_A_OFF + (uint32_t)c * A_CHUNK + swz(r, g),
                       A + (size_t)(m0 + r) * KPAD_CAP + gg * 8);
        }
    }
    asm volatile("cp.async.commit_group;");

    for (int it = 0; it < NITER; it++) {
        const int last = (it == NITER - 1);

        // ============ phase 1: z = A @ Gt^T ============
        zero_acc();
        load_w(Gt, 0);
        for (int ch = 0; ch < 4; ch++) {
            if (ch < 3) { load_w(Gt, ch + 1); asm volatile("cp.async.wait_group 1;"); }
            else        { asm volatile("cp.async.wait_group 0;"); }
            __syncthreads();
            const uint32_t sA = sb + SMEM_A_OFF + (uint32_t)ch * A_CHUNK;
            const uint32_t sW = sb + SMEM_W_OFF + (uint32_t)(ch & 1) * W_STAGE;
            if (ch < 3) {
#pragma unroll
                for (int ks = 0; ks < 4; ks++) compute_ks(sA, sW, ks);
            } else compute_ks(sA, sW, 0);
            __syncthreads();
        }

        // z -> smem (fp16). Gt pad rows zero -> z pads zero.
#pragma unroll
        for (int mf = 0; mf < 2; mf++)
#pragma unroll
        for (int nf = 0; nf < 7; nf++)
#pragma unroll
        for (int hf = 0; hf < 2; hf++) {
            int row = wm * 32 + mf * 16 + hf * 8 + (lane >> 2);
            int col = wn * 56 + nf * 8 + ((lane & 3) << 1);
            __half2 hv = __floats2half2_rn(acc[mf][nf][hf * 2], acc[mf][nf][hf * 2 + 1]);
            *(__half2*)(smem + SMEM_Z_OFF + (uint32_t)row * 448u + (uint32_t)col * 2u) = hv;
        }
        __syncthreads();

        // prefetch W3 chunk 0 while scores compute
        load_w(W3, 0);

        // ============ phase 2: scores + softmax ============
#pragma unroll
        for (int bi = 0; bi < 2; bi++) {
            int bb = wid * 2 + bi;
            float s[4][4], beta[4];
#pragma unroll
            for (int t = 0; t < 4; t++) {
                beta[t] = 0.f;
#pragma unroll
                for (int r = 0; r < 4; r++) s[t][r] = 0.f;
            }
            if (lane < 26) {
                float zf[4][8], vf[4][8], gf[8];
                int c = lane >> 3, g = lane & 7;
#pragma unroll
                for (int t = 0; t < 4; t++) {
                    int row = bb * 4 + t;
                    ld8h(zf[t], (const __half*)(smem + SMEM_Z_OFF + (uint32_t)row * 448u + (uint32_t)lane * 16u));
                    ld8h(vf[t], (const __half*)(smem + SMEM_A_OFF + (uint32_t)c * A_CHUNK + swz(row, g)));
                }
                float4 ga = *(const float4*)(g2 + lane * 8);
                float4 gb = *(const float4*)(g2 + lane * 8 + 4);
                gf[0]=ga.x; gf[1]=ga.y; gf[2]=ga.z; gf[3]=ga.w;
                gf[4]=gb.x; gf[5]=gb.y; gf[6]=gb.z; gf[7]=gb.w;
#pragma unroll
                for (int t = 0; t < 4; t++) {
#pragma unroll
                    for (int e = 0; e < 8; e++)
                        beta[t] = fmaf(vf[t][e], gf[e], beta[t]);
#pragma unroll
                    for (int r = 0; r < 4; r++) {
                        float a2 = 0.f;
#pragma unroll
                        for (int e = 0; e < 8; e++)
                            a2 = fmaf(zf[t][e], vf[r][e], a2);
                        s[t][r] = a2;
                    }
                }
            }
#pragma unroll
            for (int t = 0; t < 4; t++) {
#pragma unroll
                for (int off = 16; off > 0; off >>= 1)
                    beta[t] += __shfl_xor_sync(0xffffffffu, beta[t], off);
#pragma unroll
                for (int r = 0; r < 4; r++)
#pragma unroll
                    for (int off = 16; off > 0; off >>= 1)
                        s[t][r] += __shfl_xor_sync(0xffffffffu, s[t][r], off);
            }
            if (lane < 16) {
                int t = lane >> 2;
                float sc[4];
#pragma unroll
                for (int r = 0; r < 4; r++) sc[r] = s[t][r] + beta[r];
                float m = fmaxf(fmaxf(sc[0], sc[1]), fmaxf(sc[2], sc[3]));
                float e0 = expf(sc[0] - m), e1 = expf(sc[1] - m);
                float e2 = expf(sc[2] - m), e3 = expf(sc[3] - m);
                float inv = 1.f / (e0 + e1 + e2 + e3);
                float pe = (lane & 3) == 0 ? e0 : (lane & 3) == 1 ? e1 : (lane & 3) == 2 ? e2 : e3;
                *(float*)(smem + SMEM_P_OFF + (uint32_t)bb * 64u + (uint32_t)lane * 4u) = pe * inv;
            }
        }

        // ============ phase 3: u GEMM + attention mix ============
        zero_acc();
        for (int ch = 0; ch < 4; ch++) {
            if (ch < 3) { load_w(W3, ch + 1); asm volatile("cp.async.wait_group 1;"); }
            else        { asm volatile("cp.async.wait_group 0;"); }
            __syncthreads();   // also makes probs smem visible on first pass
            const uint32_t sA = sb + SMEM_A_OFF + (uint32_t)ch * A_CHUNK;
            const uint32_t sW = sb + SMEM_W_OFF + (uint32_t)(ch & 1) * W_STAGE;
            if (ch < 3) {
#pragma unroll
                for (int ks = 0; ks < 4; ks++) compute_ks(sA, sW, ks);
            } else compute_ks(sA, sW, 0);
            __syncthreads();   // all warps done reading A before h overwrite
        }

        // epilogue: h[t] = sum_s p[t][s] * (u[s] + b3) -> A smem (and D last)
#pragma unroll
        for (int mf = 0; mf < 2; mf++)
#pragma unroll
        for (int hf = 0; hf < 2; hf++) {
            int br = wm * 32 + mf * 16 + hf * 8 + (lane >> 2);
            int bb = br >> 2, t = br & 3;
            float4 pv = *(const float4*)(smem + SMEM_P_OFF + (uint32_t)bb * 64u + (uint32_t)t * 16u);
            int base = (lane >> 2) & 4;
#pragma unroll
            for (int nf = 0; nf < 7; nf++) {
                int c0 = wn * 56 + nf * 8 + ((lane & 3) << 1);
                float hpair[2];
#pragma unroll
                for (int e = 0; e < 2; e++) {
                    float uv = acc[mf][nf][hf * 2 + e] + ((c0 + e < FV) ? b3[c0 + e] : 0.f);
                    float h = 0.f;
#pragma unroll
                    for (int s2 = 0; s2 < 4; s2++) {
                        float us = __shfl_sync(0xffffffffu, uv, ((base + s2) << 2) | (lane & 3));
                        float ps = (s2 == 0) ? pv.x : (s2 == 1) ? pv.y : (s2 == 2) ? pv.z : pv.w;
                        h = fmaf(ps, us, h);
                    }
                    hpair[e] = h;
                }
                if (c0 < FV) {
                    __half2 hv = __floats2half2_rn(hpair[0], hpair[1]);
                    if (last) {
                        *(__half2*)(D + (size_t)((m0 + br) >> 2) * FEAT + t * FV + c0) = hv;
                    } else {
                        int chk = c0 >> 6, cc = c0 & 63;
                        *(__half2*)(smem + SMEM_A_OFF + (uint32_t)chk * A_CHUNK
                                    + swz(br, cc >> 3) + (uint32_t)(cc & 7) * 2u) = hv;
                    }
                }
            }
        }
        if (!last) __syncthreads();
    }
}

// ----------------------- decoder GEMM (fp16 mma.sync, 2-stage) -------------
#define OFF_W 16384u
#define STAGE_BYTES 30720u
#define SMEM_BYTES 61440

__global__ __launch_bounds__(256, 2)
void gemm_mma(const __half* __restrict__ A, int lda,
              const __half* __restrict__ W, int ldw,
              const float* __restrict__ bias,
              __half* __restrict__ Ch, int ldc, int K, int n_real, int relu)
{
    extern __shared__ char smem[];
    const uint32_t sb = smem_u32(smem);
    const int tid = threadIdx.x;
    const int lane = tid & 31;
    const int wid = tid >> 5;
    const int wm = wid & 3;
    const int wn = wid >> 2;
    const int m0 = blockIdx.y * 128;
    const int n0 = blockIdx.x * 112;
    const int nfull = K >> 6;
    const int nch = nfull + 1;

    float acc[2][7][4];
#pragma unroll
    for (int i = 0; i < 2; i++)
#pragma unroll
        for (int j = 0; j < 7; j++)
#pragma unroll
            for (int v = 0; v < 4; v++) acc[i][j][v] = 0.f;

    auto load_full = [&](int ch) {
        const uint32_t s = sb + (uint32_t)(ch & 1) * STAGE_BYTES;
        const int kc = ch << 6;
#pragma unroll
        for (int i = 0; i < 4; i++) {
            int idx = tid + i * 256;
            int r = idx >> 3, g = idx & 7;
            cp_async16(s + swz(r, g), A + (size_t)(m0 + r) * lda + kc + g * 8);
        }
#pragma unroll
        for (int i = 0; i < 3; i++) {
            int idx = tid + i * 256;
            int r = idx >> 3, g = idx & 7;
            cp_async16(s + OFF_W + swz(r, g), W + (size_t)(n0 + r) * ldw + kc + g * 8);
        }
        {
            int idx = tid + 768;
            if (idx < 896) {
                int r = idx >> 3, g = idx & 7;
                cp_async16(s + OFF_W + swz(r, g), W + (size_t)(n0 + r) * ldw + kc + g * 8);
            }
        }
        asm volatile("cp.async.commit_group;");
    };
    auto load_tail = [&](int ch) {
        const uint32_t s = sb + (uint32_t)(ch & 1) * STAGE_BYTES;
        const int kc = ch << 6;
        {
            int r = tid >> 1, g = tid & 1;
            cp_async16(s + swz(r, g), A + (size_t)(m0 + r) * lda + kc + g * 8);
        }
        if (tid < 224) {
            int r = tid >> 1, g = tid & 1;
            cp_async16(s + OFF_W + swz(r, g), W + (size_t)(n0 + r) * ldw + kc + g * 8);
        }
        asm volatile("cp.async.commit_group;");
    };
    auto compute_ks = [&](uint32_t s, int ks) {
        uint32_t ah[2][4], bh[7][2];
        const uint32_t sw = s + OFF_W;
#pragma unroll
        for (int mf = 0; mf < 2; mf++) {
            int r = wm * 32 + mf * 16 + (lane & 15);
            int g = ks * 2 + (lane >> 4);
            ldsm_x4(ah[mf], s + swz(r, g));
        }
#pragma unroll
        for (int p = 0; p < 3; p++) {
            int r = wn * 56 + p * 16 + (lane & 7) + ((lane >> 4) & 1) * 8;
            int g = ks * 2 + ((lane >> 3) & 1);
            uint32_t t4[4];
            ldsm_x4(t4, sw + swz(r, g));
            bh[2*p][0] = t4[0]; bh[2*p][1] = t4[1];
            bh[2*p+1][0] = t4[2]; bh[2*p+1][1] = t4[3];
        }
        {
            int l15 = lane & 15;
            int r = wn * 56 + 48 + (l15 & 7);
            int g = ks * 2 + ((l15 >> 3) & 1);
            ldsm_x2(bh[6], sw + swz(r, g));
        }
#pragma unroll
        for (int mf = 0; mf < 2; mf++)
#pragma unroll
            for (int nf = 0; nf < 7; nf++)
                mma16816(acc[mf][nf], ah[mf], bh[nf]);
    };

    if (nfull > 0) load_full(0); else load_tail(0);
    for (int ch = 0; ch < nch; ch++) {
        if (ch + 1 < nch) {
            if (ch + 1 < nfull) load_full(ch + 1); else load_tail(ch + 1);
            asm volatile("cp.async.wait_group 1;");
        } else {
            asm volatile("cp.async.wait_group 0;");
        }
        __syncthreads();
        const uint32_t s = sb + (uint32_t)(ch & 1) * STAGE_BYTES;
        if (ch < nfull) {
#pragma unroll
            for (int ks = 0; ks < 4; ks++) compute_ks(s, ks);
        } else {
            compute_ks(s, 0);
        }
        if (ch + 1 < nch) __syncthreads();
    }

#pragma unroll
    for (int mf = 0; mf < 2; mf++)
#pragma unroll
    for (int nf = 0; nf < 7; nf++) {
        int r = m0 + wm * 32 + mf * 16 + (lane >> 2);
        int c = n0 + wn * 56 + nf * 8 + ((lane & 3) << 1);
#pragma unroll
        for (int hf = 0; hf < 2; hf++) {
            int rr = r + hf * 8;
#pragma unroll
            for (int e = 0; e < 2; e++) {
                int cc = c + e;
                if (cc >= n_real) continue;
                float v = acc[mf][nf][hf * 2 + e] + bias[cc];
                if (relu) v = fmaxf(v, 0.f);
                Ch[(size_t)rr * ldc + cc] = __float2half_rn(v);
            }
        }
    }
}

// ----------------------------- precompute ----------------------------------
__global__ void compute_gt(const float* __restrict__ W1, const float* __restrict__ W2,
                           const float* __restrict__ b1,
                           __half* __restrict__ gthi, float* __restrict__ g2)
{
    int idx = blockIdx.x * blockDim.x + threadIdx.x;
    if (idx < KPAD_CAP) {
        float s = 0.f;
        if (idx < FV)
            for (int j = 0; j < FV; j++) s = fmaf(b1[j], W2[(size_t)j * FV + idx], s);
        g2[idx] = s;
    }
    if (idx >= NPAD_CAP * KPAD_CAP) return;
    int n = idx / KPAD_CAP, k = idx % KPAD_CAP;
    float s = 0.f;
    if (n < FV && k < FV) {
        for (int j = 0; j < FV; j++)
            s = fmaf(W1[(size_t)j * FV + k], W2[(size_t)j * FV + n], s);
    }
    gthi[idx] = __float2half_rn(s);
}

__global__ void fold_head(const float* __restrict__ Wo, const float* __restrict__ Wd2,
                          const float* __restrict__ bd2, const float* __restrict__ bo,
                          float* __restrict__ Wop, float* __restrict__ bop)
{
    int idx = blockIdx.x * blockDim.x + threadIdx.x;
    if (idx < 10) {
        float s = bo[idx];
        for (int i = 0; i < FEAT; i++) s = fmaf(Wo[(size_t)idx * FEAT + i], bd2[i], s);
        bop[idx] = s;
    }
    if (idx >= 10 * FEAT) return;
    int j = idx / FEAT, k = idx % FEAT;
    float s = 0.f;
    for (int i = 0; i < FEAT; i++)
        s = fmaf(Wo[(size_t)j * FEAT + i], Wd2[(size_t)i * FEAT + k], s);
    Wop[idx] = s;
}

// ----------------------------- conversions --------------------------------
__global__ void convert_x_kernel(const float* __restrict__ x,
                                 __half* __restrict__ hhi)
{
    size_t idx = (size_t)blockIdx.x * blockDim.x + threadIdx.x;
    if (idx >= (size_t)BROWS * KPAD_CAP) return;
    size_t R = idx / KPAD_CAP;
    int f = (int)(idx % KPAD_CAP);
    hhi[idx] = __float2half_rn((f < FV) ? x[R * FV + f] : 0.f);
}

__global__ void convert_w_kernel(const float* __restrict__ W, int rin, int cin,
                                 __half* __restrict__ hi, int rout, int cout)
{
    int idx = blockIdx.x * blockDim.x + threadIdx.x;
    if (idx >= rout * cout) return;
    int r = idx / cout, c = idx % cout;
    float v = (r < rin && c < cin) ? W[(size_t)r * cin + c] : 0.f;
    hi[idx] = __float2half_rn(v);
}

// ----------------------------- head (fp16 activations, folded Wd2) ---------
__global__ __launch_bounds__(256)
void head_kernel(const __half* __restrict__ T, const float* __restrict__ Wop,
                 const float* __restrict__ bop, float* __restrict__ out)
{
    const int b    = blockIdx.x * 8 + threadIdx.y;
    const int lane = threadIdx.x;
    const __half* a = T + (size_t)b * FEAT;

    float acc[10];
#pragma unroll
    for (int j = 0; j < 10; j++) acc[j] = 0.f;
    for (int kk = lane; kk < FEAT; kk += 32) {
        float av = __half2float(a[kk]);
#pragma unroll
        for (int j = 0; j < 10; j++)
            acc[j] = fmaf(av, Wop[j * FEAT + kk], acc[j]);
    }
#pragma unroll
    for (int j = 0; j < 10; j++)
#pragma unroll
        for (int off = 16; off > 0; off >>= 1)
            acc[j] += __shfl_xor_sync(0xffffffffu, acc[j], off);

    if (lane == 0) {
        float v[10], m = -1e30f;
#pragma unroll
        for (int j = 0; j < 10; j++) { v[j] = acc[j] + bop[j]; m = fmaxf(m, v[j]); }
        float ssum = 0.f;
#pragma unroll
        for (int j = 0; j < 10; j++) { v[j] = expf(v[j] - m); ssum += v[j]; }
        float inv = 1.f / ssum;
#pragma unroll
        for (int j = 0; j < 10; j++) out[(size_t)b * 10 + j] = v[j] * inv;
    }
}

// ---------------------------------------------------------------------------
extern "C" void kernel_launch(void* const* d_in, const int* in_sizes, int n_in,
                              void* d_out, int out_size)
{
    const float* x   = (const float*)d_in[0];
    const float* W1  = (const float*)d_in[1];
    const float* b1  = (const float*)d_in[2];
    const float* W2  = (const float*)d_in[3];
    const float* W3  = (const float*)d_in[5];
    const float* b3  = (const float*)d_in[6];
    const float* Wd1 = (const float*)d_in[7];
    const float* bd1 = (const float*)d_in[8];
    const float* Wd2 = (const float*)d_in[9];
    const float* bd2 = (const float*)d_in[10];
    const float* Wo  = (const float*)d_in[11];
    const float* bo  = (const float*)d_in[12];
    float* out = (float*)d_out;

    cudaFuncSetAttribute(capsule_persist, cudaFuncAttributeMaxDynamicSharedMemorySize, CAP_SMEM);
    cudaFuncSetAttribute(gemm_mma, cudaFuncAttributeMaxDynamicSharedMemorySize, SMEM_BYTES);

    __half *hhi, *gthi, *w3hi, *wd1hi, *dhi, *thi;
    float *g2, *wop, *bop;
    cudaGetSymbolAddress((void**)&hhi, g_hhi);
    cudaGetSymbolAddress((void**)&g2, g_g2);
    cudaGetSymbolAddress((void**)&gthi, g_gthi);
    cudaGetSymbolAddress((void**)&w3hi, g_w3hi);
    cudaGetSymbolAddress((void**)&wd1hi, g_wd1hi);
    cudaGetSymbolAddress((void**)&wop, g_wop);
    cudaGetSymbolAddress((void**)&bop, g_bop);
    cudaGetSymbolAddress((void**)&dhi, g_dhi);
    cudaGetSymbolAddress((void**)&thi, g_thi);

    // precompute + conversions
    convert_x_kernel<<<(int)(((size_t)BROWS * KPAD_CAP + 255) / 256), 256>>>(x, hhi);
    int wcap = NPAD_CAP * KPAD_CAP;
    compute_gt<<<(wcap + 255) / 256, 256>>>(W1, W2, b1, gthi, g2);
    convert_w_kernel<<<(wcap + 255) / 256, 256>>>(W3, FV, FV, w3hi, NPAD_CAP, KPAD_CAP);

    // all 8 capsule iterations in ONE launch, h resident in smem
    capsule_persist<<<BROWS / 128, 512, CAP_SMEM>>>(hhi, gthi, w3hi, g2, b3, dhi);

    // decoder precompute
    int wdec = FEAT * FEAT;
    convert_w_kernel<<<(wdec + 255) / 256, 256>>>(Wd1, FEAT, FEAT, wd1hi, FEAT, FEAT);
    fold_head<<<(10 * FEAT + 255) / 256, 256>>>(Wo, Wd2, bd2, bo, wop, bop);

    // decoder layer 1 (fp16) + folded head
    const dim3 gdec(7, BATCH / 128);
    gemm_mma<<<gdec, 256, SMEM_BYTES>>>(dhi, FEAT, wd1hi, FEAT, bd1,
                                        thi, FEAT, FEAT, FEAT, 1);
    head_kernel<<<BATCH / 8, dim3(32, 8)>>>(thi, wop, bop, out);
}

// round 13
// speedup vs baseline: 3.8339x; 1.0613x over previous
#include <cuda_runtime.h>
#include <cuda_fp16.h>
#include <math.h>
#include <stdint.h>

#define BATCH 32768
#define FEAT  784
#define FV    196
#define NITER 8
#define BROWS (BATCH * 4)        // 131072 capsule rows

#define KPAD_CAP 208             // capsule K padded (3*64 + 16)
#define NPAD_CAP 224             // capsule N padded (4*56)

// ----------------------------- scratch ------------------------------------
__device__ __align__(256) __half g_hhi [(size_t)BROWS * KPAD_CAP];
__device__ __align__(256) __half g_gthi[NPAD_CAP * KPAD_CAP];
__device__ __align__(256) float  g_g2[KPAD_CAP];                  // pads stay 0
__device__ __align__(256) __half g_w3hi[NPAD_CAP * KPAD_CAP];
__device__ __align__(256) __half g_wd1hi[FEAT * FEAT];
__device__ __align__(256) float  g_wop[10 * FEAT];
__device__ __align__(256) float  g_bop[16];
__device__ __align__(256) __half g_dhi[(size_t)BATCH * FEAT];
__device__ __align__(256) __half g_thi[(size_t)BATCH * FEAT];

// ----------------------------- PTX helpers --------------------------------
__device__ __forceinline__ uint32_t smem_u32(const void* p) {
    uint32_t a;
    asm("{ .reg .u64 t; cvta.to.shared.u64 t, %1; cvt.u32.u64 %0, t; }" : "=r"(a) : "l"(p));
    return a;
}
__device__ __forceinline__ void cp_async16(uint32_t dst, const void* src) {
    asm volatile("cp.async.cg.shared.global [%0], [%1], 16;" :: "r"(dst), "l"(src));
}
__device__ __forceinline__ void ldsm_x4(uint32_t* r, uint32_t addr) {
    asm volatile("ldmatrix.sync.aligned.m8n8.x4.shared.b16 {%0,%1,%2,%3}, [%4];"
                 : "=r"(r[0]), "=r"(r[1]), "=r"(r[2]), "=r"(r[3]) : "r"(addr));
}
__device__ __forceinline__ void ldsm_x2(uint32_t* r, uint32_t addr) {
    asm volatile("ldmatrix.sync.aligned.m8n8.x2.shared.b16 {%0,%1}, [%2];"
                 : "=r"(r[0]), "=r"(r[1]) : "r"(addr));
}
__device__ __forceinline__ void mma16816(float* c, const uint32_t* a, const uint32_t* b) {
    asm volatile("mma.sync.aligned.m16n8k16.row.col.f32.f16.f16.f32 "
                 "{%0,%1,%2,%3}, {%4,%5,%6,%7}, {%8,%9}, {%0,%1,%2,%3};"
                 : "+f"(c[0]), "+f"(c[1]), "+f"(c[2]), "+f"(c[3])
                 : "r"(a[0]), "r"(a[1]), "r"(a[2]), "r"(a[3]), "r"(b[0]), "r"(b[1]));
}
// swizzle for 128B rows, 16B granules
__device__ __forceinline__ uint32_t swz(int r, int g) {
    return (uint32_t)r * 128u + ((uint32_t)(g ^ (r & 7)) << 4);
}
// load 8 halves -> 8 floats (generic pointer)
__device__ __forceinline__ void ld8h(float* f, const __half* p) {
    uint4 q = *(const uint4*)p;
    const __half2* h = reinterpret_cast<const __half2*>(&q);
#pragma unroll
    for (int i = 0; i < 4; i++) {
        float2 a = __half22float2(h[i]);
        f[2*i] = a.x; f[2*i+1] = a.y;
    }
}

// ================== persistent fused capsule (all 8 iterations) ============
// One 512-thread block owns 128 rows (32 batches).
// Resident in smem: A (h state, updated in place), full Gt.
// Per iteration: phase1 z = A@Gt^T (NO syncs, all resident) -> z smem;
// phase2 scores+softmax; phase3 u = A@W3^T with W3 streamed through the
// (dead) z region; epilogue h = probs@(u+b3) -> A smem. Last iter -> D.
#define SMEM_A_OFF 0u
#define A_CHUNK    16384u               // one 64-col chunk of A (swz layout)
#define GT_OFF     65536u
#define W_CHUNK    28672u               // 224 rows x 128B
#define GT_TAIL    (GT_OFF + 3u * W_CHUNK)          // 151552, 224 x 32B
#define SMEM_Z_OFF 158720u              // 128 x 224 fp16, row stride 448B
#define W_STAGE    28672u               // W3 stages alias the z region
#define SMEM_P_OFF 216064u              // 32 batches x 16 floats
#define CAP_SMEM   218112

__global__ __launch_bounds__(512, 1)
void capsule_persist(const __half* __restrict__ A,
                     const __half* __restrict__ Gt,
                     const __half* __restrict__ W3,
                     const float* __restrict__ g2,
                     const float* __restrict__ b3,
                     __half* __restrict__ D)
{
    extern __shared__ char smem[];
    const uint32_t sb = smem_u32(smem);
    const int tid = threadIdx.x;
    const int lane = tid & 31;
    const int wid = tid >> 5;        // 0..15
    const int wm = wid & 3;          // rows wm*32
    const int wn = wid >> 2;         // cols wn*56 (0..3)
    const int m0 = blockIdx.x * 128;

    float acc[2][7][4];

    // stream W3 chunk ch into z-region stage (ch&1)
    auto load_w3 = [&](int ch) {
        const uint32_t s = sb + SMEM_Z_OFF + (uint32_t)(ch & 1) * W_STAGE;
        if (ch < 3) {
#pragma unroll
            for (int i = 0; i < 4; i++) {          // 224 rows x 8 granules = 1792
                int idx = tid + i * 512;
                if (idx < 1792) {
                    int r = idx >> 3, g = idx & 7;
                    cp_async16(s + swz(r, g), W3 + (size_t)r * KPAD_CAP + (ch << 6) + g * 8);
                }
            }
        } else {
            if (tid < 448) {                       // tail: 224 x 2 granules
                int r = tid >> 1, g = tid & 1;
                cp_async16(s + swz(r, g), W3 + (size_t)r * KPAD_CAP + 192 + g * 8);
            }
        }
        asm volatile("cp.async.commit_group;");
    };

    // one 16-col k-step; both operands in swizzled layouts
    auto compute_ks = [&](uint32_t sA, uint32_t sW, int ks) {
        uint32_t ah[2][4], bh[7][2];
#pragma unroll
        for (int mf = 0; mf < 2; mf++) {
            int r = wm * 32 + mf * 16 + (lane & 15);
            int g = ks * 2 + (lane >> 4);
            ldsm_x4(ah[mf], sA + swz(r, g));
        }
#pragma unroll
        for (int p = 0; p < 3; p++) {
            int r = wn * 56 + p * 16 + (lane & 7) + ((lane >> 4) & 1) * 8;
            int g = ks * 2 + ((lane >> 3) & 1);
            uint32_t t4[4];
            ldsm_x4(t4, sW + swz(r, g));
            bh[2*p][0] = t4[0]; bh[2*p][1] = t4[1];
            bh[2*p+1][0] = t4[2]; bh[2*p+1][1] = t4[3];
        }
        {
            int l15 = lane & 15;
            int r = wn * 56 + 48 + (l15 & 7);
            int g = ks * 2 + ((l15 >> 3) & 1);
            ldsm_x2(bh[6], sW + swz(r, g));
        }
#pragma unroll
        for (int mf = 0; mf < 2; mf++)
#pragma unroll
            for (int nf = 0; nf < 7; nf++)
                mma16816(acc[mf][nf], ah[mf], bh[nf]);
    };

    // tail k-step against the compact Gt tail (32B row stride, no swizzle)
    auto compute_tail_gt = [&]() {
        uint32_t ah[2][4], bh[7][2];
        const uint32_t sA = sb + SMEM_A_OFF + 3u * A_CHUNK;
        const uint32_t sT = sb + GT_TAIL;
#pragma unroll
        for (int mf = 0; mf < 2; mf++) {
            int r = wm * 32 + mf * 16 + (lane & 15);
            int g = (lane >> 4);
            ldsm_x4(ah[mf], sA + swz(r, g));
        }
#pragma unroll
        for (int p = 0; p < 3; p++) {
            int r = wn * 56 + p * 16 + (lane & 7) + ((lane >> 4) & 1) * 8;
            int g = ((lane >> 3) & 1);
            uint32_t t4[4];
            ldsm_x4(t4, sT + (uint32_t)r * 32u + (uint32_t)g * 16u);
            bh[2*p][0] = t4[0]; bh[2*p][1] = t4[1];
            bh[2*p+1][0] = t4[2]; bh[2*p+1][1] = t4[3];
        }
        {
            int l15 = lane & 15;
            int r = wn * 56 + 48 + (l15 & 7);
            int g = ((l15 >> 3) & 1);
            ldsm_x2(bh[6], sT + (uint32_t)r * 32u + (uint32_t)g * 16u);
        }
#pragma unroll
        for (int mf = 0; mf < 2; mf++)
#pragma unroll
            for (int nf = 0; nf < 7; nf++)
                mma16816(acc[mf][nf], ah[mf], bh[nf]);
    };

    auto zero_acc = [&]() {
#pragma unroll
        for (int i = 0; i < 2; i++)
#pragma unroll
            for (int j = 0; j < 7; j++)
#pragma unroll
                for (int v = 0; v < 4; v++) acc[i][j][v] = 0.f;
    };

    // ---- one-time loads: A (128 x 26 granules) + Gt resident (224 x 26) ----
    for (int i = 0; i < 7; i++) {
        int idx = tid + i * 512;
        if (idx < 128 * 26) {
            int r = idx / 26, gg = idx - r * 26;
            int c = gg >> 3, g = gg & 7;
            cp_async16(sb + SMEM_A_OFF + (uint32_t)c * A_CHUNK + swz(r, g),
                       A + (size_t)(m0 + r) * KPAD_CAP + gg * 8);
        }
    }
    for (int i = 0; i < 12; i++) {
        int idx = tid + i * 512;
        if (idx < 224 * 26) {
            int r = idx / 26, gg = idx - r * 26;
            uint32_t dst;
            if (gg < 24) dst = sb + GT_OFF + (uint32_t)(gg >> 3) * W_CHUNK + swz(r, gg & 7);
            else         dst = sb + GT_TAIL + (uint32_t)r * 32u + (uint32_t)(gg - 24) * 16u;
            cp_async16(dst, Gt + (size_t)r * KPAD_CAP + gg * 8);
        }
    }
    asm volatile("cp.async.commit_group;");
    asm volatile("cp.async.wait_group 0;");
    __syncthreads();

    for (int it = 0; it < NITER; it++) {
        const int last = (it == NITER - 1);

        // ============ phase 1: z = A @ Gt^T (all resident, NO syncs) ======
        zero_acc();
#pragma unroll
        for (int ch = 0; ch < 3; ch++)
#pragma unroll
            for (int ks = 0; ks < 4; ks++)
                compute_ks(sb + SMEM_A_OFF + (uint32_t)ch * A_CHUNK,
                           sb + GT_OFF + (uint32_t)ch * W_CHUNK, ks);
        compute_tail_gt();

        // z -> smem (fp16). Gt pad rows zero -> z pads zero.
#pragma unroll
        for (int mf = 0; mf < 2; mf++)
#pragma unroll
        for (int nf = 0; nf < 7; nf++)
#pragma unroll
        for (int hf = 0; hf < 2; hf++) {
            int row = wm * 32 + mf * 16 + hf * 8 + (lane >> 2);
            int col = wn * 56 + nf * 8 + ((lane & 3) << 1);
            __half2 hv = __floats2half2_rn(acc[mf][nf][hf * 2], acc[mf][nf][hf * 2 + 1]);
            *(__half2*)(smem + SMEM_Z_OFF + (uint32_t)row * 448u + (uint32_t)col * 2u) = hv;
        }
        __syncthreads();

        // ============ phase 2: scores + softmax ============
#pragma unroll
        for (int bi = 0; bi < 2; bi++) {
            int bb = wid * 2 + bi;
            float s[4][4], beta[4];
#pragma unroll
            for (int t = 0; t < 4; t++) {
                beta[t] = 0.f;
#pragma unroll
                for (int r = 0; r < 4; r++) s[t][r] = 0.f;
            }
            if (lane < 26) {
                float zf[4][8], vf[4][8], gf[8];
                int c = lane >> 3, g = lane & 7;
#pragma unroll
                for (int t = 0; t < 4; t++) {
                    int row = bb * 4 + t;
                    ld8h(zf[t], (const __half*)(smem + SMEM_Z_OFF + (uint32_t)row * 448u + (uint32_t)lane * 16u));
                    ld8h(vf[t], (const __half*)(smem + SMEM_A_OFF + (uint32_t)c * A_CHUNK + swz(row, g)));
                }
                float4 ga = *(const float4*)(g2 + lane * 8);
                float4 gb = *(const float4*)(g2 + lane * 8 + 4);
                gf[0]=ga.x; gf[1]=ga.y; gf[2]=ga.z; gf[3]=ga.w;
                gf[4]=gb.x; gf[5]=gb.y; gf[6]=gb.z; gf[7]=gb.w;
#pragma unroll
                for (int t = 0; t < 4; t++) {
#pragma unroll
                    for (int e = 0; e < 8; e++)
                        beta[t] = fmaf(vf[t][e], gf[e], beta[t]);
#pragma unroll
                    for (int r = 0; r < 4; r++) {
                        float a2 = 0.f;
#pragma unroll
                        for (int e = 0; e < 8; e++)
                            a2 = fmaf(zf[t][e], vf[r][e], a2);
                        s[t][r] = a2;
                    }
                }
            }
#pragma unroll
            for (int t = 0; t < 4; t++) {
#pragma unroll
                for (int off = 16; off > 0; off >>= 1)
                    beta[t] += __shfl_xor_sync(0xffffffffu, beta[t], off);
#pragma unroll
                for (int r = 0; r < 4; r++)
#pragma unroll
                    for (int off = 16; off > 0; off >>= 1)
                        s[t][r] += __shfl_xor_sync(0xffffffffu, s[t][r], off);
            }
            if (lane < 16) {
                int t = lane >> 2;
                float sc[4];
#pragma unroll
                for (int r = 0; r < 4; r++) sc[r] = s[t][r] + beta[r];
                float m = fmaxf(fmaxf(sc[0], sc[1]), fmaxf(sc[2], sc[3]));
                float e0 = expf(sc[0] - m), e1 = expf(sc[1] - m);
                float e2 = expf(sc[2] - m), e3 = expf(sc[3] - m);
                float inv = 1.f / (e0 + e1 + e2 + e3);
                float pe = (lane & 3) == 0 ? e0 : (lane & 3) == 1 ? e1 : (lane & 3) == 2 ? e2 : e3;
                *(float*)(smem + SMEM_P_OFF + (uint32_t)bb * 64u + (uint32_t)lane * 4u) = pe * inv;
            }
        }
        __syncthreads();   // all warps done with z (and probs visible)

        // ============ phase 3: u = A @ W3^T (W3 streamed via z region) ====
        zero_acc();
        load_w3(0);
        for (int ch = 0; ch < 4; ch++) {
            if (ch < 3) { load_w3(ch + 1); asm volatile("cp.async.wait_group 1;"); }
            else        { asm volatile("cp.async.wait_group 0;"); }
            __syncthreads();
            const uint32_t sA = sb + SMEM_A_OFF + (uint32_t)ch * A_CHUNK;
            const uint32_t sW = sb + SMEM_Z_OFF + (uint32_t)(ch & 1) * W_STAGE;
            if (ch < 3) {
#pragma unroll
                for (int ks = 0; ks < 4; ks++) compute_ks(sA, sW, ks);
            } else compute_ks(sA, sW, 0);
            __syncthreads();   // stage reuse + (last chunk) A-read completion
        }

        // epilogue: h[t] = sum_s p[t][s] * (u[s] + b3) -> A smem (or D last)
#pragma unroll
        for (int mf = 0; mf < 2; mf++)
#pragma unroll
        for (int hf = 0; hf < 2; hf++) {
            int br = wm * 32 + mf * 16 + hf * 8 + (lane >> 2);
            int bb = br >> 2, t = br & 3;
            float4 pv = *(const float4*)(smem + SMEM_P_OFF + (uint32_t)bb * 64u + (uint32_t)t * 16u);
            int base = (lane >> 2) & 4;
#pragma unroll
            for (int nf = 0; nf < 7; nf++) {
                int c0 = wn * 56 + nf * 8 + ((lane & 3) << 1);
                float hpair[2];
#pragma unroll
                for (int e = 0; e < 2; e++) {
                    float uv = acc[mf][nf][hf * 2 + e] + ((c0 + e < FV) ? b3[c0 + e] : 0.f);
                    float h = 0.f;
#pragma unroll
                    for (int s2 = 0; s2 < 4; s2++) {
                        float us = __shfl_sync(0xffffffffu, uv, ((base + s2) << 2) | (lane & 3));
                        float ps = (s2 == 0) ? pv.x : (s2 == 1) ? pv.y : (s2 == 2) ? pv.z : pv.w;
                        h = fmaf(ps, us, h);
                    }
                    hpair[e] = h;
                }
                if (c0 < FV) {
                    __half2 hv = __floats2half2_rn(hpair[0], hpair[1]);
                    if (last) {
                        *(__half2*)(D + (size_t)((m0 + br) >> 2) * FEAT + t * FV + c0) = hv;
                    } else {
                        int chk = c0 >> 6, cc = c0 & 63;
                        *(__half2*)(smem + SMEM_A_OFF + (uint32_t)chk * A_CHUNK
                                    + swz(br, cc >> 3) + (uint32_t)(cc & 7) * 2u) = hv;
                    }
                }
            }
        }
        if (!last) __syncthreads();
    }
}

// ----------------------- decoder GEMM (fp16 mma.sync, 2-stage) -------------
#define OFF_W 16384u
#define STAGE_BYTES 30720u
#define SMEM_BYTES 61440

__global__ __launch_bounds__(256, 2)
void gemm_mma(const __half* __restrict__ A, int lda,
              const __half* __restrict__ W, int ldw,
              const float* __restrict__ bias,
              __half* __restrict__ Ch, int ldc, int K, int n_real, int relu)
{
    extern __shared__ char smem[];
    const uint32_t sb = smem_u32(smem);
    const int tid = threadIdx.x;
    const int lane = tid & 31;
    const int wid = tid >> 5;
    const int wm = wid & 3;
    const int wn = wid >> 2;
    const int m0 = blockIdx.y * 128;
    const int n0 = blockIdx.x * 112;
    const int nfull = K >> 6;
    const int nch = nfull + 1;

    float acc[2][7][4];
#pragma unroll
    for (int i = 0; i < 2; i++)
#pragma unroll
        for (int j = 0; j < 7; j++)
#pragma unroll
            for (int v = 0; v < 4; v++) acc[i][j][v] = 0.f;

    auto load_full = [&](int ch) {
        const uint32_t s = sb + (uint32_t)(ch & 1) * STAGE_BYTES;
        const int kc = ch << 6;
#pragma unroll
        for (int i = 0; i < 4; i++) {
            int idx = tid + i * 256;
            int r = idx >> 3, g = idx & 7;
            cp_async16(s + swz(r, g), A + (size_t)(m0 + r) * lda + kc + g * 8);
        }
#pragma unroll
        for (int i = 0; i < 3; i++) {
            int idx = tid + i * 256;
            int r = idx >> 3, g = idx & 7;
            cp_async16(s + OFF_W + swz(r, g), W + (size_t)(n0 + r) * ldw + kc + g * 8);
        }
        {
            int idx = tid + 768;
            if (idx < 896) {
                int r = idx >> 3, g = idx & 7;
                cp_async16(s + OFF_W + swz(r, g), W + (size_t)(n0 + r) * ldw + kc + g * 8);
            }
        }
        asm volatile("cp.async.commit_group;");
    };
    auto load_tail = [&](int ch) {
        const uint32_t s = sb + (uint32_t)(ch & 1) * STAGE_BYTES;
        const int kc = ch << 6;
        {
            int r = tid >> 1, g = tid & 1;
            cp_async16(s + swz(r, g), A + (size_t)(m0 + r) * lda + kc + g * 8);
        }
        if (tid < 224) {
            int r = tid >> 1, g = tid & 1;
            cp_async16(s + OFF_W + swz(r, g), W + (size_t)(n0 + r) * ldw + kc + g * 8);
        }
        asm volatile("cp.async.commit_group;");
    };
    auto compute_ks = [&](uint32_t s, int ks) {
        uint32_t ah[2][4], bh[7][2];
        const uint32_t sw = s + OFF_W;
#pragma unroll
        for (int mf = 0; mf < 2; mf++) {
            int r = wm * 32 + mf * 16 + (lane & 15);
            int g = ks * 2 + (lane >> 4);
            ldsm_x4(ah[mf], s + swz(r, g));
        }
#pragma unroll
        for (int p = 0; p < 3; p++) {
            int r = wn * 56 + p * 16 + (lane & 7) + ((lane >> 4) & 1) * 8;
            int g = ks * 2 + ((lane >> 3) & 1);
            uint32_t t4[4];
            ldsm_x4(t4, sw + swz(r, g));
            bh[2*p][0] = t4[0]; bh[2*p][1] = t4[1];
            bh[2*p+1][0] = t4[2]; bh[2*p+1][1] = t4[3];
        }
        {
            int l15 = lane & 15;
            int r = wn * 56 + 48 + (l15 & 7);
            int g = ks * 2 + ((l15 >> 3) & 1);
            ldsm_x2(bh[6], sw + swz(r, g));
        }
#pragma unroll
        for (int mf = 0; mf < 2; mf++)
#pragma unroll
            for (int nf = 0; nf < 7; nf++)
                mma16816(acc[mf][nf], ah[mf], bh[nf]);
    };

    if (nfull > 0) load_full(0); else load_tail(0);
    for (int ch = 0; ch < nch; ch++) {
        if (ch + 1 < nch) {
            if (ch + 1 < nfull) load_full(ch + 1); else load_tail(ch + 1);
            asm volatile("cp.async.wait_group 1;");
        } else {
            asm volatile("cp.async.wait_group 0;");
        }
        __syncthreads();
        const uint32_t s = sb + (uint32_t)(ch & 1) * STAGE_BYTES;
        if (ch < nfull) {
#pragma unroll
            for (int ks = 0; ks < 4; ks++) compute_ks(s, ks);
        } else {
            compute_ks(s, 0);
        }
        if (ch + 1 < nch) __syncthreads();
    }

#pragma unroll
    for (int mf = 0; mf < 2; mf++)
#pragma unroll
    for (int nf = 0; nf < 7; nf++) {
        int r = m0 + wm * 32 + mf * 16 + (lane >> 2);
        int c = n0 + wn * 56 + nf * 8 + ((lane & 3) << 1);
#pragma unroll
        for (int hf = 0; hf < 2; hf++) {
            int rr = r + hf * 8;
#pragma unroll
            for (int e = 0; e < 2; e++) {
                int cc = c + e;
                if (cc >= n_real) continue;
                float v = acc[mf][nf][hf * 2 + e] + bias[cc];
                if (relu) v = fmaxf(v, 0.f);
                Ch[(size_t)rr * ldc + cc] = __float2half_rn(v);
            }
        }
    }
}

// ----------------------------- precompute ----------------------------------
__global__ void compute_gt(const float* __restrict__ W1, const float* __restrict__ W2,
                           const float* __restrict__ b1,
                           __half* __restrict__ gthi, float* __restrict__ g2)
{
    int idx = blockIdx.x * blockDim.x + threadIdx.x;
    if (idx < KPAD_CAP) {
        float s = 0.f;
        if (idx < FV)
            for (int j = 0; j < FV; j++) s = fmaf(b1[j], W2[(size_t)j * FV + idx], s);
        g2[idx] = s;
    }
    if (idx >= NPAD_CAP * KPAD_CAP) return;
    int n = idx / KPAD_CAP, k = idx % KPAD_CAP;
    float s = 0.f;
    if (n < FV && k < FV) {
        for (int j = 0; j < FV; j++)
            s = fmaf(W1[(size_t)j * FV + k], W2[(size_t)j * FV + n], s);
    }
    gthi[idx] = __float2half_rn(s);
}

__global__ void fold_head(const float* __restrict__ Wo, const float* __restrict__ Wd2,
                          const float* __restrict__ bd2, const float* __restrict__ bo,
                          float* __restrict__ Wop, float* __restrict__ bop)
{
    int idx = blockIdx.x * blockDim.x + threadIdx.x;
    if (idx < 10) {
        float s = bo[idx];
        for (int i = 0; i < FEAT; i++) s = fmaf(Wo[(size_t)idx * FEAT + i], bd2[i], s);
        bop[idx] = s;
    }
    if (idx >= 10 * FEAT) return;
    int j = idx / FEAT, k = idx % FEAT;
    float s = 0.f;
    for (int i = 0; i < FEAT; i++)
        s = fmaf(Wo[(size_t)j * FEAT + i], Wd2[(size_t)i * FEAT + k], s);
    Wop[idx] = s;
}

// ----------------------------- conversions --------------------------------
__global__ void convert_x_kernel(const float* __restrict__ x,
                                 __half* __restrict__ hhi)
{
    size_t idx = (size_t)blockIdx.x * blockDim.x + threadIdx.x;
    if (idx >= (size_t)BROWS * KPAD_CAP) return;
    size_t R = idx / KPAD_CAP;
    int f = (int)(idx % KPAD_CAP);
    hhi[idx] = __float2half_rn((f < FV) ? x[R * FV + f] : 0.f);
}

__global__ void convert_w_kernel(const float* __restrict__ W, int rin, int cin,
                                 __half* __restrict__ hi, int rout, int cout)
{
    int idx = blockIdx.x * blockDim.x + threadIdx.x;
    if (idx >= rout * cout) return;
    int r = idx / cout, c = idx % cout;
    float v = (r < rin && c < cin) ? W[(size_t)r * cin + c] : 0.f;
    hi[idx] = __float2half_rn(v);
}

// ----------------------------- head (fp16 activations, folded Wd2) ---------
__global__ __launch_bounds__(256)
void head_kernel(const __half* __restrict__ T, const float* __restrict__ Wop,
                 const float* __restrict__ bop, float* __restrict__ out)
{
    const int b    = blockIdx.x * 8 + threadIdx.y;
    const int lane = threadIdx.x;
    const __half* a = T + (size_t)b * FEAT;

    float acc[10];
#pragma unroll
    for (int j = 0; j < 10; j++) acc[j] = 0.f;
    for (int kk = lane; kk < FEAT; kk += 32) {
        float av = __half2float(a[kk]);
#pragma unroll
        for (int j = 0; j < 10; j++)
            acc[j] = fmaf(av, Wop[j * FEAT + kk], acc[j]);
    }
#pragma unroll
    for (int j = 0; j < 10; j++)
#pragma unroll
        for (int off = 16; off > 0; off >>= 1)
            acc[j] += __shfl_xor_sync(0xffffffffu, acc[j], off);

    if (lane == 0) {
        float v[10], m = -1e30f;
#pragma unroll
        for (int j = 0; j < 10; j++) { v[j] = acc[j] + bop[j]; m = fmaxf(m, v[j]); }
        float ssum = 0.f;
#pragma unroll
        for (int j = 0; j < 10; j++) { v[j] = expf(v[j] - m); ssum += v[j]; }
        float inv = 1.f / ssum;
#pragma unroll
        for (int j = 0; j < 10; j++) out[(size_t)b * 10 + j] = v[j] * inv;
    }
}

// ---------------------------------------------------------------------------
extern "C" void kernel_launch(void* const* d_in, const int* in_sizes, int n_in,
                              void* d_out, int out_size)
{
    const float* x   = (const float*)d_in[0];
    const float* W1  = (const float*)d_in[1];
    const float* b1  = (const float*)d_in[2];
    const float* W2  = (const float*)d_in[3];
    const float* W3  = (const float*)d_in[5];
    const float* b3  = (const float*)d_in[6];
    const float* Wd1 = (const float*)d_in[7];
    const float* bd1 = (const float*)d_in[8];
    const float* Wd2 = (const float*)d_in[9];
    const float* bd2 = (const float*)d_in[10];
    const float* Wo  = (const float*)d_in[11];
    const float* bo  = (const float*)d_in[12];
    float* out = (float*)d_out;

    cudaFuncSetAttribute(capsule_persist, cudaFuncAttributeMaxDynamicSharedMemorySize, CAP_SMEM);
    cudaFuncSetAttribute(gemm_mma, cudaFuncAttributeMaxDynamicSharedMemorySize, SMEM_BYTES);

    __half *hhi, *gthi, *w3hi, *wd1hi, *dhi, *thi;
    float *g2, *wop, *bop;
    cudaGetSymbolAddress((void**)&hhi, g_hhi);
    cudaGetSymbolAddress((void**)&g2, g_g2);
    cudaGetSymbolAddress((void**)&gthi, g_gthi);
    cudaGetSymbolAddress((void**)&w3hi, g_w3hi);
    cudaGetSymbolAddress((void**)&wd1hi, g_wd1hi);
    cudaGetSymbolAddress((void**)&wop, g_wop);
    cudaGetSymbolAddress((void**)&bop, g_bop);
    cudaGetSymbolAddress((void**)&dhi, g_dhi);
    cudaGetSymbolAddress((void**)&thi, g_thi);

    // precompute + conversions
    convert_x_kernel<<<(int)(((size_t)BROWS * KPAD_CAP + 255) / 256), 256>>>(x, hhi);
    int wcap = NPAD_CAP * KPAD_CAP;
    compute_gt<<<(wcap + 255) / 256, 256>>>(W1, W2, b1, gthi, g2);
    convert_w_kernel<<<(wcap + 255) / 256, 256>>>(W3, FV, FV, w3hi, NPAD_CAP, KPAD_CAP);

    // all 8 capsule iterations in ONE launch; A + Gt resident in smem
    capsule_persist<<<BROWS / 128, 512, CAP_SMEM>>>(hhi, gthi, w3hi, g2, b3, dhi);

    // decoder precompute
    int wdec = FEAT * FEAT;
    convert_w_kernel<<<(wdec + 255) / 256, 256>>>(Wd1, FEAT, FEAT, wd1hi, FEAT, FEAT);
    fold_head<<<(10 * FEAT + 255) / 256, 256>>>(Wo, Wd2, bd2, bo, wop, bop);

    // decoder layer 1 (fp16) + folded head
    const dim3 gdec(7, BATCH / 128);
    gemm_mma<<<gdec, 256, SMEM_BYTES>>>(dhi, FEAT, wd1hi, FEAT, bd1,
                                        thi, FEAT, FEAT, FEAT, 1);
    head_kernel<<<BATCH / 8, dim3(32, 8)>>>(thi, wop, bop, out);
}